// round 6
// baseline (speedup 1.0000x reference)
#include <cuda_runtime.h>
#include <cuda_bf16.h>
#include <cstdint>

// Problem constants
#define B_   2
#define S_   2048
#define HID_ 4096
#define NH_  32
#define NKV_ 8
#define HD_  128
#define NREP_ 4
#define SCALING_ 0.08838834764831843f   // 128^-0.5

// fp32 scratch (GEMM outputs, pre-rope)
__device__ float g_q[(size_t)B_ * S_ * NH_  * HD_];
__device__ float g_k[(size_t)B_ * S_ * NKV_ * HD_];
__device__ float g_v[(size_t)B_ * S_ * NKV_ * HD_];

// bf16 split planes
#define HS_ELEMS  ((size_t)B_ * S_ * HID_)
#define WQ_ELEMS  ((size_t)NH_ * HD_ * HID_)
#define WK_ELEMS  ((size_t)NKV_ * HD_ * HID_)
#define WO_ELEMS  ((size_t)HID_ * NH_ * HD_)
#define KV_ELEMS  ((size_t)B_ * S_ * NKV_ * HD_)
__device__ __nv_bfloat16 g_hs_h[HS_ELEMS], g_hs_l[HS_ELEMS];
__device__ __nv_bfloat16 g_wq_h[WQ_ELEMS], g_wq_l[WQ_ELEMS];
__device__ __nv_bfloat16 g_wk_h[WK_ELEMS], g_wk_l[WK_ELEMS];
__device__ __nv_bfloat16 g_wv_h[WK_ELEMS], g_wv_l[WK_ELEMS];
__device__ __nv_bfloat16 g_wo_h[WO_ELEMS], g_wo_l[WO_ELEMS];
__device__ __nv_bfloat16 g_ob_h[HS_ELEMS], g_ob_l[HS_ELEMS];
// attention bf16 planes (post-rope)
__device__ __nv_bfloat16 g_qh[HS_ELEMS], g_ql[HS_ELEMS];
__device__ __nv_bfloat16 g_kh[KV_ELEMS], g_kl[KV_ELEMS];
__device__ __nv_bfloat16 g_vth[KV_ELEMS], g_vtl[KV_ELEMS];  // [b][hk][d][s]

// ---------------------------------------------------------------------------
// helpers
// ---------------------------------------------------------------------------
static __device__ __forceinline__ uint32_t smem_u32(const void* p) {
    uint32_t a;
    asm("{ .reg .u64 t; cvta.to.shared.u64 t, %1; cvt.u32.u64 %0, t; }"
        : "=r"(a) : "l"(p));
    return a;
}
static __device__ __forceinline__ void cp16(uint32_t dst, const void* src) {
    asm volatile("cp.async.cg.shared.global [%0], [%1], 16;\n" :: "r"(dst), "l"(src));
}
__device__ __forceinline__ void mma16816(float c[4], uint32_t a0, uint32_t a1,
                                         uint32_t a2, uint32_t a3,
                                         uint32_t b0, uint32_t b1) {
    asm volatile(
        "mma.sync.aligned.m16n8k16.row.col.f32.bf16.bf16.f32 "
        "{%0,%1,%2,%3}, {%4,%5,%6,%7}, {%8,%9}, {%0,%1,%2,%3};\n"
        : "+f"(c[0]), "+f"(c[1]), "+f"(c[2]), "+f"(c[3])
        : "r"(a0), "r"(a1), "r"(a2), "r"(a3), "r"(b0), "r"(b1));
}
__device__ __forceinline__ void ldsm4(uint32_t& r0, uint32_t& r1, uint32_t& r2,
                                      uint32_t& r3, const void* p) {
    uint32_t a = (uint32_t)__cvta_generic_to_shared(p);
    asm volatile("ldmatrix.sync.aligned.m8n8.x4.shared.b16 {%0,%1,%2,%3}, [%4];\n"
                 : "=r"(r0), "=r"(r1), "=r"(r2), "=r"(r3) : "r"(a));
}
static __device__ __forceinline__ uint32_t pk_bf2(float lo, float hi) {
    __nv_bfloat162 t = __floats2bfloat162_rn(lo, hi);
    return *reinterpret_cast<uint32_t*>(&t);
}

// ---------------------------------------------------------------------------
// fp32 -> (bf16 hi, bf16 lo) split
// ---------------------------------------------------------------------------
__global__ void split_kernel(const float* __restrict__ x,
                             __nv_bfloat16* __restrict__ hi,
                             __nv_bfloat16* __restrict__ lo, size_t n) {
    size_t i = ((size_t)blockIdx.x * blockDim.x + threadIdx.x) * 4;
    if (i >= n) return;
    float4 v = *(const float4*)(x + i);
    float f[4] = {v.x, v.y, v.z, v.w};
#pragma unroll
    for (int j = 0; j < 4; j++) {
        __nv_bfloat16 h = __float2bfloat16(f[j]);
        hi[i + j] = h;
        lo[i + j] = __float2bfloat16(f[j] - __bfloat162float(h));
    }
}

// fused RoPE + split: fp32 in (pre-rope), bf16 h/l out (post-rope), one pass.
__global__ void rope_split(const float* __restrict__ x,
                           const float* __restrict__ cosp,
                           const float* __restrict__ sinp,
                           __nv_bfloat16* __restrict__ xh,
                           __nv_bfloat16* __restrict__ xl,
                           int nheads, int total) {
    int idx = blockIdx.x * blockDim.x + threadIdx.x;
    if (idx >= total) return;
    int d  = idx & 63;
    int h  = (idx >> 6) % nheads;
    int bs = idx / (64 * nheads);
    const float* row = x + (size_t)bs * nheads * HD_ + (size_t)h * HD_;
    const float* c = cosp + (size_t)bs * HD_;
    const float* s = sinp + (size_t)bs * HD_;
    float x1 = row[d], x2 = row[d + 64];
    float y1 = x1 * c[d]      - x2 * s[d];
    float y2 = x2 * c[d + 64] + x1 * s[d + 64];
    size_t base = (size_t)bs * nheads * HD_ + (size_t)h * HD_;
    __nv_bfloat16 h1 = __float2bfloat16(y1);
    __nv_bfloat16 h2 = __float2bfloat16(y2);
    xh[base + d]      = h1;
    xh[base + d + 64] = h2;
    xl[base + d]      = __float2bfloat16(y1 - __bfloat162float(h1));
    xl[base + d + 64] = __float2bfloat16(y2 - __bfloat162float(h2));
}

// split + transpose V: in [b*S][NKV*HD] fp32 -> out [b][hk][d][s] bf16 h/l
__global__ void splitT_v(const float* __restrict__ v,
                         __nv_bfloat16* __restrict__ vh,
                         __nv_bfloat16* __restrict__ vl) {
    size_t idx = (size_t)blockIdx.x * blockDim.x + threadIdx.x;
    if (idx >= KV_ELEMS) return;
    int s  = idx & (S_ - 1);
    size_t r = idx >> 11;
    int d  = r & (HD_ - 1);  r >>= 7;
    int hk = r & (NKV_ - 1);
    int b  = (int)(r >> 3);
    float x = v[((size_t)(b * S_ + s) * NKV_ + hk) * HD_ + d];
    __nv_bfloat16 h = __float2bfloat16(x);
    vh[idx] = h;
    vl[idx] = __float2bfloat16(x - __bfloat162float(h));
}

// ---------------------------------------------------------------------------
// Split-bf16 NT GEMM, mma.sync, BK=32, 3-stage cp.async, 1 barrier/iter.
// 256 threads (8 warps 2x4), warp tile 64x32, 3 planes.
// ---------------------------------------------------------------------------
#define BM 128
#define BN 128
#define GK 32
#define GPAD 40
#define GPLANE 5120              // 128*GPAD elems
#define GSTAGE 20480             // 4 planes (Ah,Al,Bh,Bl)
#define GSMEM_B (3 * GSTAGE * 2) // 122880 bytes

__global__ __launch_bounds__(256)
void gemm_mma(const __nv_bfloat16* __restrict__ Ah, const __nv_bfloat16* __restrict__ Al,
              const __nv_bfloat16* __restrict__ Bh, const __nv_bfloat16* __restrict__ Bl,
              float* __restrict__ C, int M, int N, int K) {
    extern __shared__ __nv_bfloat16 gsm[];
    const uint32_t sb = smem_u32(gsm);

    const int tid = threadIdx.x;
    const int warp = tid >> 5, lane = tid & 31;
    const int g = lane >> 2, tg = lane & 3;
    const int warpM = warp >> 2, warpN = warp & 3;
    const int bm = blockIdx.y * BM, bn = blockIdx.x * BN;

    const int a_r = lane & 15;
    const int a_k = (lane >> 4) * 8;
    const int b_r = lane & 7;
    const int b_n8 = ((lane >> 4) & 1) * 8;
    const int b_k8 = ((lane >> 3) & 1) * 8;

    float c[4][4][4];
#pragma unroll
    for (int mi = 0; mi < 4; mi++)
#pragma unroll
        for (int ni = 0; ni < 4; ni++)
#pragma unroll
            for (int j = 0; j < 4; j++) c[mi][ni][j] = 0.f;

    const int niter = K / GK;

    auto load_stage = [&](int s, int k0) {
        const uint32_t base = sb + (uint32_t)(s * GSTAGE) * 2;
#pragma unroll
        for (int i = 0; i < 2; i++) {
            int j = tid + (i << 8);
            int row = j >> 2, col = (j & 3) * 8;
            size_t ao = (size_t)(bm + row) * K + k0 + col;
            size_t bo = (size_t)(bn + row) * K + k0 + col;
            uint32_t off = (uint32_t)(row * GPAD + col) * 2;
            cp16(base + off, Ah + ao);
            cp16(base + GPLANE * 2 + off, Al + ao);
            cp16(base + 2 * GPLANE * 2 + off, Bh + bo);
            cp16(base + 3 * GPLANE * 2 + off, Bl + bo);
        }
        asm volatile("cp.async.commit_group;\n");
    };

    load_stage(0, 0);
    load_stage(1, GK);

    for (int i = 0; i < niter; i++) {
        if (i + 1 < niter) asm volatile("cp.async.wait_group 1;\n");
        else               asm volatile("cp.async.wait_group 0;\n");
        __syncthreads();
        if (i + 2 < niter) load_stage((i + 2) % 3, (i + 2) * GK);

        const int s = i % 3;
        const __nv_bfloat16* Asm = gsm + (size_t)s * GSTAGE;
        const __nv_bfloat16* Bsm = Asm + 2 * GPLANE;
#pragma unroll
        for (int kk = 0; kk < 2; kk++) {
            const int kb = kk * 16;
            uint32_t aH[4][4], aL[4][4], bH[4][2], bL[4][2];
#pragma unroll
            for (int mi = 0; mi < 4; mi++) {
                int rb = warpM * 64 + mi * 16;
                ldsm4(aH[mi][0], aH[mi][1], aH[mi][2], aH[mi][3],
                      Asm + (size_t)(rb + a_r) * GPAD + kb + a_k);
                ldsm4(aL[mi][0], aL[mi][1], aL[mi][2], aL[mi][3],
                      Asm + GPLANE + (size_t)(rb + a_r) * GPAD + kb + a_k);
            }
#pragma unroll
            for (int np = 0; np < 2; np++) {
                int nb = warpN * 32 + np * 16;
                uint32_t r0, r1, r2, r3;
                ldsm4(r0, r1, r2, r3,
                      Bsm + (size_t)(nb + b_r + b_n8) * GPAD + kb + b_k8);
                bH[np * 2][0] = r0; bH[np * 2][1] = r1;
                bH[np * 2 + 1][0] = r2; bH[np * 2 + 1][1] = r3;
                ldsm4(r0, r1, r2, r3,
                      Bsm + GPLANE + (size_t)(nb + b_r + b_n8) * GPAD + kb + b_k8);
                bL[np * 2][0] = r0; bL[np * 2][1] = r1;
                bL[np * 2 + 1][0] = r2; bL[np * 2 + 1][1] = r3;
            }
#pragma unroll
            for (int mi = 0; mi < 4; mi++)
#pragma unroll
                for (int ni = 0; ni < 4; ni++) {
                    mma16816(c[mi][ni], aH[mi][0], aH[mi][1], aH[mi][2], aH[mi][3],
                             bH[ni][0], bH[ni][1]);
                    mma16816(c[mi][ni], aH[mi][0], aH[mi][1], aH[mi][2], aH[mi][3],
                             bL[ni][0], bL[ni][1]);
                    mma16816(c[mi][ni], aL[mi][0], aL[mi][1], aL[mi][2], aL[mi][3],
                             bH[ni][0], bH[ni][1]);
                }
        }
        __syncthreads();
    }

#pragma unroll
    for (int mi = 0; mi < 4; mi++) {
        int r0 = bm + warpM * 64 + mi * 16 + g;
#pragma unroll
        for (int ni = 0; ni < 4; ni++) {
            int cc = bn + warpN * 32 + ni * 8 + 2 * tg;
            *(float2*)(C + (size_t)r0 * N + cc) = make_float2(c[mi][ni][0], c[mi][ni][1]);
            *(float2*)(C + (size_t)(r0 + 8) * N + cc) = make_float2(c[mi][ni][2], c[mi][ni][3]);
        }
    }
}

// ---------------------------------------------------------------------------
// Flash attention, split-bf16 mma.sync.
// 256 threads (8 warps), 128 q rows/CTA (16/warp), 64-key tiles,
// double-buffered KV with 1-tile prefetch, bf16 split output.
// ---------------------------------------------------------------------------
#define FQH 0
#define FQL 17408
#define FKV0 34816
#define FKVSZ 35840
#define FKHo 0
#define FKLo 8704
#define FVHo 17408
#define FVLo 26624
#define FSMEM_B 212992

__global__ __launch_bounds__(256)
void flash_mma(const __nv_bfloat16* __restrict__ Qh, const __nv_bfloat16* __restrict__ Ql,
               const __nv_bfloat16* __restrict__ Kh, const __nv_bfloat16* __restrict__ Kl,
               const __nv_bfloat16* __restrict__ Vth, const __nv_bfloat16* __restrict__ Vtl,
               __nv_bfloat16* __restrict__ Oh, __nv_bfloat16* __restrict__ Ol) {
    extern __shared__ __nv_bfloat16 fsm[];
    const uint32_t sb = smem_u32(fsm);

    const int b = blockIdx.z, h = blockIdx.y, qt = blockIdx.x;
    const int qs = qt * 128, hk = h >> 2;
    const int tid = threadIdx.x;
    const int warp = tid >> 5, lane = tid & 31;
    const int g = lane >> 2, tg = lane & 3;

    const int a_r = lane & 15;
    const int a_k = (lane >> 4) * 8;
    const int b_r = lane & 7;
    const int b_n8 = ((lane >> 4) & 1) * 8;
    const int b_k8 = ((lane >> 3) & 1) * 8;

    // ---- load Q tile (once): 128 rows x 128 d x 2 planes ----
#pragma unroll
    for (int i = 0; i < 8; i++) {
        int j = tid + (i << 8);
        int row = j >> 4, kc = j & 15;
        uint32_t d = sb + (uint32_t)((row * 136 + kc * 8) * 2);
        size_t src = ((size_t)(b * S_ + qs + row) * NH_ + h) * HD_ + kc * 8;
        cp16(d + FQH * 2, Qh + src);
        cp16(d + FQL * 2, Ql + src);
    }
    asm volatile("cp.async.commit_group;\n");

    auto load_kv = [&](int buf, int ks) {
        const uint32_t kb = sb + (uint32_t)(FKV0 + buf * FKVSZ) * 2;
#pragma unroll
        for (int i = 0; i < 4; i++) {
            int jj = tid + (i << 8);
            int krow = jj >> 4, kkc = jj & 15;
            uint32_t dk = kb + (uint32_t)((krow * 136 + kkc * 8) * 2);
            size_t ksrc = ((size_t)(b * S_ + ks + krow) * NKV_ + hk) * HD_ + kkc * 8;
            cp16(dk + FKHo * 2, Kh + ksrc);
            cp16(dk + FKLo * 2, Kl + ksrc);
            int vd = jj >> 3, vc = jj & 7;
            uint32_t dv = kb + (uint32_t)((vd * 72 + vc * 8) * 2);
            size_t vsrc = ((size_t)(b * NKV_ + hk) * HD_ + vd) * S_ + ks + vc * 8;
            cp16(dv + FVHo * 2, Vth + vsrc);
            cp16(dv + FVLo * 2, Vtl + vsrc);
        }
        asm volatile("cp.async.commit_group;\n");
    };

    load_kv(0, 0);

    float o[16][4];
#pragma unroll
    for (int nt = 0; nt < 16; nt++)
#pragma unroll
        for (int j = 0; j < 4; j++) o[nt][j] = 0.f;
    float m0 = -1e30f, m1 = -1e30f, l0 = 0.f, l1 = 0.f;

    const int wrow0 = qs + warp * 16;      // warp's min q row
    const int qr0 = wrow0 + g;
    const int qr1 = qr0 + 8;
    const int ntiles = 2 * (qt + 1);

    for (int j = 0; j < ntiles; j++) {
        const int ks = j * 64;
        asm volatile("cp.async.wait_group 0;\n");
        __syncthreads();
        if (j + 1 < ntiles) load_kv((j + 1) & 1, (j + 1) * 64);

        if (ks > wrow0 + 15) continue;     // fully masked for this warp

        const __nv_bfloat16* kvb = fsm + FKV0 + (j & 1) * FKVSZ;

        // ---- S = Q K^T (3-plane) ----
        float S4[8][4];
#pragma unroll
        for (int nt = 0; nt < 8; nt++)
#pragma unroll
            for (int cc = 0; cc < 4; cc++) S4[nt][cc] = 0.f;

#pragma unroll
        for (int dk = 0; dk < 8; dk++) {
            uint32_t aH[4], aL[4];
            ldsm4(aH[0], aH[1], aH[2], aH[3],
                  fsm + FQH + (size_t)(warp * 16 + a_r) * 136 + dk * 16 + a_k);
            ldsm4(aL[0], aL[1], aL[2], aL[3],
                  fsm + FQL + (size_t)(warp * 16 + a_r) * 136 + dk * 16 + a_k);
#pragma unroll
            for (int np = 0; np < 4; np++) {
                int nb = np * 16;
                uint32_t h0, h1, h2, h3, l0r, l1r, l2r, l3r;
                ldsm4(h0, h1, h2, h3,
                      kvb + FKHo + (size_t)(nb + b_r + b_n8) * 136 + dk * 16 + b_k8);
                ldsm4(l0r, l1r, l2r, l3r,
                      kvb + FKLo + (size_t)(nb + b_r + b_n8) * 136 + dk * 16 + b_k8);
                mma16816(S4[2 * np],     aH[0], aH[1], aH[2], aH[3], h0, h1);
                mma16816(S4[2 * np],     aH[0], aH[1], aH[2], aH[3], l0r, l1r);
                mma16816(S4[2 * np],     aL[0], aL[1], aL[2], aL[3], h0, h1);
                mma16816(S4[2 * np + 1], aH[0], aH[1], aH[2], aH[3], h2, h3);
                mma16816(S4[2 * np + 1], aH[0], aH[1], aH[2], aH[3], l2r, l3r);
                mma16816(S4[2 * np + 1], aL[0], aL[1], aL[2], aL[3], h2, h3);
            }
        }

        // ---- scale + mask + online softmax ----
        float mx0 = -1e30f, mx1 = -1e30f;
        const bool needMask = (ks + 63 > wrow0);
#pragma unroll
        for (int nt = 0; nt < 8; nt++) {
#pragma unroll
            for (int cc = 0; cc < 4; cc++) {
                float v = S4[nt][cc] * SCALING_;
                if (needMask) {
                    int kcol = ks + nt * 8 + 2 * tg + (cc & 1);
                    int qr = (cc < 2) ? qr0 : qr1;
                    if (kcol > qr) v = -1e30f;
                }
                S4[nt][cc] = v;
                if (cc < 2) mx0 = fmaxf(mx0, v); else mx1 = fmaxf(mx1, v);
            }
        }
        mx0 = fmaxf(mx0, __shfl_xor_sync(0xffffffffu, mx0, 1));
        mx0 = fmaxf(mx0, __shfl_xor_sync(0xffffffffu, mx0, 2));
        mx1 = fmaxf(mx1, __shfl_xor_sync(0xffffffffu, mx1, 1));
        mx1 = fmaxf(mx1, __shfl_xor_sync(0xffffffffu, mx1, 2));
        const float mt0 = fmaxf(m0, mx0), mt1 = fmaxf(m1, mx1);
        const float sc0 = __expf(m0 - mt0), sc1 = __expf(m1 - mt1);
        m0 = mt0; m1 = mt1;

        float rs0 = 0.f, rs1 = 0.f;
#pragma unroll
        for (int nt = 0; nt < 8; nt++) {
            float p0 = __expf(S4[nt][0] - mt0);
            float p1 = __expf(S4[nt][1] - mt0);
            float p2 = __expf(S4[nt][2] - mt1);
            float p3 = __expf(S4[nt][3] - mt1);
            S4[nt][0] = p0; S4[nt][1] = p1; S4[nt][2] = p2; S4[nt][3] = p3;
            rs0 += p0 + p1; rs1 += p2 + p3;
        }
        rs0 += __shfl_xor_sync(0xffffffffu, rs0, 1);
        rs0 += __shfl_xor_sync(0xffffffffu, rs0, 2);
        rs1 += __shfl_xor_sync(0xffffffffu, rs1, 1);
        rs1 += __shfl_xor_sync(0xffffffffu, rs1, 2);
        l0 = l0 * sc0 + rs0;
        l1 = l1 * sc1 + rs1;
#pragma unroll
        for (int nt = 0; nt < 16; nt++) {
            o[nt][0] *= sc0; o[nt][1] *= sc0;
            o[nt][2] *= sc1; o[nt][3] *= sc1;
        }

        // ---- O += P V (3-plane, P split in registers) ----
#pragma unroll
        for (int kt = 0; kt < 4; kt++) {
            uint32_t aPh[4], aPl[4];
#pragma unroll
            for (int half = 0; half < 2; half++) {
                const float* sv = S4[2 * kt + half];
                uint32_t p01 = pk_bf2(sv[0], sv[1]);
                uint32_t p23 = pk_bf2(sv[2], sv[3]);
                float r0f = sv[0] - __uint_as_float(p01 << 16);
                float r1f = sv[1] - __uint_as_float(p01 & 0xffff0000u);
                float r2f = sv[2] - __uint_as_float(p23 << 16);
                float r3f = sv[3] - __uint_as_float(p23 & 0xffff0000u);
                aPh[0 + 2 * half] = p01;
                aPh[1 + 2 * half] = p23;
                aPl[0 + 2 * half] = pk_bf2(r0f, r1f);
                aPl[1 + 2 * half] = pk_bf2(r2f, r3f);
            }
#pragma unroll
            for (int np = 0; np < 8; np++) {
                int nb = np * 16;
                uint32_t h0, h1, h2, h3, l0r, l1r, l2r, l3r;
                ldsm4(h0, h1, h2, h3,
                      kvb + FVHo + (size_t)(nb + b_r + b_n8) * 72 + kt * 16 + b_k8);
                ldsm4(l0r, l1r, l2r, l3r,
                      kvb + FVLo + (size_t)(nb + b_r + b_n8) * 72 + kt * 16 + b_k8);
                mma16816(o[2 * np],     aPh[0], aPh[1], aPh[2], aPh[3], h0, h1);
                mma16816(o[2 * np],     aPh[0], aPh[1], aPh[2], aPh[3], l0r, l1r);
                mma16816(o[2 * np],     aPl[0], aPl[1], aPl[2], aPl[3], h0, h1);
                mma16816(o[2 * np + 1], aPh[0], aPh[1], aPh[2], aPh[3], h2, h3);
                mma16816(o[2 * np + 1], aPh[0], aPh[1], aPh[2], aPh[3], l2r, l3r);
                mma16816(o[2 * np + 1], aPl[0], aPl[1], aPl[2], aPl[3], h2, h3);
            }
        }
    }

    // ---- writeback: split fp32 -> bf16 h/l planes directly ----
    const float inv0 = 1.f / l0, inv1 = 1.f / l1;
    const size_t r0base = ((size_t)(b * S_ + qr0) * NH_ + h) * HD_;
    const size_t r1base = ((size_t)(b * S_ + qr1) * NH_ + h) * HD_;
#pragma unroll
    for (int nt = 0; nt < 16; nt++) {
        int cc = nt * 8 + 2 * tg;
        float v00 = o[nt][0] * inv0, v01 = o[nt][1] * inv0;
        float v10 = o[nt][2] * inv1, v11 = o[nt][3] * inv1;
        uint32_t h0p = pk_bf2(v00, v01);
        uint32_t h1p = pk_bf2(v10, v11);
        float e00 = v00 - __uint_as_float(h0p << 16);
        float e01 = v01 - __uint_as_float(h0p & 0xffff0000u);
        float e10 = v10 - __uint_as_float(h1p << 16);
        float e11 = v11 - __uint_as_float(h1p & 0xffff0000u);
        *(uint32_t*)(Oh + r0base + cc) = h0p;
        *(uint32_t*)(Ol + r0base + cc) = pk_bf2(e00, e01);
        *(uint32_t*)(Oh + r1base + cc) = h1p;
        *(uint32_t*)(Ol + r1base + cc) = pk_bf2(e10, e11);
    }
}

// ---------------------------------------------------------------------------
// Launch
// ---------------------------------------------------------------------------
extern "C" void kernel_launch(void* const* d_in, const int* in_sizes, int n_in,
                              void* d_out, int out_size) {
    const float* hs   = (const float*)d_in[0];
    const float* cosp = (const float*)d_in[1];
    const float* sinp = (const float*)d_in[2];
    const float* Wq   = (const float*)d_in[4];
    const float* Wk   = (const float*)d_in[5];
    const float* Wv   = (const float*)d_in[6];
    const float* Wo   = (const float*)d_in[7];
    float* out = (float*)d_out;

    float *qbuf, *kbuf, *vbuf;
    cudaGetSymbolAddress((void**)&qbuf, g_q);
    cudaGetSymbolAddress((void**)&kbuf, g_k);
    cudaGetSymbolAddress((void**)&vbuf, g_v);

    __nv_bfloat16 *hs_h, *hs_l, *wq_h, *wq_l, *wk_h, *wk_l, *wv_h, *wv_l,
                  *wo_h, *wo_l, *ob_h, *ob_l, *qh, *ql, *kh, *kl, *vth, *vtl;
    cudaGetSymbolAddress((void**)&hs_h, g_hs_h); cudaGetSymbolAddress((void**)&hs_l, g_hs_l);
    cudaGetSymbolAddress((void**)&wq_h, g_wq_h); cudaGetSymbolAddress((void**)&wq_l, g_wq_l);
    cudaGetSymbolAddress((void**)&wk_h, g_wk_h); cudaGetSymbolAddress((void**)&wk_l, g_wk_l);
    cudaGetSymbolAddress((void**)&wv_h, g_wv_h); cudaGetSymbolAddress((void**)&wv_l, g_wv_l);
    cudaGetSymbolAddress((void**)&wo_h, g_wo_h); cudaGetSymbolAddress((void**)&wo_l, g_wo_l);
    cudaGetSymbolAddress((void**)&ob_h, g_ob_h); cudaGetSymbolAddress((void**)&ob_l, g_ob_l);
    cudaGetSymbolAddress((void**)&qh, g_qh); cudaGetSymbolAddress((void**)&ql, g_ql);
    cudaGetSymbolAddress((void**)&kh, g_kh); cudaGetSymbolAddress((void**)&kl, g_kl);
    cudaGetSymbolAddress((void**)&vth, g_vth); cudaGetSymbolAddress((void**)&vtl, g_vtl);

    cudaFuncSetAttribute(gemm_mma, cudaFuncAttributeMaxDynamicSharedMemorySize, GSMEM_B);
    cudaFuncSetAttribute(flash_mma, cudaFuncAttributeMaxDynamicSharedMemorySize, FSMEM_B);

    const int M = B_ * S_;   // 4096

    // Split conversions (inputs)
    split_kernel<<<(HS_ELEMS / 4 + 255) / 256, 256>>>(hs, hs_h, hs_l, HS_ELEMS);
    split_kernel<<<(WQ_ELEMS / 4 + 255) / 256, 256>>>(Wq, wq_h, wq_l, WQ_ELEMS);
    split_kernel<<<(WK_ELEMS / 4 + 255) / 256, 256>>>(Wk, wk_h, wk_l, WK_ELEMS);
    split_kernel<<<(WK_ELEMS / 4 + 255) / 256, 256>>>(Wv, wv_h, wv_l, WK_ELEMS);
    split_kernel<<<(WO_ELEMS / 4 + 255) / 256, 256>>>(Wo, wo_h, wo_l, WO_ELEMS);

    // QKV projections
    gemm_mma<<<dim3((NH_ * HD_) / BN, M / BM), 256, GSMEM_B>>>(hs_h, hs_l, wq_h, wq_l, qbuf, M, NH_ * HD_, HID_);
    gemm_mma<<<dim3((NKV_ * HD_) / BN, M / BM), 256, GSMEM_B>>>(hs_h, hs_l, wk_h, wk_l, kbuf, M, NKV_ * HD_, HID_);
    gemm_mma<<<dim3((NKV_ * HD_) / BN, M / BM), 256, GSMEM_B>>>(hs_h, hs_l, wv_h, wv_l, vbuf, M, NKV_ * HD_, HID_);

    // Fused RoPE + split; V split+transpose
    {
        int totq = B_ * S_ * NH_ * 64;
        rope_split<<<(totq + 255) / 256, 256>>>(qbuf, cosp, sinp, qh, ql, NH_, totq);
        int totk = B_ * S_ * NKV_ * 64;
        rope_split<<<(totk + 255) / 256, 256>>>(kbuf, cosp, sinp, kh, kl, NKV_, totk);
        splitT_v<<<(KV_ELEMS + 255) / 256, 256>>>(vbuf, vth, vtl);
    }

    // Flash attention (split-bf16 mma, bf16 split output)
    flash_mma<<<dim3(S_ / 128, NH_, B_), 256, FSMEM_B>>>(qh, ql, kh, kl, vth, vtl, ob_h, ob_l);

    // O projection
    gemm_mma<<<dim3(HID_ / BN, M / BM), 256, GSMEM_B>>>(ob_h, ob_l, wo_h, wo_l, out, M, HID_, NH_ * HD_);
}

// round 7
// speedup vs baseline: 1.1130x; 1.1130x over previous
#include <cuda_runtime.h>
#include <cuda_bf16.h>
#include <cstdint>

// Problem constants
#define B_   2
#define S_   2048
#define HID_ 4096
#define NH_  32
#define NKV_ 8
#define HD_  128
#define NREP_ 4
#define SCALING_ 0.08838834764831843f   // 128^-0.5

// fp32 scratch (GEMM outputs, pre-rope)
__device__ float g_q[(size_t)B_ * S_ * NH_  * HD_];
__device__ float g_k[(size_t)B_ * S_ * NKV_ * HD_];
__device__ float g_v[(size_t)B_ * S_ * NKV_ * HD_];

// bf16 split planes
#define HS_ELEMS  ((size_t)B_ * S_ * HID_)
#define WQ_ELEMS  ((size_t)NH_ * HD_ * HID_)
#define WK_ELEMS  ((size_t)NKV_ * HD_ * HID_)
#define WO_ELEMS  ((size_t)HID_ * NH_ * HD_)
#define KV_ELEMS  ((size_t)B_ * S_ * NKV_ * HD_)
__device__ __nv_bfloat16 g_hs_h[HS_ELEMS], g_hs_l[HS_ELEMS];
__device__ __nv_bfloat16 g_wq_h[WQ_ELEMS], g_wq_l[WQ_ELEMS];
__device__ __nv_bfloat16 g_wk_h[WK_ELEMS], g_wk_l[WK_ELEMS];
__device__ __nv_bfloat16 g_wv_h[WK_ELEMS], g_wv_l[WK_ELEMS];
__device__ __nv_bfloat16 g_wo_h[WO_ELEMS], g_wo_l[WO_ELEMS];
__device__ __nv_bfloat16 g_ob_h[HS_ELEMS], g_ob_l[HS_ELEMS];
// attention bf16 planes (post-rope)
__device__ __nv_bfloat16 g_qh[HS_ELEMS], g_ql[HS_ELEMS];
__device__ __nv_bfloat16 g_kh[KV_ELEMS], g_kl[KV_ELEMS];
__device__ __nv_bfloat16 g_vth[KV_ELEMS], g_vtl[KV_ELEMS];  // [b][hk][d][s]

// ---------------------------------------------------------------------------
// helpers
// ---------------------------------------------------------------------------
static __device__ __forceinline__ uint32_t smem_u32(const void* p) {
    uint32_t a;
    asm("{ .reg .u64 t; cvta.to.shared.u64 t, %1; cvt.u32.u64 %0, t; }"
        : "=r"(a) : "l"(p));
    return a;
}
static __device__ __forceinline__ void cp16(uint32_t dst, const void* src) {
    asm volatile("cp.async.cg.shared.global [%0], [%1], 16;\n" :: "r"(dst), "l"(src));
}
__device__ __forceinline__ void mma16816(float c[4], uint32_t a0, uint32_t a1,
                                         uint32_t a2, uint32_t a3,
                                         uint32_t b0, uint32_t b1) {
    asm volatile(
        "mma.sync.aligned.m16n8k16.row.col.f32.bf16.bf16.f32 "
        "{%0,%1,%2,%3}, {%4,%5,%6,%7}, {%8,%9}, {%0,%1,%2,%3};\n"
        : "+f"(c[0]), "+f"(c[1]), "+f"(c[2]), "+f"(c[3])
        : "r"(a0), "r"(a1), "r"(a2), "r"(a3), "r"(b0), "r"(b1));
}
__device__ __forceinline__ void ldsm4(uint32_t& r0, uint32_t& r1, uint32_t& r2,
                                      uint32_t& r3, const void* p) {
    uint32_t a = (uint32_t)__cvta_generic_to_shared(p);
    asm volatile("ldmatrix.sync.aligned.m8n8.x4.shared.b16 {%0,%1,%2,%3}, [%4];\n"
                 : "=r"(r0), "=r"(r1), "=r"(r2), "=r"(r3) : "r"(a));
}
static __device__ __forceinline__ uint32_t pk_bf2(float lo, float hi) {
    __nv_bfloat162 t = __floats2bfloat162_rn(lo, hi);
    return *reinterpret_cast<uint32_t*>(&t);
}

// ---------------------------------------------------------------------------
// fp32 -> (bf16 hi, bf16 lo) split
// ---------------------------------------------------------------------------
__global__ void split_kernel(const float* __restrict__ x,
                             __nv_bfloat16* __restrict__ hi,
                             __nv_bfloat16* __restrict__ lo, size_t n) {
    size_t i = ((size_t)blockIdx.x * blockDim.x + threadIdx.x) * 4;
    if (i >= n) return;
    float4 v = *(const float4*)(x + i);
    float f[4] = {v.x, v.y, v.z, v.w};
#pragma unroll
    for (int j = 0; j < 4; j++) {
        __nv_bfloat16 h = __float2bfloat16(f[j]);
        hi[i + j] = h;
        lo[i + j] = __float2bfloat16(f[j] - __bfloat162float(h));
    }
}

// fused RoPE + split: fp32 in (pre-rope), bf16 h/l out (post-rope), one pass.
__global__ void rope_split(const float* __restrict__ x,
                           const float* __restrict__ cosp,
                           const float* __restrict__ sinp,
                           __nv_bfloat16* __restrict__ xh,
                           __nv_bfloat16* __restrict__ xl,
                           int nheads, int total) {
    int idx = blockIdx.x * blockDim.x + threadIdx.x;
    if (idx >= total) return;
    int d  = idx & 63;
    int h  = (idx >> 6) % nheads;
    int bs = idx / (64 * nheads);
    const float* row = x + (size_t)bs * nheads * HD_ + (size_t)h * HD_;
    const float* c = cosp + (size_t)bs * HD_;
    const float* s = sinp + (size_t)bs * HD_;
    float x1 = row[d], x2 = row[d + 64];
    float y1 = x1 * c[d]      - x2 * s[d];
    float y2 = x2 * c[d + 64] + x1 * s[d + 64];
    size_t base = (size_t)bs * nheads * HD_ + (size_t)h * HD_;
    __nv_bfloat16 h1 = __float2bfloat16(y1);
    __nv_bfloat16 h2 = __float2bfloat16(y2);
    xh[base + d]      = h1;
    xh[base + d + 64] = h2;
    xl[base + d]      = __float2bfloat16(y1 - __bfloat162float(h1));
    xl[base + d + 64] = __float2bfloat16(y2 - __bfloat162float(h2));
}

// split + transpose V: in [b*S][NKV*HD] fp32 -> out [b][hk][d][s] bf16 h/l
__global__ void splitT_v(const float* __restrict__ v,
                         __nv_bfloat16* __restrict__ vh,
                         __nv_bfloat16* __restrict__ vl) {
    size_t idx = (size_t)blockIdx.x * blockDim.x + threadIdx.x;
    if (idx >= KV_ELEMS) return;
    int s  = idx & (S_ - 1);
    size_t r = idx >> 11;
    int d  = r & (HD_ - 1);  r >>= 7;
    int hk = r & (NKV_ - 1);
    int b  = (int)(r >> 3);
    float x = v[((size_t)(b * S_ + s) * NKV_ + hk) * HD_ + d];
    __nv_bfloat16 h = __float2bfloat16(x);
    vh[idx] = h;
    vl[idx] = __float2bfloat16(x - __bfloat162float(h));
}

// ---------------------------------------------------------------------------
// Split-bf16 NT GEMM, mma.sync, BK=32 per stage, 2-stage cp.async.
// 256 threads (8 warps 2x4), warp tile 64x32, 3 planes. 80KB smem -> 2 CTA/SM.
// ---------------------------------------------------------------------------
#define BM 128
#define BN 128
#define GK 32
#define GPAD 40
#define GA_ELEMS 20480   // 2 stages * 2 planes * 128 * 40
#define GSMEM_B ((GA_ELEMS * 2) * 2)   // bytes: 81920

__global__ __launch_bounds__(256)
void gemm_mma(const __nv_bfloat16* __restrict__ Ah, const __nv_bfloat16* __restrict__ Al,
              const __nv_bfloat16* __restrict__ Bh, const __nv_bfloat16* __restrict__ Bl,
              float* __restrict__ C, int M, int N, int K) {
    extern __shared__ __nv_bfloat16 gsm[];
    const uint32_t sb = smem_u32(gsm);

    const int tid = threadIdx.x;
    const int warp = tid >> 5, lane = tid & 31;
    const int g = lane >> 2, tg = lane & 3;
    const int warpM = warp >> 2, warpN = warp & 3;
    const int bm = blockIdx.y * BM, bn = blockIdx.x * BN;

    const int a_r = lane & 15;
    const int a_k = (lane >> 4) * 8;
    const int b_r = lane & 7;
    const int b_n8 = ((lane >> 4) & 1) * 8;
    const int b_k8 = ((lane >> 3) & 1) * 8;

    float c[4][4][4];
#pragma unroll
    for (int mi = 0; mi < 4; mi++)
#pragma unroll
        for (int ni = 0; ni < 4; ni++)
#pragma unroll
            for (int j = 0; j < 4; j++) c[mi][ni][j] = 0.f;

    const int niter = K / GK;

    auto load_stage = [&](int s, int k0) {
#pragma unroll
        for (int i = 0; i < 2; i++) {
            int j = tid + (i << 8);
            int row = j >> 2, col = (j & 3) * 8;
            size_t ao = (size_t)(bm + row) * K + k0 + col;
            size_t bo = (size_t)(bn + row) * K + k0 + col;
            uint32_t da = sb + (uint32_t)((((s * 2) * 128 + row) * GPAD + col) * 2);
            uint32_t db = sb + (uint32_t)((GA_ELEMS + ((s * 2) * 128 + row) * GPAD + col) * 2);
            cp16(da, Ah + ao);
            cp16(da + 128 * GPAD * 2, Al + ao);
            cp16(db, Bh + bo);
            cp16(db + 128 * GPAD * 2, Bl + bo);
        }
        asm volatile("cp.async.commit_group;\n");
    };

    load_stage(0, 0);

    for (int i = 0; i < niter; i++) {
        if (i + 1 < niter) {
            load_stage((i + 1) & 1, (i + 1) * GK);
            asm volatile("cp.async.wait_group 1;\n");
        } else {
            asm volatile("cp.async.wait_group 0;\n");
        }
        __syncthreads();

        const int s = i & 1;
        const __nv_bfloat16* Asm = gsm + (size_t)(s * 2) * 128 * GPAD;
        const __nv_bfloat16* Bsm = gsm + GA_ELEMS + (size_t)(s * 2) * 128 * GPAD;
#pragma unroll
        for (int kk = 0; kk < 2; kk++) {
            const int kb = kk * 16;
            uint32_t aH[4][4], aL[4][4], bH[4][2], bL[4][2];
#pragma unroll
            for (int mi = 0; mi < 4; mi++) {
                int rb = warpM * 64 + mi * 16;
                ldsm4(aH[mi][0], aH[mi][1], aH[mi][2], aH[mi][3],
                      Asm + (size_t)(rb + a_r) * GPAD + kb + a_k);
                ldsm4(aL[mi][0], aL[mi][1], aL[mi][2], aL[mi][3],
                      Asm + 128 * GPAD + (size_t)(rb + a_r) * GPAD + kb + a_k);
            }
#pragma unroll
            for (int np = 0; np < 2; np++) {
                int nb = warpN * 32 + np * 16;
                uint32_t r0, r1, r2, r3;
                ldsm4(r0, r1, r2, r3,
                      Bsm + (size_t)(nb + b_r + b_n8) * GPAD + kb + b_k8);
                bH[np * 2][0] = r0; bH[np * 2][1] = r1;
                bH[np * 2 + 1][0] = r2; bH[np * 2 + 1][1] = r3;
                ldsm4(r0, r1, r2, r3,
                      Bsm + 128 * GPAD + (size_t)(nb + b_r + b_n8) * GPAD + kb + b_k8);
                bL[np * 2][0] = r0; bL[np * 2][1] = r1;
                bL[np * 2 + 1][0] = r2; bL[np * 2 + 1][1] = r3;
            }
#pragma unroll
            for (int mi = 0; mi < 4; mi++)
#pragma unroll
                for (int ni = 0; ni < 4; ni++) {
                    mma16816(c[mi][ni], aH[mi][0], aH[mi][1], aH[mi][2], aH[mi][3],
                             bH[ni][0], bH[ni][1]);
                    mma16816(c[mi][ni], aH[mi][0], aH[mi][1], aH[mi][2], aH[mi][3],
                             bL[ni][0], bL[ni][1]);
                    mma16816(c[mi][ni], aL[mi][0], aL[mi][1], aL[mi][2], aL[mi][3],
                             bH[ni][0], bH[ni][1]);
                }
        }
        __syncthreads();
    }

#pragma unroll
    for (int mi = 0; mi < 4; mi++) {
        int r0 = bm + warpM * 64 + mi * 16 + g;
#pragma unroll
        for (int ni = 0; ni < 4; ni++) {
            int cc = bn + warpN * 32 + ni * 8 + 2 * tg;
            *(float2*)(C + (size_t)r0 * N + cc) = make_float2(c[mi][ni][0], c[mi][ni][1]);
            *(float2*)(C + (size_t)(r0 + 8) * N + cc) = make_float2(c[mi][ni][2], c[mi][ni][3]);
        }
    }
}

// ---------------------------------------------------------------------------
// Flash attention, split-bf16 mma.sync (round-5 structure, bf16 split output).
// 128 threads (4 warps), 64 q rows (16/warp), 64-key tiles, 106KB -> 2 CTA/SM.
// ---------------------------------------------------------------------------
#define FQH 0
#define FQL 8704
#define FKH 17408
#define FKL 26112
#define FVH 34816
#define FVL 44032
#define FSMEM_B 106496

__global__ __launch_bounds__(128)
void flash_mma(const __nv_bfloat16* __restrict__ Qh, const __nv_bfloat16* __restrict__ Ql,
               const __nv_bfloat16* __restrict__ Kh, const __nv_bfloat16* __restrict__ Kl,
               const __nv_bfloat16* __restrict__ Vth, const __nv_bfloat16* __restrict__ Vtl,
               __nv_bfloat16* __restrict__ Oh, __nv_bfloat16* __restrict__ Ol) {
    extern __shared__ __nv_bfloat16 fsm[];
    const uint32_t sb = smem_u32(fsm);

    const int b = blockIdx.z, h = blockIdx.y, qt = blockIdx.x;
    const int qs = qt * 64, hk = h >> 2;
    const int tid = threadIdx.x;
    const int warp = tid >> 5, lane = tid & 31;
    const int g = lane >> 2, tg = lane & 3;

    const int a_r = lane & 15;
    const int a_k = (lane >> 4) * 8;
    const int b_r = lane & 7;
    const int b_n8 = ((lane >> 4) & 1) * 8;
    const int b_k8 = ((lane >> 3) & 1) * 8;

    // ---- load Q tile (once) ----
#pragma unroll
    for (int i = 0; i < 8; i++) {
        int j = tid + (i << 7);
        int row = j >> 4, kc = j & 15;
        uint32_t d = sb + (uint32_t)((row * 136 + kc * 8) * 2);
        size_t src = ((size_t)(b * S_ + qs + row) * NH_ + h) * HD_ + kc * 8;
        cp16(d + FQH * 2, Qh + src);
        cp16(d + FQL * 2, Ql + src);
    }
    asm volatile("cp.async.commit_group;\n");

    float o[16][4];
#pragma unroll
    for (int nt = 0; nt < 16; nt++)
#pragma unroll
        for (int j = 0; j < 4; j++) o[nt][j] = 0.f;
    float m0 = -1e30f, m1 = -1e30f, l0 = 0.f, l1 = 0.f;

    const int qr0 = qs + warp * 16 + g;
    const int qr1 = qr0 + 8;
    const int ntiles = qt + 1;

    for (int j = 0; j < ntiles; j++) {
        const int ks = j * 64;
        // ---- load K and Vt tiles ----
#pragma unroll
        for (int i = 0; i < 8; i++) {
            int jj = tid + (i << 7);
            int krow = jj >> 4, kkc = jj & 15;
            uint32_t dk = sb + (uint32_t)((krow * 136 + kkc * 8) * 2);
            size_t ksrc = ((size_t)(b * S_ + ks + krow) * NKV_ + hk) * HD_ + kkc * 8;
            cp16(dk + FKH * 2, Kh + ksrc);
            cp16(dk + FKL * 2, Kl + ksrc);
            int vd = jj >> 3, vc = jj & 7;
            uint32_t dv = sb + (uint32_t)((vd * 72 + vc * 8) * 2);
            size_t vsrc = ((size_t)(b * NKV_ + hk) * HD_ + vd) * S_ + ks + vc * 8;
            cp16(dv + FVH * 2, Vth + vsrc);
            cp16(dv + FVL * 2, Vtl + vsrc);
        }
        asm volatile("cp.async.commit_group;\n");
        asm volatile("cp.async.wait_group 0;\n");
        __syncthreads();

        // ---- S = Q K^T (3-plane) ----
        float S4[8][4];
#pragma unroll
        for (int nt = 0; nt < 8; nt++)
#pragma unroll
            for (int cc = 0; cc < 4; cc++) S4[nt][cc] = 0.f;

#pragma unroll
        for (int dk = 0; dk < 8; dk++) {
            uint32_t aH[4], aL[4];
            ldsm4(aH[0], aH[1], aH[2], aH[3],
                  fsm + FQH + (size_t)(warp * 16 + a_r) * 136 + dk * 16 + a_k);
            ldsm4(aL[0], aL[1], aL[2], aL[3],
                  fsm + FQL + (size_t)(warp * 16 + a_r) * 136 + dk * 16 + a_k);
#pragma unroll
            for (int np = 0; np < 4; np++) {
                int nb = np * 16;
                uint32_t h0, h1, h2, h3, l0r, l1r, l2r, l3r;
                ldsm4(h0, h1, h2, h3,
                      fsm + FKH + (size_t)(nb + b_r + b_n8) * 136 + dk * 16 + b_k8);
                ldsm4(l0r, l1r, l2r, l3r,
                      fsm + FKL + (size_t)(nb + b_r + b_n8) * 136 + dk * 16 + b_k8);
                mma16816(S4[2 * np],     aH[0], aH[1], aH[2], aH[3], h0, h1);
                mma16816(S4[2 * np],     aH[0], aH[1], aH[2], aH[3], l0r, l1r);
                mma16816(S4[2 * np],     aL[0], aL[1], aL[2], aL[3], h0, h1);
                mma16816(S4[2 * np + 1], aH[0], aH[1], aH[2], aH[3], h2, h3);
                mma16816(S4[2 * np + 1], aH[0], aH[1], aH[2], aH[3], l2r, l3r);
                mma16816(S4[2 * np + 1], aL[0], aL[1], aL[2], aL[3], h2, h3);
            }
        }

        // ---- scale + mask + online softmax ----
        float mx0 = -1e30f, mx1 = -1e30f;
        const bool diag = (j == ntiles - 1);
#pragma unroll
        for (int nt = 0; nt < 8; nt++) {
#pragma unroll
            for (int cc = 0; cc < 4; cc++) {
                float v = S4[nt][cc] * SCALING_;
                if (diag) {
                    int kcol = ks + nt * 8 + 2 * tg + (cc & 1);
                    int qr = (cc < 2) ? qr0 : qr1;
                    if (kcol > qr) v = -1e30f;
                }
                S4[nt][cc] = v;
                if (cc < 2) mx0 = fmaxf(mx0, v); else mx1 = fmaxf(mx1, v);
            }
        }
        mx0 = fmaxf(mx0, __shfl_xor_sync(0xffffffffu, mx0, 1));
        mx0 = fmaxf(mx0, __shfl_xor_sync(0xffffffffu, mx0, 2));
        mx1 = fmaxf(mx1, __shfl_xor_sync(0xffffffffu, mx1, 1));
        mx1 = fmaxf(mx1, __shfl_xor_sync(0xffffffffu, mx1, 2));
        const float mt0 = fmaxf(m0, mx0), mt1 = fmaxf(m1, mx1);
        const float sc0 = __expf(m0 - mt0), sc1 = __expf(m1 - mt1);
        m0 = mt0; m1 = mt1;

        float rs0 = 0.f, rs1 = 0.f;
#pragma unroll
        for (int nt = 0; nt < 8; nt++) {
            float p0 = __expf(S4[nt][0] - mt0);
            float p1 = __expf(S4[nt][1] - mt0);
            float p2 = __expf(S4[nt][2] - mt1);
            float p3 = __expf(S4[nt][3] - mt1);
            S4[nt][0] = p0; S4[nt][1] = p1; S4[nt][2] = p2; S4[nt][3] = p3;
            rs0 += p0 + p1; rs1 += p2 + p3;
        }
        rs0 += __shfl_xor_sync(0xffffffffu, rs0, 1);
        rs0 += __shfl_xor_sync(0xffffffffu, rs0, 2);
        rs1 += __shfl_xor_sync(0xffffffffu, rs1, 1);
        rs1 += __shfl_xor_sync(0xffffffffu, rs1, 2);
        l0 = l0 * sc0 + rs0;
        l1 = l1 * sc1 + rs1;
#pragma unroll
        for (int nt = 0; nt < 16; nt++) {
            o[nt][0] *= sc0; o[nt][1] *= sc0;
            o[nt][2] *= sc1; o[nt][3] *= sc1;
        }

        // ---- O += P V (3-plane, P split in registers) ----
#pragma unroll
        for (int kt = 0; kt < 4; kt++) {
            uint32_t aPh[4], aPl[4];
#pragma unroll
            for (int half = 0; half < 2; half++) {
                const float* sv = S4[2 * kt + half];
                uint32_t p01 = pk_bf2(sv[0], sv[1]);
                uint32_t p23 = pk_bf2(sv[2], sv[3]);
                float r0f = sv[0] - __uint_as_float(p01 << 16);
                float r1f = sv[1] - __uint_as_float(p01 & 0xffff0000u);
                float r2f = sv[2] - __uint_as_float(p23 << 16);
                float r3f = sv[3] - __uint_as_float(p23 & 0xffff0000u);
                aPh[0 + 2 * half] = p01;
                aPh[1 + 2 * half] = p23;
                aPl[0 + 2 * half] = pk_bf2(r0f, r1f);
                aPl[1 + 2 * half] = pk_bf2(r2f, r3f);
            }
#pragma unroll
            for (int np = 0; np < 8; np++) {
                int nb = np * 16;
                uint32_t h0, h1, h2, h3, l0r, l1r, l2r, l3r;
                ldsm4(h0, h1, h2, h3,
                      fsm + FVH + (size_t)(nb + b_r + b_n8) * 72 + kt * 16 + b_k8);
                ldsm4(l0r, l1r, l2r, l3r,
                      fsm + FVL + (size_t)(nb + b_r + b_n8) * 72 + kt * 16 + b_k8);
                mma16816(o[2 * np],     aPh[0], aPh[1], aPh[2], aPh[3], h0, h1);
                mma16816(o[2 * np],     aPh[0], aPh[1], aPh[2], aPh[3], l0r, l1r);
                mma16816(o[2 * np],     aPl[0], aPl[1], aPl[2], aPl[3], h0, h1);
                mma16816(o[2 * np + 1], aPh[0], aPh[1], aPh[2], aPh[3], h2, h3);
                mma16816(o[2 * np + 1], aPh[0], aPh[1], aPh[2], aPh[3], l2r, l3r);
                mma16816(o[2 * np + 1], aPl[0], aPl[1], aPl[2], aPl[3], h2, h3);
            }
        }
        __syncthreads();
    }

    // ---- writeback: split fp32 -> bf16 h/l planes directly ----
    const float inv0 = 1.f / l0, inv1 = 1.f / l1;
    const size_t r0base = ((size_t)(b * S_ + qr0) * NH_ + h) * HD_;
    const size_t r1base = ((size_t)(b * S_ + qr1) * NH_ + h) * HD_;
#pragma unroll
    for (int nt = 0; nt < 16; nt++) {
        int cc = nt * 8 + 2 * tg;
        float v00 = o[nt][0] * inv0, v01 = o[nt][1] * inv0;
        float v10 = o[nt][2] * inv1, v11 = o[nt][3] * inv1;
        uint32_t h0p = pk_bf2(v00, v01);
        uint32_t h1p = pk_bf2(v10, v11);
        float e00 = v00 - __uint_as_float(h0p << 16);
        float e01 = v01 - __uint_as_float(h0p & 0xffff0000u);
        float e10 = v10 - __uint_as_float(h1p << 16);
        float e11 = v11 - __uint_as_float(h1p & 0xffff0000u);
        *(uint32_t*)(Oh + r0base + cc) = h0p;
        *(uint32_t*)(Ol + r0base + cc) = pk_bf2(e00, e01);
        *(uint32_t*)(Oh + r1base + cc) = h1p;
        *(uint32_t*)(Ol + r1base + cc) = pk_bf2(e10, e11);
    }
}

// ---------------------------------------------------------------------------
// Launch
// ---------------------------------------------------------------------------
extern "C" void kernel_launch(void* const* d_in, const int* in_sizes, int n_in,
                              void* d_out, int out_size) {
    const float* hs   = (const float*)d_in[0];
    const float* cosp = (const float*)d_in[1];
    const float* sinp = (const float*)d_in[2];
    const float* Wq   = (const float*)d_in[4];
    const float* Wk   = (const float*)d_in[5];
    const float* Wv   = (const float*)d_in[6];
    const float* Wo   = (const float*)d_in[7];
    float* out = (float*)d_out;

    float *qbuf, *kbuf, *vbuf;
    cudaGetSymbolAddress((void**)&qbuf, g_q);
    cudaGetSymbolAddress((void**)&kbuf, g_k);
    cudaGetSymbolAddress((void**)&vbuf, g_v);

    __nv_bfloat16 *hs_h, *hs_l, *wq_h, *wq_l, *wk_h, *wk_l, *wv_h, *wv_l,
                  *wo_h, *wo_l, *ob_h, *ob_l, *qh, *ql, *kh, *kl, *vth, *vtl;
    cudaGetSymbolAddress((void**)&hs_h, g_hs_h); cudaGetSymbolAddress((void**)&hs_l, g_hs_l);
    cudaGetSymbolAddress((void**)&wq_h, g_wq_h); cudaGetSymbolAddress((void**)&wq_l, g_wq_l);
    cudaGetSymbolAddress((void**)&wk_h, g_wk_h); cudaGetSymbolAddress((void**)&wk_l, g_wk_l);
    cudaGetSymbolAddress((void**)&wv_h, g_wv_h); cudaGetSymbolAddress((void**)&wv_l, g_wv_l);
    cudaGetSymbolAddress((void**)&wo_h, g_wo_h); cudaGetSymbolAddress((void**)&wo_l, g_wo_l);
    cudaGetSymbolAddress((void**)&ob_h, g_ob_h); cudaGetSymbolAddress((void**)&ob_l, g_ob_l);
    cudaGetSymbolAddress((void**)&qh, g_qh); cudaGetSymbolAddress((void**)&ql, g_ql);
    cudaGetSymbolAddress((void**)&kh, g_kh); cudaGetSymbolAddress((void**)&kl, g_kl);
    cudaGetSymbolAddress((void**)&vth, g_vth); cudaGetSymbolAddress((void**)&vtl, g_vtl);

    cudaFuncSetAttribute(gemm_mma, cudaFuncAttributeMaxDynamicSharedMemorySize, GSMEM_B);
    cudaFuncSetAttribute(flash_mma, cudaFuncAttributeMaxDynamicSharedMemorySize, FSMEM_B);

    const int M = B_ * S_;   // 4096

    // Split conversions (inputs)
    split_kernel<<<(HS_ELEMS / 4 + 255) / 256, 256>>>(hs, hs_h, hs_l, HS_ELEMS);
    split_kernel<<<(WQ_ELEMS / 4 + 255) / 256, 256>>>(Wq, wq_h, wq_l, WQ_ELEMS);
    split_kernel<<<(WK_ELEMS / 4 + 255) / 256, 256>>>(Wk, wk_h, wk_l, WK_ELEMS);
    split_kernel<<<(WK_ELEMS / 4 + 255) / 256, 256>>>(Wv, wv_h, wv_l, WK_ELEMS);
    split_kernel<<<(WO_ELEMS / 4 + 255) / 256, 256>>>(Wo, wo_h, wo_l, WO_ELEMS);

    // QKV projections
    gemm_mma<<<dim3((NH_ * HD_) / BN, M / BM), 256, GSMEM_B>>>(hs_h, hs_l, wq_h, wq_l, qbuf, M, NH_ * HD_, HID_);
    gemm_mma<<<dim3((NKV_ * HD_) / BN, M / BM), 256, GSMEM_B>>>(hs_h, hs_l, wk_h, wk_l, kbuf, M, NKV_ * HD_, HID_);
    gemm_mma<<<dim3((NKV_ * HD_) / BN, M / BM), 256, GSMEM_B>>>(hs_h, hs_l, wv_h, wv_l, vbuf, M, NKV_ * HD_, HID_);

    // Fused RoPE + split; V split+transpose
    {
        int totq = B_ * S_ * NH_ * 64;
        rope_split<<<(totq + 255) / 256, 256>>>(qbuf, cosp, sinp, qh, ql, NH_, totq);
        int totk = B_ * S_ * NKV_ * 64;
        rope_split<<<(totk + 255) / 256, 256>>>(kbuf, cosp, sinp, kh, kl, NKV_, totk);
        splitT_v<<<(KV_ELEMS + 255) / 256, 256>>>(vbuf, vth, vtl);
    }

    // Flash attention (split-bf16 mma, bf16 split output)
    flash_mma<<<dim3(S_ / 64, NH_, B_), 128, FSMEM_B>>>(qh, ql, kh, kl, vth, vtl, ob_h, ob_l);

    // O projection
    gemm_mma<<<dim3(HID_ / BN, M / BM), 256, GSMEM_B>>>(ob_h, ob_l, wo_h, wo_l, out, M, HID_, NH_ * HD_);
}

// round 8
// speedup vs baseline: 1.1150x; 1.0018x over previous
#include <cuda_runtime.h>
#include <cuda_bf16.h>
#include <cstdint>

// Problem constants
#define B_   2
#define S_   2048
#define HID_ 4096
#define NH_  32
#define NKV_ 8
#define HD_  128
#define NREP_ 4
#define SCALING_ 0.08838834764831843f   // 128^-0.5

#define NQKV 6144      // 4096 (Q) + 1024 (K) + 1024 (V)
#define KOFF 4096
#define VOFF 5120

// fp32 scratch: fused QKV GEMM output [B*S][NQKV]
__device__ float g_qkv[(size_t)B_ * S_ * NQKV];

// bf16 split planes
#define HS_ELEMS   ((size_t)B_ * S_ * HID_)
#define WQKV_ELEMS ((size_t)NQKV * HID_)
#define WQ_ELEMS   ((size_t)NH_ * HD_ * HID_)
#define WK_ELEMS   ((size_t)NKV_ * HD_ * HID_)
#define WO_ELEMS   ((size_t)HID_ * NH_ * HD_)
#define KV_ELEMS   ((size_t)B_ * S_ * NKV_ * HD_)
__device__ __nv_bfloat16 g_hs_h[HS_ELEMS], g_hs_l[HS_ELEMS];
__device__ __nv_bfloat16 g_wqkv_h[WQKV_ELEMS], g_wqkv_l[WQKV_ELEMS];
__device__ __nv_bfloat16 g_wo_h[WO_ELEMS], g_wo_l[WO_ELEMS];
__device__ __nv_bfloat16 g_ob_h[HS_ELEMS], g_ob_l[HS_ELEMS];
// attention bf16 planes (post-rope)
__device__ __nv_bfloat16 g_qh[HS_ELEMS], g_ql[HS_ELEMS];
__device__ __nv_bfloat16 g_kh[KV_ELEMS], g_kl[KV_ELEMS];
__device__ __nv_bfloat16 g_vth[KV_ELEMS], g_vtl[KV_ELEMS];  // [b][hk][d][s]

// ---------------------------------------------------------------------------
// helpers
// ---------------------------------------------------------------------------
static __device__ __forceinline__ uint32_t smem_u32(const void* p) {
    uint32_t a;
    asm("{ .reg .u64 t; cvta.to.shared.u64 t, %1; cvt.u32.u64 %0, t; }"
        : "=r"(a) : "l"(p));
    return a;
}
static __device__ __forceinline__ void cp16(uint32_t dst, const void* src) {
    asm volatile("cp.async.cg.shared.global [%0], [%1], 16;\n" :: "r"(dst), "l"(src));
}
__device__ __forceinline__ void mma16816(float c[4], uint32_t a0, uint32_t a1,
                                         uint32_t a2, uint32_t a3,
                                         uint32_t b0, uint32_t b1) {
    asm volatile(
        "mma.sync.aligned.m16n8k16.row.col.f32.bf16.bf16.f32 "
        "{%0,%1,%2,%3}, {%4,%5,%6,%7}, {%8,%9}, {%0,%1,%2,%3};\n"
        : "+f"(c[0]), "+f"(c[1]), "+f"(c[2]), "+f"(c[3])
        : "r"(a0), "r"(a1), "r"(a2), "r"(a3), "r"(b0), "r"(b1));
}
__device__ __forceinline__ void ldsm4(uint32_t& r0, uint32_t& r1, uint32_t& r2,
                                      uint32_t& r3, const void* p) {
    uint32_t a = (uint32_t)__cvta_generic_to_shared(p);
    asm volatile("ldmatrix.sync.aligned.m8n8.x4.shared.b16 {%0,%1,%2,%3}, [%4];\n"
                 : "=r"(r0), "=r"(r1), "=r"(r2), "=r"(r3) : "r"(a));
}
static __device__ __forceinline__ uint32_t pk_bf2(float lo, float hi) {
    __nv_bfloat162 t = __floats2bfloat162_rn(lo, hi);
    return *reinterpret_cast<uint32_t*>(&t);
}

// ---------------------------------------------------------------------------
// fp32 -> (bf16 hi, bf16 lo) split
// ---------------------------------------------------------------------------
__global__ void split_kernel(const float* __restrict__ x,
                             __nv_bfloat16* __restrict__ hi,
                             __nv_bfloat16* __restrict__ lo, size_t n) {
    size_t i = ((size_t)blockIdx.x * blockDim.x + threadIdx.x) * 4;
    if (i >= n) return;
    float4 v = *(const float4*)(x + i);
    float f[4] = {v.x, v.y, v.z, v.w};
#pragma unroll
    for (int j = 0; j < 4; j++) {
        __nv_bfloat16 h = __float2bfloat16(f[j]);
        hi[i + j] = h;
        lo[i + j] = __float2bfloat16(f[j] - __bfloat162float(h));
    }
}

// fused RoPE + split. x: [B*S][NQKV] at column offset hoff; out: dense planes.
__global__ void rope_split(const float* __restrict__ x, int hoff,
                           const float* __restrict__ cosp,
                           const float* __restrict__ sinp,
                           __nv_bfloat16* __restrict__ xh,
                           __nv_bfloat16* __restrict__ xl,
                           int nheads, int total) {
    int idx = blockIdx.x * blockDim.x + threadIdx.x;
    if (idx >= total) return;
    int d  = idx & 63;
    int h  = (idx >> 6) % nheads;
    int bs = idx / (64 * nheads);
    const float* row = x + (size_t)bs * NQKV + hoff + (size_t)h * HD_;
    const float* c = cosp + (size_t)bs * HD_;
    const float* s = sinp + (size_t)bs * HD_;
    float x1 = row[d], x2 = row[d + 64];
    float y1 = x1 * c[d]      - x2 * s[d];
    float y2 = x2 * c[d + 64] + x1 * s[d + 64];
    size_t base = (size_t)bs * nheads * HD_ + (size_t)h * HD_;
    __nv_bfloat16 h1 = __float2bfloat16(y1);
    __nv_bfloat16 h2 = __float2bfloat16(y2);
    xh[base + d]      = h1;
    xh[base + d + 64] = h2;
    xl[base + d]      = __float2bfloat16(y1 - __bfloat162float(h1));
    xl[base + d + 64] = __float2bfloat16(y2 - __bfloat162float(h2));
}

// split + transpose V: in [B*S][NQKV] @ VOFF -> out [b][hk][d][s] bf16 h/l
__global__ void splitT_v(const float* __restrict__ v,
                         __nv_bfloat16* __restrict__ vh,
                         __nv_bfloat16* __restrict__ vl) {
    size_t idx = (size_t)blockIdx.x * blockDim.x + threadIdx.x;
    if (idx >= KV_ELEMS) return;
    int s  = idx & (S_ - 1);
    size_t r = idx >> 11;
    int d  = r & (HD_ - 1);  r >>= 7;
    int hk = r & (NKV_ - 1);
    int b  = (int)(r >> 3);
    float x = v[(size_t)(b * S_ + s) * NQKV + VOFF + hk * HD_ + d];
    __nv_bfloat16 h = __float2bfloat16(x);
    vh[idx] = h;
    vl[idx] = __float2bfloat16(x - __bfloat162float(h));
}

// ---------------------------------------------------------------------------
// Split-bf16 NT GEMM, mma.sync, BK=32 per stage, 2-stage cp.async.
// 256 threads (8 warps 2x4), warp tile 64x32, 3 planes. 80KB smem -> 2 CTA/SM.
// L2-locality CTA swizzle: 16-row groups (gridDim.y must be mult of 16).
// ---------------------------------------------------------------------------
#define BM 128
#define BN 128
#define GK 32
#define GPAD 40
#define GA_ELEMS 20480   // 2 stages * 2 planes * 128 * 40
#define GSMEM_B ((GA_ELEMS * 2) * 2)   // bytes: 81920
#define SWG 16

__global__ __launch_bounds__(256)
void gemm_mma(const __nv_bfloat16* __restrict__ Ah, const __nv_bfloat16* __restrict__ Al,
              const __nv_bfloat16* __restrict__ Bh, const __nv_bfloat16* __restrict__ Bl,
              float* __restrict__ C, int M, int N, int K) {
    extern __shared__ __nv_bfloat16 gsm[];
    const uint32_t sb = smem_u32(gsm);

    const int tid = threadIdx.x;
    const int warp = tid >> 5, lane = tid & 31;
    const int g = lane >> 2, tg = lane & 3;
    const int warpM = warp >> 2, warpN = warp & 3;

    // CTA swizzle: group SWG rows so one wave stays in a compact M x N window
    int bx, by;
    {
        int bid = blockIdx.y * gridDim.x + blockIdx.x;
        int per = SWG * gridDim.x;
        int grp = bid / per;
        int rem = bid - grp * per;
        by = grp * SWG + (rem & (SWG - 1));
        bx = rem >> 4;                       // rem / SWG  (SWG = 16)
    }
    const int bm = by * BM, bn = bx * BN;

    const int a_r = lane & 15;
    const int a_k = (lane >> 4) * 8;
    const int b_r = lane & 7;
    const int b_n8 = ((lane >> 4) & 1) * 8;
    const int b_k8 = ((lane >> 3) & 1) * 8;

    float c[4][4][4];
#pragma unroll
    for (int mi = 0; mi < 4; mi++)
#pragma unroll
        for (int ni = 0; ni < 4; ni++)
#pragma unroll
            for (int j = 0; j < 4; j++) c[mi][ni][j] = 0.f;

    const int niter = K / GK;

    auto load_stage = [&](int s, int k0) {
#pragma unroll
        for (int i = 0; i < 2; i++) {
            int j = tid + (i << 8);
            int row = j >> 2, col = (j & 3) * 8;
            size_t ao = (size_t)(bm + row) * K + k0 + col;
            size_t bo = (size_t)(bn + row) * K + k0 + col;
            uint32_t da = sb + (uint32_t)((((s * 2) * 128 + row) * GPAD + col) * 2);
            uint32_t db = sb + (uint32_t)((GA_ELEMS + ((s * 2) * 128 + row) * GPAD + col) * 2);
            cp16(da, Ah + ao);
            cp16(da + 128 * GPAD * 2, Al + ao);
            cp16(db, Bh + bo);
            cp16(db + 128 * GPAD * 2, Bl + bo);
        }
        asm volatile("cp.async.commit_group;\n");
    };

    load_stage(0, 0);

    for (int i = 0; i < niter; i++) {
        if (i + 1 < niter) {
            load_stage((i + 1) & 1, (i + 1) * GK);
            asm volatile("cp.async.wait_group 1;\n");
        } else {
            asm volatile("cp.async.wait_group 0;\n");
        }
        __syncthreads();

        const int s = i & 1;
        const __nv_bfloat16* Asm = gsm + (size_t)(s * 2) * 128 * GPAD;
        const __nv_bfloat16* Bsm = gsm + GA_ELEMS + (size_t)(s * 2) * 128 * GPAD;
#pragma unroll
        for (int kk = 0; kk < 2; kk++) {
            const int kb = kk * 16;
            uint32_t aH[4][4], aL[4][4], bH[4][2], bL[4][2];
#pragma unroll
            for (int mi = 0; mi < 4; mi++) {
                int rb = warpM * 64 + mi * 16;
                ldsm4(aH[mi][0], aH[mi][1], aH[mi][2], aH[mi][3],
                      Asm + (size_t)(rb + a_r) * GPAD + kb + a_k);
                ldsm4(aL[mi][0], aL[mi][1], aL[mi][2], aL[mi][3],
                      Asm + 128 * GPAD + (size_t)(rb + a_r) * GPAD + kb + a_k);
            }
#pragma unroll
            for (int np = 0; np < 2; np++) {
                int nb = warpN * 32 + np * 16;
                uint32_t r0, r1, r2, r3;
                ldsm4(r0, r1, r2, r3,
                      Bsm + (size_t)(nb + b_r + b_n8) * GPAD + kb + b_k8);
                bH[np * 2][0] = r0; bH[np * 2][1] = r1;
                bH[np * 2 + 1][0] = r2; bH[np * 2 + 1][1] = r3;
                ldsm4(r0, r1, r2, r3,
                      Bsm + 128 * GPAD + (size_t)(nb + b_r + b_n8) * GPAD + kb + b_k8);
                bL[np * 2][0] = r0; bL[np * 2][1] = r1;
                bL[np * 2 + 1][0] = r2; bL[np * 2 + 1][1] = r3;
            }
#pragma unroll
            for (int mi = 0; mi < 4; mi++)
#pragma unroll
                for (int ni = 0; ni < 4; ni++) {
                    mma16816(c[mi][ni], aH[mi][0], aH[mi][1], aH[mi][2], aH[mi][3],
                             bH[ni][0], bH[ni][1]);
                    mma16816(c[mi][ni], aH[mi][0], aH[mi][1], aH[mi][2], aH[mi][3],
                             bL[ni][0], bL[ni][1]);
                    mma16816(c[mi][ni], aL[mi][0], aL[mi][1], aL[mi][2], aL[mi][3],
                             bH[ni][0], bH[ni][1]);
                }
        }
        __syncthreads();
    }

#pragma unroll
    for (int mi = 0; mi < 4; mi++) {
        int r0 = bm + warpM * 64 + mi * 16 + g;
#pragma unroll
        for (int ni = 0; ni < 4; ni++) {
            int cc = bn + warpN * 32 + ni * 8 + 2 * tg;
            *(float2*)(C + (size_t)r0 * N + cc) = make_float2(c[mi][ni][0], c[mi][ni][1]);
            *(float2*)(C + (size_t)(r0 + 8) * N + cc) = make_float2(c[mi][ni][2], c[mi][ni][3]);
        }
    }
}

// ---------------------------------------------------------------------------
// Flash attention, split-bf16 mma.sync (proven round-5/7 structure).
// 128 threads (4 warps), 64 q rows (16/warp), 64-key tiles, 106KB -> 2 CTA/SM.
// ---------------------------------------------------------------------------
#define FQH 0
#define FQL 8704
#define FKH 17408
#define FKL 26112
#define FVH 34816
#define FVL 44032
#define FSMEM_B 106496

__global__ __launch_bounds__(128)
void flash_mma(const __nv_bfloat16* __restrict__ Qh, const __nv_bfloat16* __restrict__ Ql,
               const __nv_bfloat16* __restrict__ Kh, const __nv_bfloat16* __restrict__ Kl,
               const __nv_bfloat16* __restrict__ Vth, const __nv_bfloat16* __restrict__ Vtl,
               __nv_bfloat16* __restrict__ Oh, __nv_bfloat16* __restrict__ Ol) {
    extern __shared__ __nv_bfloat16 fsm[];
    const uint32_t sb = smem_u32(fsm);

    const int b = blockIdx.z, h = blockIdx.y, qt = blockIdx.x;
    const int qs = qt * 64, hk = h >> 2;
    const int tid = threadIdx.x;
    const int warp = tid >> 5, lane = tid & 31;
    const int g = lane >> 2, tg = lane & 3;

    const int a_r = lane & 15;
    const int a_k = (lane >> 4) * 8;
    const int b_r = lane & 7;
    const int b_n8 = ((lane >> 4) & 1) * 8;
    const int b_k8 = ((lane >> 3) & 1) * 8;

    // ---- load Q tile (once) ----
#pragma unroll
    for (int i = 0; i < 8; i++) {
        int j = tid + (i << 7);
        int row = j >> 4, kc = j & 15;
        uint32_t d = sb + (uint32_t)((row * 136 + kc * 8) * 2);
        size_t src = ((size_t)(b * S_ + qs + row) * NH_ + h) * HD_ + kc * 8;
        cp16(d + FQH * 2, Qh + src);
        cp16(d + FQL * 2, Ql + src);
    }
    asm volatile("cp.async.commit_group;\n");

    float o[16][4];
#pragma unroll
    for (int nt = 0; nt < 16; nt++)
#pragma unroll
        for (int j = 0; j < 4; j++) o[nt][j] = 0.f;
    float m0 = -1e30f, m1 = -1e30f, l0 = 0.f, l1 = 0.f;

    const int qr0 = qs + warp * 16 + g;
    const int qr1 = qr0 + 8;
    const int ntiles = qt + 1;

    for (int j = 0; j < ntiles; j++) {
        const int ks = j * 64;
        // ---- load K and Vt tiles ----
#pragma unroll
        for (int i = 0; i < 8; i++) {
            int jj = tid + (i << 7);
            int krow = jj >> 4, kkc = jj & 15;
            uint32_t dk = sb + (uint32_t)((krow * 136 + kkc * 8) * 2);
            size_t ksrc = ((size_t)(b * S_ + ks + krow) * NKV_ + hk) * HD_ + kkc * 8;
            cp16(dk + FKH * 2, Kh + ksrc);
            cp16(dk + FKL * 2, Kl + ksrc);
            int vd = jj >> 3, vc = jj & 7;
            uint32_t dv = sb + (uint32_t)((vd * 72 + vc * 8) * 2);
            size_t vsrc = ((size_t)(b * NKV_ + hk) * HD_ + vd) * S_ + ks + vc * 8;
            cp16(dv + FVH * 2, Vth + vsrc);
            cp16(dv + FVL * 2, Vtl + vsrc);
        }
        asm volatile("cp.async.commit_group;\n");
        asm volatile("cp.async.wait_group 0;\n");
        __syncthreads();

        // ---- S = Q K^T (3-plane) ----
        float S4[8][4];
#pragma unroll
        for (int nt = 0; nt < 8; nt++)
#pragma unroll
            for (int cc = 0; cc < 4; cc++) S4[nt][cc] = 0.f;

#pragma unroll
        for (int dk = 0; dk < 8; dk++) {
            uint32_t aH[4], aL[4];
            ldsm4(aH[0], aH[1], aH[2], aH[3],
                  fsm + FQH + (size_t)(warp * 16 + a_r) * 136 + dk * 16 + a_k);
            ldsm4(aL[0], aL[1], aL[2], aL[3],
                  fsm + FQL + (size_t)(warp * 16 + a_r) * 136 + dk * 16 + a_k);
#pragma unroll
            for (int np = 0; np < 4; np++) {
                int nb = np * 16;
                uint32_t h0, h1, h2, h3, l0r, l1r, l2r, l3r;
                ldsm4(h0, h1, h2, h3,
                      fsm + FKH + (size_t)(nb + b_r + b_n8) * 136 + dk * 16 + b_k8);
                ldsm4(l0r, l1r, l2r, l3r,
                      fsm + FKL + (size_t)(nb + b_r + b_n8) * 136 + dk * 16 + b_k8);
                mma16816(S4[2 * np],     aH[0], aH[1], aH[2], aH[3], h0, h1);
                mma16816(S4[2 * np],     aH[0], aH[1], aH[2], aH[3], l0r, l1r);
                mma16816(S4[2 * np],     aL[0], aL[1], aL[2], aL[3], h0, h1);
                mma16816(S4[2 * np + 1], aH[0], aH[1], aH[2], aH[3], h2, h3);
                mma16816(S4[2 * np + 1], aH[0], aH[1], aH[2], aH[3], l2r, l3r);
                mma16816(S4[2 * np + 1], aL[0], aL[1], aL[2], aL[3], h2, h3);
            }
        }

        // ---- scale + mask + online softmax ----
        float mx0 = -1e30f, mx1 = -1e30f;
        const bool diag = (j == ntiles - 1);
#pragma unroll
        for (int nt = 0; nt < 8; nt++) {
#pragma unroll
            for (int cc = 0; cc < 4; cc++) {
                float v = S4[nt][cc] * SCALING_;
                if (diag) {
                    int kcol = ks + nt * 8 + 2 * tg + (cc & 1);
                    int qr = (cc < 2) ? qr0 : qr1;
                    if (kcol > qr) v = -1e30f;
                }
                S4[nt][cc] = v;
                if (cc < 2) mx0 = fmaxf(mx0, v); else mx1 = fmaxf(mx1, v);
            }
        }
        mx0 = fmaxf(mx0, __shfl_xor_sync(0xffffffffu, mx0, 1));
        mx0 = fmaxf(mx0, __shfl_xor_sync(0xffffffffu, mx0, 2));
        mx1 = fmaxf(mx1, __shfl_xor_sync(0xffffffffu, mx1, 1));
        mx1 = fmaxf(mx1, __shfl_xor_sync(0xffffffffu, mx1, 2));
        const float mt0 = fmaxf(m0, mx0), mt1 = fmaxf(m1, mx1);
        const float sc0 = __expf(m0 - mt0), sc1 = __expf(m1 - mt1);
        m0 = mt0; m1 = mt1;

        float rs0 = 0.f, rs1 = 0.f;
#pragma unroll
        for (int nt = 0; nt < 8; nt++) {
            float p0 = __expf(S4[nt][0] - mt0);
            float p1 = __expf(S4[nt][1] - mt0);
            float p2 = __expf(S4[nt][2] - mt1);
            float p3 = __expf(S4[nt][3] - mt1);
            S4[nt][0] = p0; S4[nt][1] = p1; S4[nt][2] = p2; S4[nt][3] = p3;
            rs0 += p0 + p1; rs1 += p2 + p3;
        }
        rs0 += __shfl_xor_sync(0xffffffffu, rs0, 1);
        rs0 += __shfl_xor_sync(0xffffffffu, rs0, 2);
        rs1 += __shfl_xor_sync(0xffffffffu, rs1, 1);
        rs1 += __shfl_xor_sync(0xffffffffu, rs1, 2);
        l0 = l0 * sc0 + rs0;
        l1 = l1 * sc1 + rs1;
#pragma unroll
        for (int nt = 0; nt < 16; nt++) {
            o[nt][0] *= sc0; o[nt][1] *= sc0;
            o[nt][2] *= sc1; o[nt][3] *= sc1;
        }

        // ---- O += P V (3-plane, P split in registers) ----
#pragma unroll
        for (int kt = 0; kt < 4; kt++) {
            uint32_t aPh[4], aPl[4];
#pragma unroll
            for (int half = 0; half < 2; half++) {
                const float* sv = S4[2 * kt + half];
                uint32_t p01 = pk_bf2(sv[0], sv[1]);
                uint32_t p23 = pk_bf2(sv[2], sv[3]);
                float r0f = sv[0] - __uint_as_float(p01 << 16);
                float r1f = sv[1] - __uint_as_float(p01 & 0xffff0000u);
                float r2f = sv[2] - __uint_as_float(p23 << 16);
                float r3f = sv[3] - __uint_as_float(p23 & 0xffff0000u);
                aPh[0 + 2 * half] = p01;
                aPh[1 + 2 * half] = p23;
                aPl[0 + 2 * half] = pk_bf2(r0f, r1f);
                aPl[1 + 2 * half] = pk_bf2(r2f, r3f);
            }
#pragma unroll
            for (int np = 0; np < 8; np++) {
                int nb = np * 16;
                uint32_t h0, h1, h2, h3, l0r, l1r, l2r, l3r;
                ldsm4(h0, h1, h2, h3,
                      fsm + FVH + (size_t)(nb + b_r + b_n8) * 72 + kt * 16 + b_k8);
                ldsm4(l0r, l1r, l2r, l3r,
                      fsm + FVL + (size_t)(nb + b_r + b_n8) * 72 + kt * 16 + b_k8);
                mma16816(o[2 * np],     aPh[0], aPh[1], aPh[2], aPh[3], h0, h1);
                mma16816(o[2 * np],     aPh[0], aPh[1], aPh[2], aPh[3], l0r, l1r);
                mma16816(o[2 * np],     aPl[0], aPl[1], aPl[2], aPl[3], h0, h1);
                mma16816(o[2 * np + 1], aPh[0], aPh[1], aPh[2], aPh[3], h2, h3);
                mma16816(o[2 * np + 1], aPh[0], aPh[1], aPh[2], aPh[3], l2r, l3r);
                mma16816(o[2 * np + 1], aPl[0], aPl[1], aPl[2], aPl[3], h2, h3);
            }
        }
        __syncthreads();
    }

    // ---- writeback: split fp32 -> bf16 h/l planes directly ----
    const float inv0 = 1.f / l0, inv1 = 1.f / l1;
    const size_t r0base = ((size_t)(b * S_ + qr0) * NH_ + h) * HD_;
    const size_t r1base = ((size_t)(b * S_ + qr1) * NH_ + h) * HD_;
#pragma unroll
    for (int nt = 0; nt < 16; nt++) {
        int cc = nt * 8 + 2 * tg;
        float v00 = o[nt][0] * inv0, v01 = o[nt][1] * inv0;
        float v10 = o[nt][2] * inv1, v11 = o[nt][3] * inv1;
        uint32_t h0p = pk_bf2(v00, v01);
        uint32_t h1p = pk_bf2(v10, v11);
        float e00 = v00 - __uint_as_float(h0p << 16);
        float e01 = v01 - __uint_as_float(h0p & 0xffff0000u);
        float e10 = v10 - __uint_as_float(h1p << 16);
        float e11 = v11 - __uint_as_float(h1p & 0xffff0000u);
        *(uint32_t*)(Oh + r0base + cc) = h0p;
        *(uint32_t*)(Ol + r0base + cc) = pk_bf2(e00, e01);
        *(uint32_t*)(Oh + r1base + cc) = h1p;
        *(uint32_t*)(Ol + r1base + cc) = pk_bf2(e10, e11);
    }
}

// ---------------------------------------------------------------------------
// Launch
// ---------------------------------------------------------------------------
extern "C" void kernel_launch(void* const* d_in, const int* in_sizes, int n_in,
                              void* d_out, int out_size) {
    const float* hs   = (const float*)d_in[0];
    const float* cosp = (const float*)d_in[1];
    const float* sinp = (const float*)d_in[2];
    const float* Wq   = (const float*)d_in[4];
    const float* Wk   = (const float*)d_in[5];
    const float* Wv   = (const float*)d_in[6];
    const float* Wo   = (const float*)d_in[7];
    float* out = (float*)d_out;

    float* qkv;
    cudaGetSymbolAddress((void**)&qkv, g_qkv);

    __nv_bfloat16 *hs_h, *hs_l, *wqkv_h, *wqkv_l, *wo_h, *wo_l,
                  *ob_h, *ob_l, *qh, *ql, *kh, *kl, *vth, *vtl;
    cudaGetSymbolAddress((void**)&hs_h, g_hs_h); cudaGetSymbolAddress((void**)&hs_l, g_hs_l);
    cudaGetSymbolAddress((void**)&wqkv_h, g_wqkv_h); cudaGetSymbolAddress((void**)&wqkv_l, g_wqkv_l);
    cudaGetSymbolAddress((void**)&wo_h, g_wo_h); cudaGetSymbolAddress((void**)&wo_l, g_wo_l);
    cudaGetSymbolAddress((void**)&ob_h, g_ob_h); cudaGetSymbolAddress((void**)&ob_l, g_ob_l);
    cudaGetSymbolAddress((void**)&qh, g_qh); cudaGetSymbolAddress((void**)&ql, g_ql);
    cudaGetSymbolAddress((void**)&kh, g_kh); cudaGetSymbolAddress((void**)&kl, g_kl);
    cudaGetSymbolAddress((void**)&vth, g_vth); cudaGetSymbolAddress((void**)&vtl, g_vtl);

    cudaFuncSetAttribute(gemm_mma, cudaFuncAttributeMaxDynamicSharedMemorySize, GSMEM_B);
    cudaFuncSetAttribute(flash_mma, cudaFuncAttributeMaxDynamicSharedMemorySize, FSMEM_B);

    const int M = B_ * S_;   // 4096

    // Split conversions (inputs); Wq/Wk/Wv into one concatenated plane buffer
    split_kernel<<<(HS_ELEMS / 4 + 255) / 256, 256>>>(hs, hs_h, hs_l, HS_ELEMS);
    split_kernel<<<(WQ_ELEMS / 4 + 255) / 256, 256>>>(Wq, wqkv_h, wqkv_l, WQ_ELEMS);
    split_kernel<<<(WK_ELEMS / 4 + 255) / 256, 256>>>(
        Wk, wqkv_h + (size_t)KOFF * HID_, wqkv_l + (size_t)KOFF * HID_, WK_ELEMS);
    split_kernel<<<(WK_ELEMS / 4 + 255) / 256, 256>>>(
        Wv, wqkv_h + (size_t)VOFF * HID_, wqkv_l + (size_t)VOFF * HID_, WK_ELEMS);
    split_kernel<<<(WO_ELEMS / 4 + 255) / 256, 256>>>(Wo, wo_h, wo_l, WO_ELEMS);

    // Fused QKV projection: C[M][6144]
    gemm_mma<<<dim3(NQKV / BN, M / BM), 256, GSMEM_B>>>(
        hs_h, hs_l, wqkv_h, wqkv_l, qkv, M, NQKV, HID_);

    // Fused RoPE + split; V split+transpose (reading from fused buffer)
    {
        int totq = B_ * S_ * NH_ * 64;
        rope_split<<<(totq + 255) / 256, 256>>>(qkv, 0, cosp, sinp, qh, ql, NH_, totq);
        int totk = B_ * S_ * NKV_ * 64;
        rope_split<<<(totk + 255) / 256, 256>>>(qkv, KOFF, cosp, sinp, kh, kl, NKV_, totk);
        splitT_v<<<(KV_ELEMS + 255) / 256, 256>>>(qkv, vth, vtl);
    }

    // Flash attention (split-bf16 mma, bf16 split output)
    flash_mma<<<dim3(S_ / 64, NH_, B_), 128, FSMEM_B>>>(qh, ql, kh, kl, vth, vtl, ob_h, ob_l);

    // O projection
    gemm_mma<<<dim3(HID_ / BN, M / BM), 256, GSMEM_B>>>(ob_h, ob_l, wo_h, wo_l, out, M, HID_, NH_ * HD_);
}

// round 9
// speedup vs baseline: 1.1356x; 1.0185x over previous
#include <cuda_runtime.h>
#include <cuda_fp16.h>
#include <cstdint>

// Problem constants
#define B_   2
#define S_   2048
#define HID_ 4096
#define NH_  32
#define NKV_ 8
#define HD_  128
#define NREP_ 4
#define SCALING_ 0.08838834764831843f   // 128^-0.5

#define NQKV 6144      // 4096 (Q) + 1024 (K) + 1024 (V)
#define KOFF 4096
#define VOFF 5120

// fp32 scratch: fused QKV GEMM output [B*S][NQKV]
__device__ float g_qkv[(size_t)B_ * S_ * NQKV];

// fp16 split planes
#define HS_ELEMS   ((size_t)B_ * S_ * HID_)
#define WQKV_ELEMS ((size_t)NQKV * HID_)
#define WO_ELEMS   ((size_t)HID_ * NH_ * HD_)
#define KV_ELEMS   ((size_t)B_ * S_ * NKV_ * HD_)
__device__ __half g_hs_h[HS_ELEMS], g_hs_l[HS_ELEMS];
__device__ __half g_wqkv_h[WQKV_ELEMS], g_wqkv_l[WQKV_ELEMS];
__device__ __half g_wo_h[WO_ELEMS], g_wo_l[WO_ELEMS];
__device__ __half g_ob_h[HS_ELEMS], g_ob_l[HS_ELEMS];
// attention fp16 planes (post-rope)
__device__ __half g_qh[HS_ELEMS], g_ql[HS_ELEMS];
__device__ __half g_kh[KV_ELEMS], g_kl[KV_ELEMS];
__device__ __half g_vth[KV_ELEMS], g_vtl[KV_ELEMS];  // [b][hk][d][s]

// ---------------------------------------------------------------------------
// helpers
// ---------------------------------------------------------------------------
static __device__ __forceinline__ uint32_t smem_u32(const void* p) {
    uint32_t a;
    asm("{ .reg .u64 t; cvta.to.shared.u64 t, %1; cvt.u32.u64 %0, t; }"
        : "=r"(a) : "l"(p));
    return a;
}
static __device__ __forceinline__ void cp16(uint32_t dst, const void* src) {
    asm volatile("cp.async.cg.shared.global [%0], [%1], 16;\n" :: "r"(dst), "l"(src));
}
// fp16 inputs, fp32 accumulate
__device__ __forceinline__ void mma16816(float c[4], uint32_t a0, uint32_t a1,
                                         uint32_t a2, uint32_t a3,
                                         uint32_t b0, uint32_t b1) {
    asm volatile(
        "mma.sync.aligned.m16n8k16.row.col.f32.f16.f16.f32 "
        "{%0,%1,%2,%3}, {%4,%5,%6,%7}, {%8,%9}, {%0,%1,%2,%3};\n"
        : "+f"(c[0]), "+f"(c[1]), "+f"(c[2]), "+f"(c[3])
        : "r"(a0), "r"(a1), "r"(a2), "r"(a3), "r"(b0), "r"(b1));
}
// fp16 inputs, fp16 accumulate (correction terms)
__device__ __forceinline__ void mma16816h(uint32_t& c0, uint32_t& c1,
                                          uint32_t a0, uint32_t a1,
                                          uint32_t a2, uint32_t a3,
                                          uint32_t b0, uint32_t b1) {
    asm volatile(
        "mma.sync.aligned.m16n8k16.row.col.f16.f16.f16.f16 "
        "{%0,%1}, {%2,%3,%4,%5}, {%6,%7}, {%0,%1};\n"
        : "+r"(c0), "+r"(c1)
        : "r"(a0), "r"(a1), "r"(a2), "r"(a3), "r"(b0), "r"(b1));
}
__device__ __forceinline__ void ldsm4(uint32_t& r0, uint32_t& r1, uint32_t& r2,
                                      uint32_t& r3, const void* p) {
    uint32_t a = (uint32_t)__cvta_generic_to_shared(p);
    asm volatile("ldmatrix.sync.aligned.m8n8.x4.shared.b16 {%0,%1,%2,%3}, [%4];\n"
                 : "=r"(r0), "=r"(r1), "=r"(r2), "=r"(r3) : "r"(a));
}
static __device__ __forceinline__ uint32_t pk_h2(float lo, float hi) {
    __half2 t = __floats2half2_rn(lo, hi);
    return *reinterpret_cast<uint32_t*>(&t);
}
static __device__ __forceinline__ float h2lo(uint32_t u) {
    __half2 h = *reinterpret_cast<__half2*>(&u);
    return __half2float(__low2half(h));
}
static __device__ __forceinline__ float h2hi(uint32_t u) {
    __half2 h = *reinterpret_cast<__half2*>(&u);
    return __half2float(__high2half(h));
}
static __device__ __forceinline__ uint32_t h2scale(uint32_t u, float s) {
    __half2 h = *reinterpret_cast<__half2*>(&u);
    __half2 r = __hmul2(h, __float2half2_rn(s));
    return *reinterpret_cast<uint32_t*>(&r);
}

// ---------------------------------------------------------------------------
// fp32 -> (fp16 hi, fp16 lo) split
// ---------------------------------------------------------------------------
__global__ void split_kernel(const float* __restrict__ x,
                             __half* __restrict__ hi,
                             __half* __restrict__ lo, size_t n) {
    size_t i = ((size_t)blockIdx.x * blockDim.x + threadIdx.x) * 4;
    if (i >= n) return;
    float4 v = *(const float4*)(x + i);
    float f[4] = {v.x, v.y, v.z, v.w};
#pragma unroll
    for (int j = 0; j < 4; j++) {
        __half h = __float2half_rn(f[j]);
        hi[i + j] = h;
        lo[i + j] = __float2half_rn(f[j] - __half2float(h));
    }
}

// fused Wq/Wk/Wv split into concatenated planes (single launch)
__global__ void split_wqkv(const float* __restrict__ Wq,
                           const float* __restrict__ Wk,
                           const float* __restrict__ Wv,
                           __half* __restrict__ hi,
                           __half* __restrict__ lo) {
    size_t i = ((size_t)blockIdx.x * blockDim.x + threadIdx.x) * 4;
    if (i >= WQKV_ELEMS) return;
    size_t row = i / HID_;
    const float* src;
    size_t off;
    if (row < (size_t)KOFF)      { src = Wq; off = i; }
    else if (row < (size_t)VOFF) { src = Wk; off = i - (size_t)KOFF * HID_; }
    else                         { src = Wv; off = i - (size_t)VOFF * HID_; }
    float4 v = *(const float4*)(src + off);
    float f[4] = {v.x, v.y, v.z, v.w};
#pragma unroll
    for (int j = 0; j < 4; j++) {
        __half h = __float2half_rn(f[j]);
        hi[i + j] = h;
        lo[i + j] = __float2half_rn(f[j] - __half2float(h));
    }
}

// fused RoPE + split. x: [B*S][NQKV] at column offset hoff; out: dense planes.
__global__ void rope_split(const float* __restrict__ x, int hoff,
                           const float* __restrict__ cosp,
                           const float* __restrict__ sinp,
                           __half* __restrict__ xh,
                           __half* __restrict__ xl,
                           int nheads, int total) {
    int idx = blockIdx.x * blockDim.x + threadIdx.x;
    if (idx >= total) return;
    int d  = idx & 63;
    int h  = (idx >> 6) % nheads;
    int bs = idx / (64 * nheads);
    const float* row = x + (size_t)bs * NQKV + hoff + (size_t)h * HD_;
    const float* c = cosp + (size_t)bs * HD_;
    const float* s = sinp + (size_t)bs * HD_;
    float x1 = row[d], x2 = row[d + 64];
    float y1 = x1 * c[d]      - x2 * s[d];
    float y2 = x2 * c[d + 64] + x1 * s[d + 64];
    size_t base = (size_t)bs * nheads * HD_ + (size_t)h * HD_;
    __half h1 = __float2half_rn(y1);
    __half h2 = __float2half_rn(y2);
    xh[base + d]      = h1;
    xh[base + d + 64] = h2;
    xl[base + d]      = __float2half_rn(y1 - __half2float(h1));
    xl[base + d + 64] = __float2half_rn(y2 - __half2float(h2));
}

// split + transpose V: in [B*S][NQKV] @ VOFF -> out [b][hk][d][s] fp16 h/l
__global__ void splitT_v(const float* __restrict__ v,
                         __half* __restrict__ vh,
                         __half* __restrict__ vl) {
    size_t idx = (size_t)blockIdx.x * blockDim.x + threadIdx.x;
    if (idx >= KV_ELEMS) return;
    int s  = idx & (S_ - 1);
    size_t r = idx >> 11;
    int d  = r & (HD_ - 1);  r >>= 7;
    int hk = r & (NKV_ - 1);
    int b  = (int)(r >> 3);
    float x = v[(size_t)(b * S_ + s) * NQKV + VOFF + hk * HD_ + d];
    __half h = __float2half_rn(x);
    vh[idx] = h;
    vl[idx] = __float2half_rn(x - __half2float(h));
}

// ---------------------------------------------------------------------------
// Split-fp16 NT GEMM, mma.sync, BK=32 per stage, 2-stage cp.async.
// 256 threads (8 warps 2x4), warp tile 64x32, 3 planes (f32 acc). 80KB smem.
// ---------------------------------------------------------------------------
#define BM 128
#define BN 128
#define GK 32
#define GPAD 40
#define GA_ELEMS 20480
#define GSMEM_B ((GA_ELEMS * 2) * 2)   // 81920
#define SWG 16

__global__ __launch_bounds__(256)
void gemm_mma(const __half* __restrict__ Ah, const __half* __restrict__ Al,
              const __half* __restrict__ Bh, const __half* __restrict__ Bl,
              float* __restrict__ C, int M, int N, int K) {
    extern __shared__ __half gsm[];
    const uint32_t sb = smem_u32(gsm);

    const int tid = threadIdx.x;
    const int warp = tid >> 5, lane = tid & 31;
    const int g = lane >> 2, tg = lane & 3;
    const int warpM = warp >> 2, warpN = warp & 3;

    int bx, by;
    {
        int bid = blockIdx.y * gridDim.x + blockIdx.x;
        int per = SWG * gridDim.x;
        int grp = bid / per;
        int rem = bid - grp * per;
        by = grp * SWG + (rem & (SWG - 1));
        bx = rem >> 4;
    }
    const int bm = by * BM, bn = bx * BN;

    const int a_r = lane & 15;
    const int a_k = (lane >> 4) * 8;
    const int b_r = lane & 7;
    const int b_n8 = ((lane >> 4) & 1) * 8;
    const int b_k8 = ((lane >> 3) & 1) * 8;

    float c[4][4][4];
#pragma unroll
    for (int mi = 0; mi < 4; mi++)
#pragma unroll
        for (int ni = 0; ni < 4; ni++)
#pragma unroll
            for (int j = 0; j < 4; j++) c[mi][ni][j] = 0.f;

    const int niter = K / GK;

    auto load_stage = [&](int s, int k0) {
#pragma unroll
        for (int i = 0; i < 2; i++) {
            int j = tid + (i << 8);
            int row = j >> 2, col = (j & 3) * 8;
            size_t ao = (size_t)(bm + row) * K + k0 + col;
            size_t bo = (size_t)(bn + row) * K + k0 + col;
            uint32_t da = sb + (uint32_t)((((s * 2) * 128 + row) * GPAD + col) * 2);
            uint32_t db = sb + (uint32_t)((GA_ELEMS + ((s * 2) * 128 + row) * GPAD + col) * 2);
            cp16(da, Ah + ao);
            cp16(da + 128 * GPAD * 2, Al + ao);
            cp16(db, Bh + bo);
            cp16(db + 128 * GPAD * 2, Bl + bo);
        }
        asm volatile("cp.async.commit_group;\n");
    };

    load_stage(0, 0);

    for (int i = 0; i < niter; i++) {
        if (i + 1 < niter) {
            load_stage((i + 1) & 1, (i + 1) * GK);
            asm volatile("cp.async.wait_group 1;\n");
        } else {
            asm volatile("cp.async.wait_group 0;\n");
        }
        __syncthreads();

        const int s = i & 1;
        const __half* Asm = gsm + (size_t)(s * 2) * 128 * GPAD;
        const __half* Bsm = gsm + GA_ELEMS + (size_t)(s * 2) * 128 * GPAD;
#pragma unroll
        for (int kk = 0; kk < 2; kk++) {
            const int kb = kk * 16;
            uint32_t aH[4][4], aL[4][4], bH[4][2], bL[4][2];
#pragma unroll
            for (int mi = 0; mi < 4; mi++) {
                int rb = warpM * 64 + mi * 16;
                ldsm4(aH[mi][0], aH[mi][1], aH[mi][2], aH[mi][3],
                      Asm + (size_t)(rb + a_r) * GPAD + kb + a_k);
                ldsm4(aL[mi][0], aL[mi][1], aL[mi][2], aL[mi][3],
                      Asm + 128 * GPAD + (size_t)(rb + a_r) * GPAD + kb + a_k);
            }
#pragma unroll
            for (int np = 0; np < 2; np++) {
                int nb = warpN * 32 + np * 16;
                uint32_t r0, r1, r2, r3;
                ldsm4(r0, r1, r2, r3,
                      Bsm + (size_t)(nb + b_r + b_n8) * GPAD + kb + b_k8);
                bH[np * 2][0] = r0; bH[np * 2][1] = r1;
                bH[np * 2 + 1][0] = r2; bH[np * 2 + 1][1] = r3;
                ldsm4(r0, r1, r2, r3,
                      Bsm + 128 * GPAD + (size_t)(nb + b_r + b_n8) * GPAD + kb + b_k8);
                bL[np * 2][0] = r0; bL[np * 2][1] = r1;
                bL[np * 2 + 1][0] = r2; bL[np * 2 + 1][1] = r3;
            }
#pragma unroll
            for (int mi = 0; mi < 4; mi++)
#pragma unroll
                for (int ni = 0; ni < 4; ni++) {
                    mma16816(c[mi][ni], aH[mi][0], aH[mi][1], aH[mi][2], aH[mi][3],
                             bH[ni][0], bH[ni][1]);
                    mma16816(c[mi][ni], aH[mi][0], aH[mi][1], aH[mi][2], aH[mi][3],
                             bL[ni][0], bL[ni][1]);
                    mma16816(c[mi][ni], aL[mi][0], aL[mi][1], aL[mi][2], aL[mi][3],
                             bH[ni][0], bH[ni][1]);
                }
        }
        __syncthreads();
    }

#pragma unroll
    for (int mi = 0; mi < 4; mi++) {
        int r0 = bm + warpM * 64 + mi * 16 + g;
#pragma unroll
        for (int ni = 0; ni < 4; ni++) {
            int cc = bn + warpN * 32 + ni * 8 + 2 * tg;
            *(float2*)(C + (size_t)r0 * N + cc) = make_float2(c[mi][ni][0], c[mi][ni][1]);
            *(float2*)(C + (size_t)(r0 + 8) * N + cc) = make_float2(c[mi][ni][2], c[mi][ni][3]);
        }
    }
}

// ---------------------------------------------------------------------------
// Flash attention, split-fp16 mma.sync: main terms f32-acc, correction terms
// f16-acc (2 correction MMAs share one f16x2 accumulator pair per tile).
// 128 threads (4 warps), 64 q rows, 64-key tiles, 106KB -> 2 CTA/SM.
// ---------------------------------------------------------------------------
#define FQH 0
#define FQL 8704
#define FKH 17408
#define FKL 26112
#define FVH 34816
#define FVL 44032
#define FSMEM_B 106496

__global__ __launch_bounds__(128)
void flash_mma(const __half* __restrict__ Qh, const __half* __restrict__ Ql,
               const __half* __restrict__ Kh, const __half* __restrict__ Kl,
               const __half* __restrict__ Vth, const __half* __restrict__ Vtl,
               __half* __restrict__ Oh, __half* __restrict__ Ol) {
    extern __shared__ __half fsm[];
    const uint32_t sb = smem_u32(fsm);

    const int b = blockIdx.z, h = blockIdx.y, qt = blockIdx.x;
    const int qs = qt * 64, hk = h >> 2;
    const int tid = threadIdx.x;
    const int warp = tid >> 5, lane = tid & 31;
    const int g = lane >> 2, tg = lane & 3;

    const int a_r = lane & 15;
    const int a_k = (lane >> 4) * 8;
    const int b_r = lane & 7;
    const int b_n8 = ((lane >> 4) & 1) * 8;
    const int b_k8 = ((lane >> 3) & 1) * 8;

    // ---- load Q tile (once) ----
#pragma unroll
    for (int i = 0; i < 8; i++) {
        int j = tid + (i << 7);
        int row = j >> 4, kc = j & 15;
        uint32_t d = sb + (uint32_t)((row * 136 + kc * 8) * 2);
        size_t src = ((size_t)(b * S_ + qs + row) * NH_ + h) * HD_ + kc * 8;
        cp16(d + FQH * 2, Qh + src);
        cp16(d + FQL * 2, Ql + src);
    }
    asm volatile("cp.async.commit_group;\n");

    float o[16][4];
    uint32_t ocorr[16][2];
#pragma unroll
    for (int nt = 0; nt < 16; nt++) {
#pragma unroll
        for (int j = 0; j < 4; j++) o[nt][j] = 0.f;
        ocorr[nt][0] = 0u; ocorr[nt][1] = 0u;
    }
    float m0 = -1e30f, m1 = -1e30f, l0 = 0.f, l1 = 0.f;

    const int qr0 = qs + warp * 16 + g;
    const int qr1 = qr0 + 8;
    const int ntiles = qt + 1;

    for (int j = 0; j < ntiles; j++) {
        const int ks = j * 64;
        // ---- load K and Vt tiles ----
#pragma unroll
        for (int i = 0; i < 8; i++) {
            int jj = tid + (i << 7);
            int krow = jj >> 4, kkc = jj & 15;
            uint32_t dk = sb + (uint32_t)((krow * 136 + kkc * 8) * 2);
            size_t ksrc = ((size_t)(b * S_ + ks + krow) * NKV_ + hk) * HD_ + kkc * 8;
            cp16(dk + FKH * 2, Kh + ksrc);
            cp16(dk + FKL * 2, Kl + ksrc);
            int vd = jj >> 3, vc = jj & 7;
            uint32_t dv = sb + (uint32_t)((vd * 72 + vc * 8) * 2);
            size_t vsrc = ((size_t)(b * NKV_ + hk) * HD_ + vd) * S_ + ks + vc * 8;
            cp16(dv + FVH * 2, Vth + vsrc);
            cp16(dv + FVL * 2, Vtl + vsrc);
        }
        asm volatile("cp.async.commit_group;\n");
        asm volatile("cp.async.wait_group 0;\n");
        __syncthreads();

        // ---- S = Q K^T : main f32-acc, corrections f16-acc ----
        float S4[8][4];
        uint32_t scorr[8][2];
#pragma unroll
        for (int nt = 0; nt < 8; nt++) {
#pragma unroll
            for (int cc = 0; cc < 4; cc++) S4[nt][cc] = 0.f;
            scorr[nt][0] = 0u; scorr[nt][1] = 0u;
        }

#pragma unroll
        for (int dk = 0; dk < 8; dk++) {
            uint32_t aH[4], aL[4];
            ldsm4(aH[0], aH[1], aH[2], aH[3],
                  fsm + FQH + (size_t)(warp * 16 + a_r) * 136 + dk * 16 + a_k);
            ldsm4(aL[0], aL[1], aL[2], aL[3],
                  fsm + FQL + (size_t)(warp * 16 + a_r) * 136 + dk * 16 + a_k);
#pragma unroll
            for (int np = 0; np < 4; np++) {
                int nb = np * 16;
                uint32_t h0, h1, h2, h3, l0r, l1r, l2r, l3r;
                ldsm4(h0, h1, h2, h3,
                      fsm + FKH + (size_t)(nb + b_r + b_n8) * 136 + dk * 16 + b_k8);
                ldsm4(l0r, l1r, l2r, l3r,
                      fsm + FKL + (size_t)(nb + b_r + b_n8) * 136 + dk * 16 + b_k8);
                mma16816(S4[2 * np],     aH[0], aH[1], aH[2], aH[3], h0, h1);
                mma16816(S4[2 * np + 1], aH[0], aH[1], aH[2], aH[3], h2, h3);
                mma16816h(scorr[2 * np][0],     scorr[2 * np][1],
                          aH[0], aH[1], aH[2], aH[3], l0r, l1r);
                mma16816h(scorr[2 * np][0],     scorr[2 * np][1],
                          aL[0], aL[1], aL[2], aL[3], h0, h1);
                mma16816h(scorr[2 * np + 1][0], scorr[2 * np + 1][1],
                          aH[0], aH[1], aH[2], aH[3], l2r, l3r);
                mma16816h(scorr[2 * np + 1][0], scorr[2 * np + 1][1],
                          aL[0], aL[1], aL[2], aL[3], h2, h3);
            }
        }
        // fold corrections into S
#pragma unroll
        for (int nt = 0; nt < 8; nt++) {
            S4[nt][0] += h2lo(scorr[nt][0]);
            S4[nt][1] += h2hi(scorr[nt][0]);
            S4[nt][2] += h2lo(scorr[nt][1]);
            S4[nt][3] += h2hi(scorr[nt][1]);
        }

        // ---- scale + mask + online softmax ----
        float mx0 = -1e30f, mx1 = -1e30f;
        const bool diag = (j == ntiles - 1);
#pragma unroll
        for (int nt = 0; nt < 8; nt++) {
#pragma unroll
            for (int cc = 0; cc < 4; cc++) {
                float v = S4[nt][cc] * SCALING_;
                if (diag) {
                    int kcol = ks + nt * 8 + 2 * tg + (cc & 1);
                    int qr = (cc < 2) ? qr0 : qr1;
                    if (kcol > qr) v = -1e30f;
                }
                S4[nt][cc] = v;
                if (cc < 2) mx0 = fmaxf(mx0, v); else mx1 = fmaxf(mx1, v);
            }
        }
        mx0 = fmaxf(mx0, __shfl_xor_sync(0xffffffffu, mx0, 1));
        mx0 = fmaxf(mx0, __shfl_xor_sync(0xffffffffu, mx0, 2));
        mx1 = fmaxf(mx1, __shfl_xor_sync(0xffffffffu, mx1, 1));
        mx1 = fmaxf(mx1, __shfl_xor_sync(0xffffffffu, mx1, 2));
        const float mt0 = fmaxf(m0, mx0), mt1 = fmaxf(m1, mx1);
        const float sc0 = __expf(m0 - mt0), sc1 = __expf(m1 - mt1);
        m0 = mt0; m1 = mt1;

        float rs0 = 0.f, rs1 = 0.f;
#pragma unroll
        for (int nt = 0; nt < 8; nt++) {
            float p0 = __expf(S4[nt][0] - mt0);
            float p1 = __expf(S4[nt][1] - mt0);
            float p2 = __expf(S4[nt][2] - mt1);
            float p3 = __expf(S4[nt][3] - mt1);
            S4[nt][0] = p0; S4[nt][1] = p1; S4[nt][2] = p2; S4[nt][3] = p3;
            rs0 += p0 + p1; rs1 += p2 + p3;
        }
        rs0 += __shfl_xor_sync(0xffffffffu, rs0, 1);
        rs0 += __shfl_xor_sync(0xffffffffu, rs0, 2);
        rs1 += __shfl_xor_sync(0xffffffffu, rs1, 1);
        rs1 += __shfl_xor_sync(0xffffffffu, rs1, 2);
        l0 = l0 * sc0 + rs0;
        l1 = l1 * sc1 + rs1;
#pragma unroll
        for (int nt = 0; nt < 16; nt++) {
            o[nt][0] *= sc0; o[nt][1] *= sc0;
            o[nt][2] *= sc1; o[nt][3] *= sc1;
            ocorr[nt][0] = h2scale(ocorr[nt][0], sc0);
            ocorr[nt][1] = h2scale(ocorr[nt][1], sc1);
        }

        // ---- O += P V : main f32-acc, corrections f16-acc ----
#pragma unroll
        for (int kt = 0; kt < 4; kt++) {
            uint32_t aPh[4], aPl[4];
#pragma unroll
            for (int half = 0; half < 2; half++) {
                const float* sv = S4[2 * kt + half];
                uint32_t p01 = pk_h2(sv[0], sv[1]);
                uint32_t p23 = pk_h2(sv[2], sv[3]);
                float r0f = sv[0] - h2lo(p01);
                float r1f = sv[1] - h2hi(p01);
                float r2f = sv[2] - h2lo(p23);
                float r3f = sv[3] - h2hi(p23);
                aPh[0 + 2 * half] = p01;
                aPh[1 + 2 * half] = p23;
                aPl[0 + 2 * half] = pk_h2(r0f, r1f);
                aPl[1 + 2 * half] = pk_h2(r2f, r3f);
            }
#pragma unroll
            for (int np = 0; np < 8; np++) {
                int nb = np * 16;
                uint32_t h0, h1, h2, h3, l0r, l1r, l2r, l3r;
                ldsm4(h0, h1, h2, h3,
                      fsm + FVH + (size_t)(nb + b_r + b_n8) * 72 + kt * 16 + b_k8);
                ldsm4(l0r, l1r, l2r, l3r,
                      fsm + FVL + (size_t)(nb + b_r + b_n8) * 72 + kt * 16 + b_k8);
                mma16816(o[2 * np],     aPh[0], aPh[1], aPh[2], aPh[3], h0, h1);
                mma16816(o[2 * np + 1], aPh[0], aPh[1], aPh[2], aPh[3], h2, h3);
                mma16816h(ocorr[2 * np][0],     ocorr[2 * np][1],
                          aPh[0], aPh[1], aPh[2], aPh[3], l0r, l1r);
                mma16816h(ocorr[2 * np][0],     ocorr[2 * np][1],
                          aPl[0], aPl[1], aPl[2], aPl[3], h0, h1);
                mma16816h(ocorr[2 * np + 1][0], ocorr[2 * np + 1][1],
                          aPh[0], aPh[1], aPh[2], aPh[3], l2r, l3r);
                mma16816h(ocorr[2 * np + 1][0], ocorr[2 * np + 1][1],
                          aPl[0], aPl[1], aPl[2], aPl[3], h2, h3);
            }
        }
        __syncthreads();
    }

    // ---- writeback: fold corrections, split fp32 -> fp16 h/l planes ----
    const float inv0 = 1.f / l0, inv1 = 1.f / l1;
    const size_t r0base = ((size_t)(b * S_ + qr0) * NH_ + h) * HD_;
    const size_t r1base = ((size_t)(b * S_ + qr1) * NH_ + h) * HD_;
#pragma unroll
    for (int nt = 0; nt < 16; nt++) {
        int cc = nt * 8 + 2 * tg;
        float v00 = (o[nt][0] + h2lo(ocorr[nt][0])) * inv0;
        float v01 = (o[nt][1] + h2hi(ocorr[nt][0])) * inv0;
        float v10 = (o[nt][2] + h2lo(ocorr[nt][1])) * inv1;
        float v11 = (o[nt][3] + h2hi(ocorr[nt][1])) * inv1;
        uint32_t h0p = pk_h2(v00, v01);
        uint32_t h1p = pk_h2(v10, v11);
        float e00 = v00 - h2lo(h0p);
        float e01 = v01 - h2hi(h0p);
        float e10 = v10 - h2lo(h1p);
        float e11 = v11 - h2hi(h1p);
        *(uint32_t*)(Oh + r0base + cc) = h0p;
        *(uint32_t*)(Ol + r0base + cc) = pk_h2(e00, e01);
        *(uint32_t*)(Oh + r1base + cc) = h1p;
        *(uint32_t*)(Ol + r1base + cc) = pk_h2(e10, e11);
    }
}

// ---------------------------------------------------------------------------
// Launch
// ---------------------------------------------------------------------------
extern "C" void kernel_launch(void* const* d_in, const int* in_sizes, int n_in,
                              void* d_out, int out_size) {
    const float* hs   = (const float*)d_in[0];
    const float* cosp = (const float*)d_in[1];
    const float* sinp = (const float*)d_in[2];
    const float* Wq   = (const float*)d_in[4];
    const float* Wk   = (const float*)d_in[5];
    const float* Wv   = (const float*)d_in[6];
    const float* Wo   = (const float*)d_in[7];
    float* out = (float*)d_out;

    float* qkv;
    cudaGetSymbolAddress((void**)&qkv, g_qkv);

    __half *hs_h, *hs_l, *wqkv_h, *wqkv_l, *wo_h, *wo_l,
           *ob_h, *ob_l, *qh, *ql, *kh, *kl, *vth, *vtl;
    cudaGetSymbolAddress((void**)&hs_h, g_hs_h); cudaGetSymbolAddress((void**)&hs_l, g_hs_l);
    cudaGetSymbolAddress((void**)&wqkv_h, g_wqkv_h); cudaGetSymbolAddress((void**)&wqkv_l, g_wqkv_l);
    cudaGetSymbolAddress((void**)&wo_h, g_wo_h); cudaGetSymbolAddress((void**)&wo_l, g_wo_l);
    cudaGetSymbolAddress((void**)&ob_h, g_ob_h); cudaGetSymbolAddress((void**)&ob_l, g_ob_l);
    cudaGetSymbolAddress((void**)&qh, g_qh); cudaGetSymbolAddress((void**)&ql, g_ql);
    cudaGetSymbolAddress((void**)&kh, g_kh); cudaGetSymbolAddress((void**)&kl, g_kl);
    cudaGetSymbolAddress((void**)&vth, g_vth); cudaGetSymbolAddress((void**)&vtl, g_vtl);

    cudaFuncSetAttribute(gemm_mma, cudaFuncAttributeMaxDynamicSharedMemorySize, GSMEM_B);
    cudaFuncSetAttribute(flash_mma, cudaFuncAttributeMaxDynamicSharedMemorySize, FSMEM_B);

    const int M = B_ * S_;   // 4096

    // #1: fused QKV weight split; #2: hidden-state split
    split_wqkv<<<(WQKV_ELEMS / 4 + 255) / 256, 256>>>(Wq, Wk, Wv, wqkv_h, wqkv_l);
    split_kernel<<<(HS_ELEMS / 4 + 255) / 256, 256>>>(hs, hs_h, hs_l, HS_ELEMS);

    // #3: fused QKV projection (target for the ncu capture window)
    gemm_mma<<<dim3(NQKV / BN, M / BM), 256, GSMEM_B>>>(
        hs_h, hs_l, wqkv_h, wqkv_l, qkv, M, NQKV, HID_);

    // #4: O-projection weight split (independent; overlaps conceptually)
    split_kernel<<<(WO_ELEMS / 4 + 255) / 256, 256>>>(Wo, wo_h, wo_l, WO_ELEMS);

    // #5-7: fused RoPE + split; V split+transpose
    {
        int totq = B_ * S_ * NH_ * 64;
        rope_split<<<(totq + 255) / 256, 256>>>(qkv, 0, cosp, sinp, qh, ql, NH_, totq);
        int totk = B_ * S_ * NKV_ * 64;
        rope_split<<<(totk + 255) / 256, 256>>>(qkv, KOFF, cosp, sinp, kh, kl, NKV_, totk);
        splitT_v<<<(KV_ELEMS + 255) / 256, 256>>>(qkv, vth, vtl);
    }

    // #8: flash attention (split-fp16 mma, f16-acc corrections)
    flash_mma<<<dim3(S_ / 64, NH_, B_), 128, FSMEM_B>>>(qh, ql, kh, kl, vth, vtl, ob_h, ob_l);

    // #9: O projection
    gemm_mma<<<dim3(HID_ / BN, M / BM), 256, GSMEM_B>>>(ob_h, ob_l, wo_h, wo_l, out, M, HID_, NH_ * HD_);
}

// round 10
// speedup vs baseline: 1.6376x; 1.4420x over previous
#include <cuda_runtime.h>
#include <cuda_fp16.h>
#include <cstdint>

// Problem constants
#define B_   2
#define S_   2048
#define HID_ 4096
#define NH_  32
#define NKV_ 8
#define HD_  128
#define NREP_ 4
#define SCALING_ 0.08838834764831843f   // 128^-0.5

#define NQKV 6144      // 4096 (Q) + 1024 (K) + 1024 (V)
#define KOFF 4096
#define VOFF 5120

// fp32 scratch: fused QKV GEMM output [B*S][NQKV]
__device__ float g_qkv[(size_t)B_ * S_ * NQKV];

// fp16 planes
#define HS_ELEMS   ((size_t)B_ * S_ * HID_)
#define WQKV_ELEMS ((size_t)NQKV * HID_)
#define WO_ELEMS   ((size_t)HID_ * NH_ * HD_)
#define KV_ELEMS   ((size_t)B_ * S_ * NKV_ * HD_)
__device__ __half g_hs_h[HS_ELEMS], g_hs_l[HS_ELEMS];
__device__ __half g_wqkv_h[WQKV_ELEMS];             // weights: hi only
__device__ __half g_wo_h[WO_ELEMS];                 // weights: hi only
__device__ __half g_ob_h[HS_ELEMS], g_ob_l[HS_ELEMS];
// attention planes (post-rope): Q hi+lo; K,V hi only
__device__ __half g_qh[HS_ELEMS], g_ql[HS_ELEMS];
__device__ __half g_kh[KV_ELEMS];
__device__ __half g_vth[KV_ELEMS];                  // [b][hk][d][s]

// ---------------------------------------------------------------------------
// helpers
// ---------------------------------------------------------------------------
static __device__ __forceinline__ uint32_t smem_u32(const void* p) {
    uint32_t a;
    asm("{ .reg .u64 t; cvta.to.shared.u64 t, %1; cvt.u32.u64 %0, t; }"
        : "=r"(a) : "l"(p));
    return a;
}
static __device__ __forceinline__ void cp16(uint32_t dst, const void* src) {
    asm volatile("cp.async.cg.shared.global [%0], [%1], 16;\n" :: "r"(dst), "l"(src));
}
__device__ __forceinline__ void mma16816(float c[4], uint32_t a0, uint32_t a1,
                                         uint32_t a2, uint32_t a3,
                                         uint32_t b0, uint32_t b1) {
    asm volatile(
        "mma.sync.aligned.m16n8k16.row.col.f32.f16.f16.f32 "
        "{%0,%1,%2,%3}, {%4,%5,%6,%7}, {%8,%9}, {%0,%1,%2,%3};\n"
        : "+f"(c[0]), "+f"(c[1]), "+f"(c[2]), "+f"(c[3])
        : "r"(a0), "r"(a1), "r"(a2), "r"(a3), "r"(b0), "r"(b1));
}
__device__ __forceinline__ void mma16816h(uint32_t& c0, uint32_t& c1,
                                          uint32_t a0, uint32_t a1,
                                          uint32_t a2, uint32_t a3,
                                          uint32_t b0, uint32_t b1) {
    asm volatile(
        "mma.sync.aligned.m16n8k16.row.col.f16.f16.f16.f16 "
        "{%0,%1}, {%2,%3,%4,%5}, {%6,%7}, {%0,%1};\n"
        : "+r"(c0), "+r"(c1)
        : "r"(a0), "r"(a1), "r"(a2), "r"(a3), "r"(b0), "r"(b1));
}
__device__ __forceinline__ void ldsm4(uint32_t& r0, uint32_t& r1, uint32_t& r2,
                                      uint32_t& r3, const void* p) {
    uint32_t a = (uint32_t)__cvta_generic_to_shared(p);
    asm volatile("ldmatrix.sync.aligned.m8n8.x4.shared.b16 {%0,%1,%2,%3}, [%4];\n"
                 : "=r"(r0), "=r"(r1), "=r"(r2), "=r"(r3) : "r"(a));
}
static __device__ __forceinline__ uint32_t pk_h2(float lo, float hi) {
    __half2 t = __floats2half2_rn(lo, hi);
    return *reinterpret_cast<uint32_t*>(&t);
}
static __device__ __forceinline__ float h2lo(uint32_t u) {
    __half2 h = *reinterpret_cast<__half2*>(&u);
    return __half2float(__low2half(h));
}
static __device__ __forceinline__ float h2hi(uint32_t u) {
    __half2 h = *reinterpret_cast<__half2*>(&u);
    return __half2float(__high2half(h));
}
static __device__ __forceinline__ uint32_t h2scale(uint32_t u, float s) {
    __half2 h = *reinterpret_cast<__half2*>(&u);
    __half2 r = __hmul2(h, __float2half2_rn(s));
    return *reinterpret_cast<uint32_t*>(&r);
}

// ---------------------------------------------------------------------------
// conversion kernels
// ---------------------------------------------------------------------------
__global__ void split_kernel(const float* __restrict__ x,
                             __half* __restrict__ hi,
                             __half* __restrict__ lo, size_t n) {
    size_t i = ((size_t)blockIdx.x * blockDim.x + threadIdx.x) * 4;
    if (i >= n) return;
    float4 v = *(const float4*)(x + i);
    float f[4] = {v.x, v.y, v.z, v.w};
#pragma unroll
    for (int j = 0; j < 4; j++) {
        __half h = __float2half_rn(f[j]);
        hi[i + j] = h;
        lo[i + j] = __float2half_rn(f[j] - __half2float(h));
    }
}

// hi-only convert
__global__ void cvt_hi(const float* __restrict__ x, __half* __restrict__ hi, size_t n) {
    size_t i = ((size_t)blockIdx.x * blockDim.x + threadIdx.x) * 4;
    if (i >= n) return;
    float4 v = *(const float4*)(x + i);
    hi[i + 0] = __float2half_rn(v.x);
    hi[i + 1] = __float2half_rn(v.y);
    hi[i + 2] = __float2half_rn(v.z);
    hi[i + 3] = __float2half_rn(v.w);
}

// fused Wq/Wk/Wv hi-only convert into concatenated buffer
__global__ void cvt_wqkv(const float* __restrict__ Wq,
                         const float* __restrict__ Wk,
                         const float* __restrict__ Wv,
                         __half* __restrict__ hi) {
    size_t i = ((size_t)blockIdx.x * blockDim.x + threadIdx.x) * 4;
    if (i >= WQKV_ELEMS) return;
    size_t row = i / HID_;
    const float* src;
    size_t off;
    if (row < (size_t)KOFF)      { src = Wq; off = i; }
    else if (row < (size_t)VOFF) { src = Wk; off = i - (size_t)KOFF * HID_; }
    else                         { src = Wv; off = i - (size_t)VOFF * HID_; }
    float4 v = *(const float4*)(src + off);
    hi[i + 0] = __float2half_rn(v.x);
    hi[i + 1] = __float2half_rn(v.y);
    hi[i + 2] = __float2half_rn(v.z);
    hi[i + 3] = __float2half_rn(v.w);
}

// fused RoPE + split (Q: hi+lo) or hi-only (K) via write_lo flag
__global__ void rope_split(const float* __restrict__ x, int hoff,
                           const float* __restrict__ cosp,
                           const float* __restrict__ sinp,
                           __half* __restrict__ xh,
                           __half* __restrict__ xl, int write_lo,
                           int nheads, int total) {
    int idx = blockIdx.x * blockDim.x + threadIdx.x;
    if (idx >= total) return;
    int d  = idx & 63;
    int h  = (idx >> 6) % nheads;
    int bs = idx / (64 * nheads);
    const float* row = x + (size_t)bs * NQKV + hoff + (size_t)h * HD_;
    const float* c = cosp + (size_t)bs * HD_;
    const float* s = sinp + (size_t)bs * HD_;
    float x1 = row[d], x2 = row[d + 64];
    float y1 = x1 * c[d]      - x2 * s[d];
    float y2 = x2 * c[d + 64] + x1 * s[d + 64];
    size_t base = (size_t)bs * nheads * HD_ + (size_t)h * HD_;
    __half h1 = __float2half_rn(y1);
    __half h2 = __float2half_rn(y2);
    xh[base + d]      = h1;
    xh[base + d + 64] = h2;
    if (write_lo) {
        xl[base + d]      = __float2half_rn(y1 - __half2float(h1));
        xl[base + d + 64] = __float2half_rn(y2 - __half2float(h2));
    }
}

// transpose + hi convert V: in [B*S][NQKV] @ VOFF -> out [b][hk][d][s]
__global__ void cvtT_v(const float* __restrict__ v, __half* __restrict__ vh) {
    size_t idx = (size_t)blockIdx.x * blockDim.x + threadIdx.x;
    if (idx >= KV_ELEMS) return;
    int s  = idx & (S_ - 1);
    size_t r = idx >> 11;
    int d  = r & (HD_ - 1);  r >>= 7;
    int hk = r & (NKV_ - 1);
    int b  = (int)(r >> 3);
    float x = v[(size_t)(b * S_ + s) * NQKV + VOFF + hk * HD_ + d];
    vh[idx] = __float2half_rn(x);
}

// ---------------------------------------------------------------------------
// 2-plane fp16 NT GEMM: C = (Ah+Al) * Bh^T. 2 MMAs per k16 (both f32-acc).
// BK=32, 2-stage cp.async, 256 threads (2x4 warps), warp tile 64x32.
// smem 60KB -> 2 CTA/SM.
// ---------------------------------------------------------------------------
#define BM 128
#define BN 128
#define GK 32
#define GPAD 40
#define GPLANE 5120
#define GSTAGE 15360                  // 3 planes (Ah, Al, Bh)
#define GSMEM_B (2 * GSTAGE * 2)      // 61440 bytes
#define SWG 16

__global__ __launch_bounds__(256)
void gemm_mma(const __half* __restrict__ Ah, const __half* __restrict__ Al,
              const __half* __restrict__ Bh,
              float* __restrict__ C, int M, int N, int K) {
    extern __shared__ __half gsm[];
    const uint32_t sb = smem_u32(gsm);

    const int tid = threadIdx.x;
    const int warp = tid >> 5, lane = tid & 31;
    const int g = lane >> 2, tg = lane & 3;
    const int warpM = warp >> 2, warpN = warp & 3;

    int bx, by;
    {
        int bid = blockIdx.y * gridDim.x + blockIdx.x;
        int per = SWG * gridDim.x;
        int grp = bid / per;
        int rem = bid - grp * per;
        by = grp * SWG + (rem & (SWG - 1));
        bx = rem >> 4;
    }
    const int bm = by * BM, bn = bx * BN;

    const int a_r = lane & 15;
    const int a_k = (lane >> 4) * 8;
    const int b_r = lane & 7;
    const int b_n8 = ((lane >> 4) & 1) * 8;
    const int b_k8 = ((lane >> 3) & 1) * 8;

    float c[4][4][4];
#pragma unroll
    for (int mi = 0; mi < 4; mi++)
#pragma unroll
        for (int ni = 0; ni < 4; ni++)
#pragma unroll
            for (int j = 0; j < 4; j++) c[mi][ni][j] = 0.f;

    const int niter = K / GK;

    auto load_stage = [&](int s, int k0) {
        const uint32_t base = sb + (uint32_t)(s * GSTAGE) * 2;
#pragma unroll
        for (int i = 0; i < 2; i++) {
            int j = tid + (i << 8);
            int row = j >> 2, col = (j & 3) * 8;
            size_t ao = (size_t)(bm + row) * K + k0 + col;
            size_t bo = (size_t)(bn + row) * K + k0 + col;
            uint32_t off = (uint32_t)(row * GPAD + col) * 2;
            cp16(base + off, Ah + ao);
            cp16(base + GPLANE * 2 + off, Al + ao);
            cp16(base + 2 * GPLANE * 2 + off, Bh + bo);
        }
        asm volatile("cp.async.commit_group;\n");
    };

    load_stage(0, 0);

    for (int i = 0; i < niter; i++) {
        if (i + 1 < niter) {
            load_stage((i + 1) & 1, (i + 1) * GK);
            asm volatile("cp.async.wait_group 1;\n");
        } else {
            asm volatile("cp.async.wait_group 0;\n");
        }
        __syncthreads();

        const int s = i & 1;
        const __half* Asm = gsm + (size_t)s * GSTAGE;
        const __half* Bsm = Asm + 2 * GPLANE;
#pragma unroll
        for (int kk = 0; kk < 2; kk++) {
            const int kb = kk * 16;
            uint32_t aH[4][4], aL[4][4], bH[4][2];
#pragma unroll
            for (int mi = 0; mi < 4; mi++) {
                int rb = warpM * 64 + mi * 16;
                ldsm4(aH[mi][0], aH[mi][1], aH[mi][2], aH[mi][3],
                      Asm + (size_t)(rb + a_r) * GPAD + kb + a_k);
                ldsm4(aL[mi][0], aL[mi][1], aL[mi][2], aL[mi][3],
                      Asm + GPLANE + (size_t)(rb + a_r) * GPAD + kb + a_k);
            }
#pragma unroll
            for (int np = 0; np < 2; np++) {
                int nb = warpN * 32 + np * 16;
                uint32_t r0, r1, r2, r3;
                ldsm4(r0, r1, r2, r3,
                      Bsm + (size_t)(nb + b_r + b_n8) * GPAD + kb + b_k8);
                bH[np * 2][0] = r0; bH[np * 2][1] = r1;
                bH[np * 2 + 1][0] = r2; bH[np * 2 + 1][1] = r3;
            }
#pragma unroll
            for (int mi = 0; mi < 4; mi++)
#pragma unroll
                for (int ni = 0; ni < 4; ni++) {
                    mma16816(c[mi][ni], aH[mi][0], aH[mi][1], aH[mi][2], aH[mi][3],
                             bH[ni][0], bH[ni][1]);
                    mma16816(c[mi][ni], aL[mi][0], aL[mi][1], aL[mi][2], aL[mi][3],
                             bH[ni][0], bH[ni][1]);
                }
        }
        __syncthreads();
    }

#pragma unroll
    for (int mi = 0; mi < 4; mi++) {
        int r0 = bm + warpM * 64 + mi * 16 + g;
#pragma unroll
        for (int ni = 0; ni < 4; ni++) {
            int cc = bn + warpN * 32 + ni * 8 + 2 * tg;
            *(float2*)(C + (size_t)r0 * N + cc) = make_float2(c[mi][ni][0], c[mi][ni][1]);
            *(float2*)(C + (size_t)(r0 + 8) * N + cc) = make_float2(c[mi][ni][2], c[mi][ni][3]);
        }
    }
}

// ---------------------------------------------------------------------------
// Flash attention: S = (Qh+Ql)Kh^T, O = (Ph+Pl)Vh. Main f32-acc, lo-plane
// corrections f16-acc. 128 threads, 64 q rows, 64-key tiles. smem 69KB.
// ---------------------------------------------------------------------------
#define FQH 0
#define FQL 8704
#define FKH 17408
#define FVH 26112
#define FSMEM_B 70656

__global__ __launch_bounds__(128)
void flash_mma(const __half* __restrict__ Qh, const __half* __restrict__ Ql,
               const __half* __restrict__ Kh, const __half* __restrict__ Vth,
               __half* __restrict__ Oh, __half* __restrict__ Ol) {
    extern __shared__ __half fsm[];
    const uint32_t sb = smem_u32(fsm);

    const int b = blockIdx.z, h = blockIdx.y, qt = blockIdx.x;
    const int qs = qt * 64, hk = h >> 2;
    const int tid = threadIdx.x;
    const int warp = tid >> 5, lane = tid & 31;
    const int g = lane >> 2, tg = lane & 3;

    const int a_r = lane & 15;
    const int a_k = (lane >> 4) * 8;
    const int b_r = lane & 7;
    const int b_n8 = ((lane >> 4) & 1) * 8;
    const int b_k8 = ((lane >> 3) & 1) * 8;

    // ---- load Q tile (hi+lo, once) ----
#pragma unroll
    for (int i = 0; i < 8; i++) {
        int j = tid + (i << 7);
        int row = j >> 4, kc = j & 15;
        uint32_t d = sb + (uint32_t)((row * 136 + kc * 8) * 2);
        size_t src = ((size_t)(b * S_ + qs + row) * NH_ + h) * HD_ + kc * 8;
        cp16(d + FQH * 2, Qh + src);
        cp16(d + FQL * 2, Ql + src);
    }
    asm volatile("cp.async.commit_group;\n");

    float o[16][4];
    uint32_t ocorr[16][2];
#pragma unroll
    for (int nt = 0; nt < 16; nt++) {
#pragma unroll
        for (int j = 0; j < 4; j++) o[nt][j] = 0.f;
        ocorr[nt][0] = 0u; ocorr[nt][1] = 0u;
    }
    float m0 = -1e30f, m1 = -1e30f, l0 = 0.f, l1 = 0.f;

    const int qr0 = qs + warp * 16 + g;
    const int qr1 = qr0 + 8;
    const int ntiles = qt + 1;

    for (int j = 0; j < ntiles; j++) {
        const int ks = j * 64;
        // ---- load K (hi) and Vt (hi) tiles ----
#pragma unroll
        for (int i = 0; i < 8; i++) {
            int jj = tid + (i << 7);
            int krow = jj >> 4, kkc = jj & 15;
            uint32_t dk = sb + (uint32_t)((krow * 136 + kkc * 8) * 2);
            size_t ksrc = ((size_t)(b * S_ + ks + krow) * NKV_ + hk) * HD_ + kkc * 8;
            cp16(dk + FKH * 2, Kh + ksrc);
            int vd = jj >> 3, vc = jj & 7;
            uint32_t dv = sb + (uint32_t)((vd * 72 + vc * 8) * 2);
            size_t vsrc = ((size_t)(b * NKV_ + hk) * HD_ + vd) * S_ + ks + vc * 8;
            cp16(dv + FVH * 2, Vth + vsrc);
        }
        asm volatile("cp.async.commit_group;\n");
        asm volatile("cp.async.wait_group 0;\n");
        __syncthreads();

        // ---- S = Q K^T : main f32-acc, Ql correction f16-acc ----
        float S4[8][4];
        uint32_t scorr[8][2];
#pragma unroll
        for (int nt = 0; nt < 8; nt++) {
#pragma unroll
            for (int cc = 0; cc < 4; cc++) S4[nt][cc] = 0.f;
            scorr[nt][0] = 0u; scorr[nt][1] = 0u;
        }

#pragma unroll
        for (int dk = 0; dk < 8; dk++) {
            uint32_t aH[4], aL[4];
            ldsm4(aH[0], aH[1], aH[2], aH[3],
                  fsm + FQH + (size_t)(warp * 16 + a_r) * 136 + dk * 16 + a_k);
            ldsm4(aL[0], aL[1], aL[2], aL[3],
                  fsm + FQL + (size_t)(warp * 16 + a_r) * 136 + dk * 16 + a_k);
#pragma unroll
            for (int np = 0; np < 4; np++) {
                int nb = np * 16;
                uint32_t h0, h1, h2, h3;
                ldsm4(h0, h1, h2, h3,
                      fsm + FKH + (size_t)(nb + b_r + b_n8) * 136 + dk * 16 + b_k8);
                mma16816(S4[2 * np],     aH[0], aH[1], aH[2], aH[3], h0, h1);
                mma16816(S4[2 * np + 1], aH[0], aH[1], aH[2], aH[3], h2, h3);
                mma16816h(scorr[2 * np][0],     scorr[2 * np][1],
                          aL[0], aL[1], aL[2], aL[3], h0, h1);
                mma16816h(scorr[2 * np + 1][0], scorr[2 * np + 1][1],
                          aL[0], aL[1], aL[2], aL[3], h2, h3);
            }
        }
#pragma unroll
        for (int nt = 0; nt < 8; nt++) {
            S4[nt][0] += h2lo(scorr[nt][0]);
            S4[nt][1] += h2hi(scorr[nt][0]);
            S4[nt][2] += h2lo(scorr[nt][1]);
            S4[nt][3] += h2hi(scorr[nt][1]);
        }

        // ---- scale + mask + online softmax ----
        float mx0 = -1e30f, mx1 = -1e30f;
        const bool diag = (j == ntiles - 1);
#pragma unroll
        for (int nt = 0; nt < 8; nt++) {
#pragma unroll
            for (int cc = 0; cc < 4; cc++) {
                float v = S4[nt][cc] * SCALING_;
                if (diag) {
                    int kcol = ks + nt * 8 + 2 * tg + (cc & 1);
                    int qr = (cc < 2) ? qr0 : qr1;
                    if (kcol > qr) v = -1e30f;
                }
                S4[nt][cc] = v;
                if (cc < 2) mx0 = fmaxf(mx0, v); else mx1 = fmaxf(mx1, v);
            }
        }
        mx0 = fmaxf(mx0, __shfl_xor_sync(0xffffffffu, mx0, 1));
        mx0 = fmaxf(mx0, __shfl_xor_sync(0xffffffffu, mx0, 2));
        mx1 = fmaxf(mx1, __shfl_xor_sync(0xffffffffu, mx1, 1));
        mx1 = fmaxf(mx1, __shfl_xor_sync(0xffffffffu, mx1, 2));
        const float mt0 = fmaxf(m0, mx0), mt1 = fmaxf(m1, mx1);
        const float sc0 = __expf(m0 - mt0), sc1 = __expf(m1 - mt1);
        m0 = mt0; m1 = mt1;

        float rs0 = 0.f, rs1 = 0.f;
#pragma unroll
        for (int nt = 0; nt < 8; nt++) {
            float p0 = __expf(S4[nt][0] - mt0);
            float p1 = __expf(S4[nt][1] - mt0);
            float p2 = __expf(S4[nt][2] - mt1);
            float p3 = __expf(S4[nt][3] - mt1);
            S4[nt][0] = p0; S4[nt][1] = p1; S4[nt][2] = p2; S4[nt][3] = p3;
            rs0 += p0 + p1; rs1 += p2 + p3;
        }
        rs0 += __shfl_xor_sync(0xffffffffu, rs0, 1);
        rs0 += __shfl_xor_sync(0xffffffffu, rs0, 2);
        rs1 += __shfl_xor_sync(0xffffffffu, rs1, 1);
        rs1 += __shfl_xor_sync(0xffffffffu, rs1, 2);
        l0 = l0 * sc0 + rs0;
        l1 = l1 * sc1 + rs1;
#pragma unroll
        for (int nt = 0; nt < 16; nt++) {
            o[nt][0] *= sc0; o[nt][1] *= sc0;
            o[nt][2] *= sc1; o[nt][3] *= sc1;
            ocorr[nt][0] = h2scale(ocorr[nt][0], sc0);
            ocorr[nt][1] = h2scale(ocorr[nt][1], sc1);
        }

        // ---- O += P V : main f32-acc, Pl correction f16-acc ----
#pragma unroll
        for (int kt = 0; kt < 4; kt++) {
            uint32_t aPh[4], aPl[4];
#pragma unroll
            for (int half = 0; half < 2; half++) {
                const float* sv = S4[2 * kt + half];
                uint32_t p01 = pk_h2(sv[0], sv[1]);
                uint32_t p23 = pk_h2(sv[2], sv[3]);
                float r0f = sv[0] - h2lo(p01);
                float r1f = sv[1] - h2hi(p01);
                float r2f = sv[2] - h2lo(p23);
                float r3f = sv[3] - h2hi(p23);
                aPh[0 + 2 * half] = p01;
                aPh[1 + 2 * half] = p23;
                aPl[0 + 2 * half] = pk_h2(r0f, r1f);
                aPl[1 + 2 * half] = pk_h2(r2f, r3f);
            }
#pragma unroll
            for (int np = 0; np < 8; np++) {
                int nb = np * 16;
                uint32_t h0, h1, h2, h3;
                ldsm4(h0, h1, h2, h3,
                      fsm + FVH + (size_t)(nb + b_r + b_n8) * 72 + kt * 16 + b_k8);
                mma16816(o[2 * np],     aPh[0], aPh[1], aPh[2], aPh[3], h0, h1);
                mma16816(o[2 * np + 1], aPh[0], aPh[1], aPh[2], aPh[3], h2, h3);
                mma16816h(ocorr[2 * np][0],     ocorr[2 * np][1],
                          aPl[0], aPl[1], aPl[2], aPl[3], h0, h1);
                mma16816h(ocorr[2 * np + 1][0], ocorr[2 * np + 1][1],
                          aPl[0], aPl[1], aPl[2], aPl[3], h2, h3);
            }
        }
        __syncthreads();
    }

    // ---- writeback: fold corrections, split fp32 -> fp16 h/l planes ----
    const float inv0 = 1.f / l0, inv1 = 1.f / l1;
    const size_t r0base = ((size_t)(b * S_ + qr0) * NH_ + h) * HD_;
    const size_t r1base = ((size_t)(b * S_ + qr1) * NH_ + h) * HD_;
#pragma unroll
    for (int nt = 0; nt < 16; nt++) {
        int cc = nt * 8 + 2 * tg;
        float v00 = (o[nt][0] + h2lo(ocorr[nt][0])) * inv0;
        float v01 = (o[nt][1] + h2hi(ocorr[nt][0])) * inv0;
        float v10 = (o[nt][2] + h2lo(ocorr[nt][1])) * inv1;
        float v11 = (o[nt][3] + h2hi(ocorr[nt][1])) * inv1;
        uint32_t h0p = pk_h2(v00, v01);
        uint32_t h1p = pk_h2(v10, v11);
        float e00 = v00 - h2lo(h0p);
        float e01 = v01 - h2hi(h0p);
        float e10 = v10 - h2lo(h1p);
        float e11 = v11 - h2hi(h1p);
        *(uint32_t*)(Oh + r0base + cc) = h0p;
        *(uint32_t*)(Ol + r0base + cc) = pk_h2(e00, e01);
        *(uint32_t*)(Oh + r1base + cc) = h1p;
        *(uint32_t*)(Ol + r1base + cc) = pk_h2(e10, e11);
    }
}

// ---------------------------------------------------------------------------
// Launch
// ---------------------------------------------------------------------------
extern "C" void kernel_launch(void* const* d_in, const int* in_sizes, int n_in,
                              void* d_out, int out_size) {
    const float* hs   = (const float*)d_in[0];
    const float* cosp = (const float*)d_in[1];
    const float* sinp = (const float*)d_in[2];
    const float* Wq   = (const float*)d_in[4];
    const float* Wk   = (const float*)d_in[5];
    const float* Wv   = (const float*)d_in[6];
    const float* Wo   = (const float*)d_in[7];
    float* out = (float*)d_out;

    float* qkv;
    cudaGetSymbolAddress((void**)&qkv, g_qkv);

    __half *hs_h, *hs_l, *wqkv_h, *wo_h, *ob_h, *ob_l, *qh, *ql, *kh, *vth;
    cudaGetSymbolAddress((void**)&hs_h, g_hs_h); cudaGetSymbolAddress((void**)&hs_l, g_hs_l);
    cudaGetSymbolAddress((void**)&wqkv_h, g_wqkv_h);
    cudaGetSymbolAddress((void**)&wo_h, g_wo_h);
    cudaGetSymbolAddress((void**)&ob_h, g_ob_h); cudaGetSymbolAddress((void**)&ob_l, g_ob_l);
    cudaGetSymbolAddress((void**)&qh, g_qh); cudaGetSymbolAddress((void**)&ql, g_ql);
    cudaGetSymbolAddress((void**)&kh, g_kh);
    cudaGetSymbolAddress((void**)&vth, g_vth);

    cudaFuncSetAttribute(gemm_mma, cudaFuncAttributeMaxDynamicSharedMemorySize, GSMEM_B);
    cudaFuncSetAttribute(flash_mma, cudaFuncAttributeMaxDynamicSharedMemorySize, FSMEM_B);

    const int M = B_ * S_;   // 4096

    // conversions
    cvt_wqkv<<<(WQKV_ELEMS / 4 + 255) / 256, 256>>>(Wq, Wk, Wv, wqkv_h);
    split_kernel<<<(HS_ELEMS / 4 + 255) / 256, 256>>>(hs, hs_h, hs_l, HS_ELEMS);

    // fused QKV projection
    gemm_mma<<<dim3(NQKV / BN, M / BM), 256, GSMEM_B>>>(
        hs_h, hs_l, wqkv_h, qkv, M, NQKV, HID_);

    cvt_hi<<<(WO_ELEMS / 4 + 255) / 256, 256>>>(Wo, wo_h, WO_ELEMS);

    // RoPE + split (Q hi+lo, K hi); V transpose+convert
    {
        int totq = B_ * S_ * NH_ * 64;
        rope_split<<<(totq + 255) / 256, 256>>>(qkv, 0, cosp, sinp, qh, ql, 1, NH_, totq);
        int totk = B_ * S_ * NKV_ * 64;
        rope_split<<<(totk + 255) / 256, 256>>>(qkv, KOFF, cosp, sinp, kh, nullptr, 0, NKV_, totk);
        cvtT_v<<<(KV_ELEMS + 255) / 256, 256>>>(qkv, vth);
    }

    // flash attention
    flash_mma<<<dim3(S_ / 64, NH_, B_), 128, FSMEM_B>>>(qh, ql, kh, vth, ob_h, ob_l);

    // O projection
    gemm_mma<<<dim3(HID_ / BN, M / BM), 256, GSMEM_B>>>(ob_h, ob_l, wo_h, out, M, HID_, NH_ * HD_);
}

// round 11
// speedup vs baseline: 1.6713x; 1.0206x over previous
#include <cuda_runtime.h>
#include <cuda_fp16.h>
#include <cstdint>

// Problem constants
#define B_   2
#define S_   2048
#define HID_ 4096
#define NH_  32
#define NKV_ 8
#define HD_  128
#define NREP_ 4
#define SCALING_ 0.08838834764831843f   // 128^-0.5

#define NQKV 6144      // 4096 (Q) + 1024 (K) + 1024 (V)
#define KOFF 4096
#define VOFF 5120

// fp32 scratch: fused QKV GEMM output [B*S][NQKV]
__device__ float g_qkv[(size_t)B_ * S_ * NQKV];

// fp16 planes
#define HS_ELEMS   ((size_t)B_ * S_ * HID_)
#define WQKV_ELEMS ((size_t)NQKV * HID_)
#define WO_ELEMS   ((size_t)HID_ * NH_ * HD_)
#define KV_ELEMS   ((size_t)B_ * S_ * NKV_ * HD_)
__device__ __half g_hs_h[HS_ELEMS], g_hs_l[HS_ELEMS];
__device__ __half g_wqkv_h[WQKV_ELEMS];             // weights: hi only
__device__ __half g_wo_h[WO_ELEMS];                 // weights: hi only
__device__ __half g_ob_h[HS_ELEMS], g_ob_l[HS_ELEMS];
// attention planes (post-rope): Q hi+lo; K,V hi only
__device__ __half g_qh[HS_ELEMS], g_ql[HS_ELEMS];
__device__ __half g_kh[KV_ELEMS];
__device__ __half g_vth[KV_ELEMS];                  // [b][hk][d][s]

// ---------------------------------------------------------------------------
// helpers
// ---------------------------------------------------------------------------
static __device__ __forceinline__ uint32_t smem_u32(const void* p) {
    uint32_t a;
    asm("{ .reg .u64 t; cvta.to.shared.u64 t, %1; cvt.u32.u64 %0, t; }"
        : "=r"(a) : "l"(p));
    return a;
}
static __device__ __forceinline__ void cp16(uint32_t dst, const void* src) {
    asm volatile("cp.async.cg.shared.global [%0], [%1], 16;\n" :: "r"(dst), "l"(src));
}
__device__ __forceinline__ void mma16816(float c[4], uint32_t a0, uint32_t a1,
                                         uint32_t a2, uint32_t a3,
                                         uint32_t b0, uint32_t b1) {
    asm volatile(
        "mma.sync.aligned.m16n8k16.row.col.f32.f16.f16.f32 "
        "{%0,%1,%2,%3}, {%4,%5,%6,%7}, {%8,%9}, {%0,%1,%2,%3};\n"
        : "+f"(c[0]), "+f"(c[1]), "+f"(c[2]), "+f"(c[3])
        : "r"(a0), "r"(a1), "r"(a2), "r"(a3), "r"(b0), "r"(b1));
}
__device__ __forceinline__ void mma16816h(uint32_t& c0, uint32_t& c1,
                                          uint32_t a0, uint32_t a1,
                                          uint32_t a2, uint32_t a3,
                                          uint32_t b0, uint32_t b1) {
    asm volatile(
        "mma.sync.aligned.m16n8k16.row.col.f16.f16.f16.f16 "
        "{%0,%1}, {%2,%3,%4,%5}, {%6,%7}, {%0,%1};\n"
        : "+r"(c0), "+r"(c1)
        : "r"(a0), "r"(a1), "r"(a2), "r"(a3), "r"(b0), "r"(b1));
}
__device__ __forceinline__ void ldsm4(uint32_t& r0, uint32_t& r1, uint32_t& r2,
                                      uint32_t& r3, const void* p) {
    uint32_t a = (uint32_t)__cvta_generic_to_shared(p);
    asm volatile("ldmatrix.sync.aligned.m8n8.x4.shared.b16 {%0,%1,%2,%3}, [%4];\n"
                 : "=r"(r0), "=r"(r1), "=r"(r2), "=r"(r3) : "r"(a));
}
static __device__ __forceinline__ uint32_t pk_h2(float lo, float hi) {
    __half2 t = __floats2half2_rn(lo, hi);
    return *reinterpret_cast<uint32_t*>(&t);
}
static __device__ __forceinline__ float h2lo(uint32_t u) {
    __half2 h = *reinterpret_cast<__half2*>(&u);
    return __half2float(__low2half(h));
}
static __device__ __forceinline__ float h2hi(uint32_t u) {
    __half2 h = *reinterpret_cast<__half2*>(&u);
    return __half2float(__high2half(h));
}
static __device__ __forceinline__ uint32_t h2scale(uint32_t u, float s) {
    __half2 h = *reinterpret_cast<__half2*>(&u);
    __half2 r = __hmul2(h, __float2half2_rn(s));
    return *reinterpret_cast<uint32_t*>(&r);
}

// ---------------------------------------------------------------------------
// conversion kernels
// ---------------------------------------------------------------------------
__global__ void split_kernel(const float* __restrict__ x,
                             __half* __restrict__ hi,
                             __half* __restrict__ lo, size_t n) {
    size_t i = ((size_t)blockIdx.x * blockDim.x + threadIdx.x) * 4;
    if (i >= n) return;
    float4 v = *(const float4*)(x + i);
    float f[4] = {v.x, v.y, v.z, v.w};
#pragma unroll
    for (int j = 0; j < 4; j++) {
        __half h = __float2half_rn(f[j]);
        hi[i + j] = h;
        lo[i + j] = __float2half_rn(f[j] - __half2float(h));
    }
}

__global__ void cvt_hi(const float* __restrict__ x, __half* __restrict__ hi, size_t n) {
    size_t i = ((size_t)blockIdx.x * blockDim.x + threadIdx.x) * 4;
    if (i >= n) return;
    float4 v = *(const float4*)(x + i);
    hi[i + 0] = __float2half_rn(v.x);
    hi[i + 1] = __float2half_rn(v.y);
    hi[i + 2] = __float2half_rn(v.z);
    hi[i + 3] = __float2half_rn(v.w);
}

__global__ void cvt_wqkv(const float* __restrict__ Wq,
                         const float* __restrict__ Wk,
                         const float* __restrict__ Wv,
                         __half* __restrict__ hi) {
    size_t i = ((size_t)blockIdx.x * blockDim.x + threadIdx.x) * 4;
    if (i >= WQKV_ELEMS) return;
    size_t row = i / HID_;
    const float* src;
    size_t off;
    if (row < (size_t)KOFF)      { src = Wq; off = i; }
    else if (row < (size_t)VOFF) { src = Wk; off = i - (size_t)KOFF * HID_; }
    else                         { src = Wv; off = i - (size_t)VOFF * HID_; }
    float4 v = *(const float4*)(src + off);
    hi[i + 0] = __float2half_rn(v.x);
    hi[i + 1] = __float2half_rn(v.y);
    hi[i + 2] = __float2half_rn(v.z);
    hi[i + 3] = __float2half_rn(v.w);
}

__global__ void rope_split(const float* __restrict__ x, int hoff,
                           const float* __restrict__ cosp,
                           const float* __restrict__ sinp,
                           __half* __restrict__ xh,
                           __half* __restrict__ xl, int write_lo,
                           int nheads, int total) {
    int idx = blockIdx.x * blockDim.x + threadIdx.x;
    if (idx >= total) return;
    int d  = idx & 63;
    int h  = (idx >> 6) % nheads;
    int bs = idx / (64 * nheads);
    const float* row = x + (size_t)bs * NQKV + hoff + (size_t)h * HD_;
    const float* c = cosp + (size_t)bs * HD_;
    const float* s = sinp + (size_t)bs * HD_;
    float x1 = row[d], x2 = row[d + 64];
    float y1 = x1 * c[d]      - x2 * s[d];
    float y2 = x2 * c[d + 64] + x1 * s[d + 64];
    size_t base = (size_t)bs * nheads * HD_ + (size_t)h * HD_;
    __half h1 = __float2half_rn(y1);
    __half h2 = __float2half_rn(y2);
    xh[base + d]      = h1;
    xh[base + d + 64] = h2;
    if (write_lo) {
        xl[base + d]      = __float2half_rn(y1 - __half2float(h1));
        xl[base + d + 64] = __float2half_rn(y2 - __half2float(h2));
    }
}

__global__ void cvtT_v(const float* __restrict__ v, __half* __restrict__ vh) {
    size_t idx = (size_t)blockIdx.x * blockDim.x + threadIdx.x;
    if (idx >= KV_ELEMS) return;
    int s  = idx & (S_ - 1);
    size_t r = idx >> 11;
    int d  = r & (HD_ - 1);  r >>= 7;
    int hk = r & (NKV_ - 1);
    int b  = (int)(r >> 3);
    float x = v[(size_t)(b * S_ + s) * NQKV + VOFF + hk * HD_ + d];
    vh[idx] = __float2half_rn(x);
}

// ---------------------------------------------------------------------------
// 2-plane fp16 NT GEMM: C = (Ah+Al) * Bh^T. 2 MMAs per k16 (both f32-acc).
// BK=32, 3-stage cp.async (2-deep lookahead), ONE barrier per iter.
// 256 threads (2x4 warps), warp tile 64x32. smem 92160B -> 2 CTA/SM.
// ---------------------------------------------------------------------------
#define BM 128
#define BN 128
#define GK 32
#define GPAD 40
#define GPLANE 5120
#define GSTAGE 15360                  // 3 planes (Ah, Al, Bh)
#define GSMEM_B (3 * GSTAGE * 2)      // 92160 bytes
#define SWG 16

__global__ __launch_bounds__(256)
void gemm_mma(const __half* __restrict__ Ah, const __half* __restrict__ Al,
              const __half* __restrict__ Bh,
              float* __restrict__ C, int M, int N, int K) {
    extern __shared__ __half gsm[];
    const uint32_t sb = smem_u32(gsm);

    const int tid = threadIdx.x;
    const int warp = tid >> 5, lane = tid & 31;
    const int g = lane >> 2, tg = lane & 3;
    const int warpM = warp >> 2, warpN = warp & 3;

    int bx, by;
    {
        int bid = blockIdx.y * gridDim.x + blockIdx.x;
        int per = SWG * gridDim.x;
        int grp = bid / per;
        int rem = bid - grp * per;
        by = grp * SWG + (rem & (SWG - 1));
        bx = rem >> 4;
    }
    const int bm = by * BM, bn = bx * BN;

    const int a_r = lane & 15;
    const int a_k = (lane >> 4) * 8;
    const int b_r = lane & 7;
    const int b_n8 = ((lane >> 4) & 1) * 8;
    const int b_k8 = ((lane >> 3) & 1) * 8;

    float c[4][4][4];
#pragma unroll
    for (int mi = 0; mi < 4; mi++)
#pragma unroll
        for (int ni = 0; ni < 4; ni++)
#pragma unroll
            for (int j = 0; j < 4; j++) c[mi][ni][j] = 0.f;

    const int niter = K / GK;

    auto load_stage = [&](int s, int k0) {
        const uint32_t base = sb + (uint32_t)(s * GSTAGE) * 2;
#pragma unroll
        for (int i = 0; i < 2; i++) {
            int j = tid + (i << 8);
            int row = j >> 2, col = (j & 3) * 8;
            size_t ao = (size_t)(bm + row) * K + k0 + col;
            size_t bo = (size_t)(bn + row) * K + k0 + col;
            uint32_t off = (uint32_t)(row * GPAD + col) * 2;
            cp16(base + off, Ah + ao);
            cp16(base + GPLANE * 2 + off, Al + ao);
            cp16(base + 2 * GPLANE * 2 + off, Bh + bo);
        }
        asm volatile("cp.async.commit_group;\n");
    };

    // prologue: 2-deep lookahead
    load_stage(0, 0);
    load_stage(1, GK);

    for (int i = 0; i < niter; i++) {
        if (i + 1 < niter) asm volatile("cp.async.wait_group 1;\n");
        else               asm volatile("cp.async.wait_group 0;\n");
        __syncthreads();
        // refill stage (i+2)%3 (its previous contents were consumed in iter i-1,
        // and every warp has passed that compute phase to reach this barrier)
        if (i + 2 < niter) load_stage((i + 2) % 3, (i + 2) * GK);

        const int s = i % 3;
        const __half* Asm = gsm + (size_t)s * GSTAGE;
        const __half* Bsm = Asm + 2 * GPLANE;
#pragma unroll
        for (int kk = 0; kk < 2; kk++) {
            const int kb = kk * 16;
            uint32_t aH[4][4], aL[4][4], bH[4][2];
#pragma unroll
            for (int mi = 0; mi < 4; mi++) {
                int rb = warpM * 64 + mi * 16;
                ldsm4(aH[mi][0], aH[mi][1], aH[mi][2], aH[mi][3],
                      Asm + (size_t)(rb + a_r) * GPAD + kb + a_k);
                ldsm4(aL[mi][0], aL[mi][1], aL[mi][2], aL[mi][3],
                      Asm + GPLANE + (size_t)(rb + a_r) * GPAD + kb + a_k);
            }
#pragma unroll
            for (int np = 0; np < 2; np++) {
                int nb = warpN * 32 + np * 16;
                uint32_t r0, r1, r2, r3;
                ldsm4(r0, r1, r2, r3,
                      Bsm + (size_t)(nb + b_r + b_n8) * GPAD + kb + b_k8);
                bH[np * 2][0] = r0; bH[np * 2][1] = r1;
                bH[np * 2 + 1][0] = r2; bH[np * 2 + 1][1] = r3;
            }
#pragma unroll
            for (int mi = 0; mi < 4; mi++)
#pragma unroll
                for (int ni = 0; ni < 4; ni++) {
                    mma16816(c[mi][ni], aH[mi][0], aH[mi][1], aH[mi][2], aH[mi][3],
                             bH[ni][0], bH[ni][1]);
                    mma16816(c[mi][ni], aL[mi][0], aL[mi][1], aL[mi][2], aL[mi][3],
                             bH[ni][0], bH[ni][1]);
                }
        }
    }

#pragma unroll
    for (int mi = 0; mi < 4; mi++) {
        int r0 = bm + warpM * 64 + mi * 16 + g;
#pragma unroll
        for (int ni = 0; ni < 4; ni++) {
            int cc = bn + warpN * 32 + ni * 8 + 2 * tg;
            *(float2*)(C + (size_t)r0 * N + cc) = make_float2(c[mi][ni][0], c[mi][ni][1]);
            *(float2*)(C + (size_t)(r0 + 8) * N + cc) = make_float2(c[mi][ni][2], c[mi][ni][3]);
        }
    }
}

// ---------------------------------------------------------------------------
// Flash attention: S = (Qh+Ql)Kh^T, O = (Ph+Pl)Vh. Main f32-acc, lo-plane
// corrections f16-acc. 128 threads, 64 q rows, 64-key tiles. smem 69KB.
// ---------------------------------------------------------------------------
#define FQH 0
#define FQL 8704
#define FKH 17408
#define FVH 26112
#define FSMEM_B 70656

__global__ __launch_bounds__(128)
void flash_mma(const __half* __restrict__ Qh, const __half* __restrict__ Ql,
               const __half* __restrict__ Kh, const __half* __restrict__ Vth,
               __half* __restrict__ Oh, __half* __restrict__ Ol) {
    extern __shared__ __half fsm[];
    const uint32_t sb = smem_u32(fsm);

    const int b = blockIdx.z, h = blockIdx.y, qt = blockIdx.x;
    const int qs = qt * 64, hk = h >> 2;
    const int tid = threadIdx.x;
    const int warp = tid >> 5, lane = tid & 31;
    const int g = lane >> 2, tg = lane & 3;

    const int a_r = lane & 15;
    const int a_k = (lane >> 4) * 8;
    const int b_r = lane & 7;
    const int b_n8 = ((lane >> 4) & 1) * 8;
    const int b_k8 = ((lane >> 3) & 1) * 8;

    // ---- load Q tile (hi+lo, once) ----
#pragma unroll
    for (int i = 0; i < 8; i++) {
        int j = tid + (i << 7);
        int row = j >> 4, kc = j & 15;
        uint32_t d = sb + (uint32_t)((row * 136 + kc * 8) * 2);
        size_t src = ((size_t)(b * S_ + qs + row) * NH_ + h) * HD_ + kc * 8;
        cp16(d + FQH * 2, Qh + src);
        cp16(d + FQL * 2, Ql + src);
    }
    asm volatile("cp.async.commit_group;\n");

    float o[16][4];
    uint32_t ocorr[16][2];
#pragma unroll
    for (int nt = 0; nt < 16; nt++) {
#pragma unroll
        for (int j = 0; j < 4; j++) o[nt][j] = 0.f;
        ocorr[nt][0] = 0u; ocorr[nt][1] = 0u;
    }
    float m0 = -1e30f, m1 = -1e30f, l0 = 0.f, l1 = 0.f;

    const int qr0 = qs + warp * 16 + g;
    const int qr1 = qr0 + 8;
    const int ntiles = qt + 1;

    for (int j = 0; j < ntiles; j++) {
        const int ks = j * 64;
#pragma unroll
        for (int i = 0; i < 8; i++) {
            int jj = tid + (i << 7);
            int krow = jj >> 4, kkc = jj & 15;
            uint32_t dk = sb + (uint32_t)((krow * 136 + kkc * 8) * 2);
            size_t ksrc = ((size_t)(b * S_ + ks + krow) * NKV_ + hk) * HD_ + kkc * 8;
            cp16(dk + FKH * 2, Kh + ksrc);
            int vd = jj >> 3, vc = jj & 7;
            uint32_t dv = sb + (uint32_t)((vd * 72 + vc * 8) * 2);
            size_t vsrc = ((size_t)(b * NKV_ + hk) * HD_ + vd) * S_ + ks + vc * 8;
            cp16(dv + FVH * 2, Vth + vsrc);
        }
        asm volatile("cp.async.commit_group;\n");
        asm volatile("cp.async.wait_group 0;\n");
        __syncthreads();

        // ---- S = Q K^T ----
        float S4[8][4];
        uint32_t scorr[8][2];
#pragma unroll
        for (int nt = 0; nt < 8; nt++) {
#pragma unroll
            for (int cc = 0; cc < 4; cc++) S4[nt][cc] = 0.f;
            scorr[nt][0] = 0u; scorr[nt][1] = 0u;
        }

#pragma unroll
        for (int dk = 0; dk < 8; dk++) {
            uint32_t aH[4], aL[4];
            ldsm4(aH[0], aH[1], aH[2], aH[3],
                  fsm + FQH + (size_t)(warp * 16 + a_r) * 136 + dk * 16 + a_k);
            ldsm4(aL[0], aL[1], aL[2], aL[3],
                  fsm + FQL + (size_t)(warp * 16 + a_r) * 136 + dk * 16 + a_k);
#pragma unroll
            for (int np = 0; np < 4; np++) {
                int nb = np * 16;
                uint32_t h0, h1, h2, h3;
                ldsm4(h0, h1, h2, h3,
                      fsm + FKH + (size_t)(nb + b_r + b_n8) * 136 + dk * 16 + b_k8);
                mma16816(S4[2 * np],     aH[0], aH[1], aH[2], aH[3], h0, h1);
                mma16816(S4[2 * np + 1], aH[0], aH[1], aH[2], aH[3], h2, h3);
                mma16816h(scorr[2 * np][0],     scorr[2 * np][1],
                          aL[0], aL[1], aL[2], aL[3], h0, h1);
                mma16816h(scorr[2 * np + 1][0], scorr[2 * np + 1][1],
                          aL[0], aL[1], aL[2], aL[3], h2, h3);
            }
        }
#pragma unroll
        for (int nt = 0; nt < 8; nt++) {
            S4[nt][0] += h2lo(scorr[nt][0]);
            S4[nt][1] += h2hi(scorr[nt][0]);
            S4[nt][2] += h2lo(scorr[nt][1]);
            S4[nt][3] += h2hi(scorr[nt][1]);
        }

        // ---- scale + mask + online softmax ----
        float mx0 = -1e30f, mx1 = -1e30f;
        const bool diag = (j == ntiles - 1);
#pragma unroll
        for (int nt = 0; nt < 8; nt++) {
#pragma unroll
            for (int cc = 0; cc < 4; cc++) {
                float v = S4[nt][cc] * SCALING_;
                if (diag) {
                    int kcol = ks + nt * 8 + 2 * tg + (cc & 1);
                    int qr = (cc < 2) ? qr0 : qr1;
                    if (kcol > qr) v = -1e30f;
                }
                S4[nt][cc] = v;
                if (cc < 2) mx0 = fmaxf(mx0, v); else mx1 = fmaxf(mx1, v);
            }
        }
        mx0 = fmaxf(mx0, __shfl_xor_sync(0xffffffffu, mx0, 1));
        mx0 = fmaxf(mx0, __shfl_xor_sync(0xffffffffu, mx0, 2));
        mx1 = fmaxf(mx1, __shfl_xor_sync(0xffffffffu, mx1, 1));
        mx1 = fmaxf(mx1, __shfl_xor_sync(0xffffffffu, mx1, 2));
        const float mt0 = fmaxf(m0, mx0), mt1 = fmaxf(m1, mx1);
        const float sc0 = __expf(m0 - mt0), sc1 = __expf(m1 - mt1);
        m0 = mt0; m1 = mt1;

        float rs0 = 0.f, rs1 = 0.f;
#pragma unroll
        for (int nt = 0; nt < 8; nt++) {
            float p0 = __expf(S4[nt][0] - mt0);
            float p1 = __expf(S4[nt][1] - mt0);
            float p2 = __expf(S4[nt][2] - mt1);
            float p3 = __expf(S4[nt][3] - mt1);
            S4[nt][0] = p0; S4[nt][1] = p1; S4[nt][2] = p2; S4[nt][3] = p3;
            rs0 += p0 + p1; rs1 += p2 + p3;
        }
        rs0 += __shfl_xor_sync(0xffffffffu, rs0, 1);
        rs0 += __shfl_xor_sync(0xffffffffu, rs0, 2);
        rs1 += __shfl_xor_sync(0xffffffffu, rs1, 1);
        rs1 += __shfl_xor_sync(0xffffffffu, rs1, 2);
        l0 = l0 * sc0 + rs0;
        l1 = l1 * sc1 + rs1;
#pragma unroll
        for (int nt = 0; nt < 16; nt++) {
            o[nt][0] *= sc0; o[nt][1] *= sc0;
            o[nt][2] *= sc1; o[nt][3] *= sc1;
            ocorr[nt][0] = h2scale(ocorr[nt][0], sc0);
            ocorr[nt][1] = h2scale(ocorr[nt][1], sc1);
        }

        // ---- O += P V ----
#pragma unroll
        for (int kt = 0; kt < 4; kt++) {
            uint32_t aPh[4], aPl[4];
#pragma unroll
            for (int half = 0; half < 2; half++) {
                const float* sv = S4[2 * kt + half];
                uint32_t p01 = pk_h2(sv[0], sv[1]);
                uint32_t p23 = pk_h2(sv[2], sv[3]);
                float r0f = sv[0] - h2lo(p01);
                float r1f = sv[1] - h2hi(p01);
                float r2f = sv[2] - h2lo(p23);
                float r3f = sv[3] - h2hi(p23);
                aPh[0 + 2 * half] = p01;
                aPh[1 + 2 * half] = p23;
                aPl[0 + 2 * half] = pk_h2(r0f, r1f);
                aPl[1 + 2 * half] = pk_h2(r2f, r3f);
            }
#pragma unroll
            for (int np = 0; np < 8; np++) {
                int nb = np * 16;
                uint32_t h0, h1, h2, h3;
                ldsm4(h0, h1, h2, h3,
                      fsm + FVH + (size_t)(nb + b_r + b_n8) * 72 + kt * 16 + b_k8);
                mma16816(o[2 * np],     aPh[0], aPh[1], aPh[2], aPh[3], h0, h1);
                mma16816(o[2 * np + 1], aPh[0], aPh[1], aPh[2], aPh[3], h2, h3);
                mma16816h(ocorr[2 * np][0],     ocorr[2 * np][1],
                          aPl[0], aPl[1], aPl[2], aPl[3], h0, h1);
                mma16816h(ocorr[2 * np + 1][0], ocorr[2 * np + 1][1],
                          aPl[0], aPl[1], aPl[2], aPl[3], h2, h3);
            }
        }
        __syncthreads();
    }

    // ---- writeback ----
    const float inv0 = 1.f / l0, inv1 = 1.f / l1;
    const size_t r0base = ((size_t)(b * S_ + qr0) * NH_ + h) * HD_;
    const size_t r1base = ((size_t)(b * S_ + qr1) * NH_ + h) * HD_;
#pragma unroll
    for (int nt = 0; nt < 16; nt++) {
        int cc = nt * 8 + 2 * tg;
        float v00 = (o[nt][0] + h2lo(ocorr[nt][0])) * inv0;
        float v01 = (o[nt][1] + h2hi(ocorr[nt][0])) * inv0;
        float v10 = (o[nt][2] + h2lo(ocorr[nt][1])) * inv1;
        float v11 = (o[nt][3] + h2hi(ocorr[nt][1])) * inv1;
        uint32_t h0p = pk_h2(v00, v01);
        uint32_t h1p = pk_h2(v10, v11);
        float e00 = v00 - h2lo(h0p);
        float e01 = v01 - h2hi(h0p);
        float e10 = v10 - h2lo(h1p);
        float e11 = v11 - h2hi(h1p);
        *(uint32_t*)(Oh + r0base + cc) = h0p;
        *(uint32_t*)(Ol + r0base + cc) = pk_h2(e00, e01);
        *(uint32_t*)(Oh + r1base + cc) = h1p;
        *(uint32_t*)(Ol + r1base + cc) = pk_h2(e10, e11);
    }
}

// ---------------------------------------------------------------------------
// Launch
// ---------------------------------------------------------------------------
extern "C" void kernel_launch(void* const* d_in, const int* in_sizes, int n_in,
                              void* d_out, int out_size) {
    const float* hs   = (const float*)d_in[0];
    const float* cosp = (const float*)d_in[1];
    const float* sinp = (const float*)d_in[2];
    const float* Wq   = (const float*)d_in[4];
    const float* Wk   = (const float*)d_in[5];
    const float* Wv   = (const float*)d_in[6];
    const float* Wo   = (const float*)d_in[7];
    float* out = (float*)d_out;

    float* qkv;
    cudaGetSymbolAddress((void**)&qkv, g_qkv);

    __half *hs_h, *hs_l, *wqkv_h, *wo_h, *ob_h, *ob_l, *qh, *ql, *kh, *vth;
    cudaGetSymbolAddress((void**)&hs_h, g_hs_h); cudaGetSymbolAddress((void**)&hs_l, g_hs_l);
    cudaGetSymbolAddress((void**)&wqkv_h, g_wqkv_h);
    cudaGetSymbolAddress((void**)&wo_h, g_wo_h);
    cudaGetSymbolAddress((void**)&ob_h, g_ob_h); cudaGetSymbolAddress((void**)&ob_l, g_ob_l);
    cudaGetSymbolAddress((void**)&qh, g_qh); cudaGetSymbolAddress((void**)&ql, g_ql);
    cudaGetSymbolAddress((void**)&kh, g_kh);
    cudaGetSymbolAddress((void**)&vth, g_vth);

    cudaFuncSetAttribute(gemm_mma, cudaFuncAttributeMaxDynamicSharedMemorySize, GSMEM_B);
    cudaFuncSetAttribute(flash_mma, cudaFuncAttributeMaxDynamicSharedMemorySize, FSMEM_B);

    const int M = B_ * S_;   // 4096

    // conversions
    cvt_wqkv<<<(WQKV_ELEMS / 4 + 255) / 256, 256>>>(Wq, Wk, Wv, wqkv_h);
    split_kernel<<<(HS_ELEMS / 4 + 255) / 256, 256>>>(hs, hs_h, hs_l, HS_ELEMS);

    // fused QKV projection
    gemm_mma<<<dim3(NQKV / BN, M / BM), 256, GSMEM_B>>>(
        hs_h, hs_l, wqkv_h, qkv, M, NQKV, HID_);

    cvt_hi<<<(WO_ELEMS / 4 + 255) / 256, 256>>>(Wo, wo_h, WO_ELEMS);

    // RoPE + split (Q hi+lo, K hi); V transpose+convert
    {
        int totq = B_ * S_ * NH_ * 64;
        rope_split<<<(totq + 255) / 256, 256>>>(qkv, 0, cosp, sinp, qh, ql, 1, NH_, totq);
        int totk = B_ * S_ * NKV_ * 64;
        rope_split<<<(totk + 255) / 256, 256>>>(qkv, KOFF, cosp, sinp, kh, nullptr, 0, NKV_, totk);
        cvtT_v<<<(KV_ELEMS + 255) / 256, 256>>>(qkv, vth);
    }

    // flash attention
    flash_mma<<<dim3(S_ / 64, NH_, B_), 128, FSMEM_B>>>(qh, ql, kh, vth, ob_h, ob_l);

    // O projection
    gemm_mma<<<dim3(HID_ / BN, M / BM), 256, GSMEM_B>>>(ob_h, ob_l, wo_h, out, M, HID_, NH_ * HD_);
}

// round 12
// speedup vs baseline: 1.7694x; 1.0587x over previous
#include <cuda_runtime.h>
#include <cuda_fp16.h>
#include <cstdint>

// Problem constants
#define B_   2
#define S_   2048
#define HID_ 4096
#define NH_  32
#define NKV_ 8
#define HD_  128
#define NREP_ 4
#define SCALING_ 0.08838834764831843f   // 128^-0.5

#define NQKV 6144      // 4096 (Q) + 1024 (K) + 1024 (V)
#define KOFF 4096
#define VOFF 5120

// fp32 scratch: fused QKV GEMM output [B*S][NQKV]
__device__ float g_qkv[(size_t)B_ * S_ * NQKV];

// fp16 planes
#define HS_ELEMS   ((size_t)B_ * S_ * HID_)
#define WQKV_ELEMS ((size_t)NQKV * HID_)
#define WO_ELEMS   ((size_t)HID_ * NH_ * HD_)
#define KV_ELEMS   ((size_t)B_ * S_ * NKV_ * HD_)
__device__ __half g_hs_h[HS_ELEMS], g_hs_l[HS_ELEMS];
__device__ __half g_wqkv_h[WQKV_ELEMS];             // weights: hi only
__device__ __half g_wo_h[WO_ELEMS];                 // weights: hi only
__device__ __half g_ob_h[HS_ELEMS], g_ob_l[HS_ELEMS];
// attention planes (post-rope): Q hi+lo; K,V hi only
__device__ __half g_qh[HS_ELEMS], g_ql[HS_ELEMS];
__device__ __half g_kh[KV_ELEMS];
__device__ __half g_vth[KV_ELEMS];                  // [b][hk][d][s]

// ---------------------------------------------------------------------------
// helpers
// ---------------------------------------------------------------------------
static __device__ __forceinline__ uint32_t smem_u32(const void* p) {
    uint32_t a;
    asm("{ .reg .u64 t; cvta.to.shared.u64 t, %1; cvt.u32.u64 %0, t; }"
        : "=r"(a) : "l"(p));
    return a;
}
static __device__ __forceinline__ void cp16(uint32_t dst, const void* src) {
    asm volatile("cp.async.cg.shared.global [%0], [%1], 16;\n" :: "r"(dst), "l"(src));
}
__device__ __forceinline__ void mma16816(float c[4], uint32_t a0, uint32_t a1,
                                         uint32_t a2, uint32_t a3,
                                         uint32_t b0, uint32_t b1) {
    asm volatile(
        "mma.sync.aligned.m16n8k16.row.col.f32.f16.f16.f32 "
        "{%0,%1,%2,%3}, {%4,%5,%6,%7}, {%8,%9}, {%0,%1,%2,%3};\n"
        : "+f"(c[0]), "+f"(c[1]), "+f"(c[2]), "+f"(c[3])
        : "r"(a0), "r"(a1), "r"(a2), "r"(a3), "r"(b0), "r"(b1));
}
__device__ __forceinline__ void mma16816h(uint32_t& c0, uint32_t& c1,
                                          uint32_t a0, uint32_t a1,
                                          uint32_t a2, uint32_t a3,
                                          uint32_t b0, uint32_t b1) {
    asm volatile(
        "mma.sync.aligned.m16n8k16.row.col.f16.f16.f16.f16 "
        "{%0,%1}, {%2,%3,%4,%5}, {%6,%7}, {%0,%1};\n"
        : "+r"(c0), "+r"(c1)
        : "r"(a0), "r"(a1), "r"(a2), "r"(a3), "r"(b0), "r"(b1));
}
__device__ __forceinline__ void ldsm4(uint32_t& r0, uint32_t& r1, uint32_t& r2,
                                      uint32_t& r3, const void* p) {
    uint32_t a = (uint32_t)__cvta_generic_to_shared(p);
    asm volatile("ldmatrix.sync.aligned.m8n8.x4.shared.b16 {%0,%1,%2,%3}, [%4];\n"
                 : "=r"(r0), "=r"(r1), "=r"(r2), "=r"(r3) : "r"(a));
}
static __device__ __forceinline__ uint32_t pk_h2(float lo, float hi) {
    __half2 t = __floats2half2_rn(lo, hi);
    return *reinterpret_cast<uint32_t*>(&t);
}
static __device__ __forceinline__ float h2lo(uint32_t u) {
    __half2 h = *reinterpret_cast<__half2*>(&u);
    return __half2float(__low2half(h));
}
static __device__ __forceinline__ float h2hi(uint32_t u) {
    __half2 h = *reinterpret_cast<__half2*>(&u);
    return __half2float(__high2half(h));
}
static __device__ __forceinline__ uint32_t h2scale(uint32_t u, float s) {
    __half2 h = *reinterpret_cast<__half2*>(&u);
    __half2 r = __hmul2(h, __float2half2_rn(s));
    return *reinterpret_cast<uint32_t*>(&r);
}

// ---------------------------------------------------------------------------
// conversion kernels
// ---------------------------------------------------------------------------
__global__ void split_kernel(const float* __restrict__ x,
                             __half* __restrict__ hi,
                             __half* __restrict__ lo, size_t n) {
    size_t i = ((size_t)blockIdx.x * blockDim.x + threadIdx.x) * 4;
    if (i >= n) return;
    float4 v = *(const float4*)(x + i);
    float f[4] = {v.x, v.y, v.z, v.w};
#pragma unroll
    for (int j = 0; j < 4; j++) {
        __half h = __float2half_rn(f[j]);
        hi[i + j] = h;
        lo[i + j] = __float2half_rn(f[j] - __half2float(h));
    }
}

__global__ void cvt_hi(const float* __restrict__ x, __half* __restrict__ hi, size_t n) {
    size_t i = ((size_t)blockIdx.x * blockDim.x + threadIdx.x) * 4;
    if (i >= n) return;
    float4 v = *(const float4*)(x + i);
    hi[i + 0] = __float2half_rn(v.x);
    hi[i + 1] = __float2half_rn(v.y);
    hi[i + 2] = __float2half_rn(v.z);
    hi[i + 3] = __float2half_rn(v.w);
}

__global__ void cvt_wqkv(const float* __restrict__ Wq,
                         const float* __restrict__ Wk,
                         const float* __restrict__ Wv,
                         __half* __restrict__ hi) {
    size_t i = ((size_t)blockIdx.x * blockDim.x + threadIdx.x) * 4;
    if (i >= WQKV_ELEMS) return;
    size_t row = i / HID_;
    const float* src;
    size_t off;
    if (row < (size_t)KOFF)      { src = Wq; off = i; }
    else if (row < (size_t)VOFF) { src = Wk; off = i - (size_t)KOFF * HID_; }
    else                         { src = Wv; off = i - (size_t)VOFF * HID_; }
    float4 v = *(const float4*)(src + off);
    hi[i + 0] = __float2half_rn(v.x);
    hi[i + 1] = __float2half_rn(v.y);
    hi[i + 2] = __float2half_rn(v.z);
    hi[i + 3] = __float2half_rn(v.w);
}

__global__ void rope_split(const float* __restrict__ x, int hoff,
                           const float* __restrict__ cosp,
                           const float* __restrict__ sinp,
                           __half* __restrict__ xh,
                           __half* __restrict__ xl, int write_lo,
                           int nheads, int total) {
    int idx = blockIdx.x * blockDim.x + threadIdx.x;
    if (idx >= total) return;
    int d  = idx & 63;
    int h  = (idx >> 6) % nheads;
    int bs = idx / (64 * nheads);
    const float* row = x + (size_t)bs * NQKV + hoff + (size_t)h * HD_;
    const float* c = cosp + (size_t)bs * HD_;
    const float* s = sinp + (size_t)bs * HD_;
    float x1 = row[d], x2 = row[d + 64];
    float y1 = x1 * c[d]      - x2 * s[d];
    float y2 = x2 * c[d + 64] + x1 * s[d + 64];
    size_t base = (size_t)bs * nheads * HD_ + (size_t)h * HD_;
    __half h1 = __float2half_rn(y1);
    __half h2 = __float2half_rn(y2);
    xh[base + d]      = h1;
    xh[base + d + 64] = h2;
    if (write_lo) {
        xl[base + d]      = __float2half_rn(y1 - __half2float(h1));
        xl[base + d + 64] = __float2half_rn(y2 - __half2float(h2));
    }
}

__global__ void cvtT_v(const float* __restrict__ v, __half* __restrict__ vh) {
    size_t idx = (size_t)blockIdx.x * blockDim.x + threadIdx.x;
    if (idx >= KV_ELEMS) return;
    int s  = idx & (S_ - 1);
    size_t r = idx >> 11;
    int d  = r & (HD_ - 1);  r >>= 7;
    int hk = r & (NKV_ - 1);
    int b  = (int)(r >> 3);
    float x = v[(size_t)(b * S_ + s) * NQKV + VOFF + hk * HD_ + d];
    vh[idx] = __float2half_rn(x);
}

// ---------------------------------------------------------------------------
// 2-plane fp16 NT GEMM: C = (Ah+Al) * Bh^T, with the Al correction SKIPPED
// for output columns >= nlo (their结果 is immediately fp16-quantized anyway).
// BK=32, 3-stage cp.async (2-deep lookahead), one barrier per iter.
// 256 threads (2x4 warps), warp tile 64x32. smem 92160B -> 2 CTA/SM.
// ---------------------------------------------------------------------------
#define BM 128
#define BN 128
#define GK 32
#define GPAD 40
#define GPLANE 5120
#define GSTAGE 15360                  // 3 planes (Ah, Al, Bh)
#define GSMEM_B (3 * GSTAGE * 2)      // 92160 bytes
#define SWG 16

__global__ __launch_bounds__(256)
void gemm_mma(const __half* __restrict__ Ah, const __half* __restrict__ Al,
              const __half* __restrict__ Bh,
              float* __restrict__ C, int M, int N, int K, int nlo) {
    extern __shared__ __half gsm[];
    const uint32_t sb = smem_u32(gsm);

    const int tid = threadIdx.x;
    const int warp = tid >> 5, lane = tid & 31;
    const int g = lane >> 2, tg = lane & 3;
    const int warpM = warp >> 2, warpN = warp & 3;

    int bx, by;
    {
        int bid = blockIdx.y * gridDim.x + blockIdx.x;
        int per = SWG * gridDim.x;
        int grp = bid / per;
        int rem = bid - grp * per;
        by = grp * SWG + (rem & (SWG - 1));
        bx = rem >> 4;
    }
    const int bm = by * BM, bn = bx * BN;
    const bool use_lo = (bn < nlo);   // CTA-uniform

    const int a_r = lane & 15;
    const int a_k = (lane >> 4) * 8;
    const int b_r = lane & 7;
    const int b_n8 = ((lane >> 4) & 1) * 8;
    const int b_k8 = ((lane >> 3) & 1) * 8;

    float c[4][4][4];
#pragma unroll
    for (int mi = 0; mi < 4; mi++)
#pragma unroll
        for (int ni = 0; ni < 4; ni++)
#pragma unroll
            for (int j = 0; j < 4; j++) c[mi][ni][j] = 0.f;

    const int niter = K / GK;

    auto load_stage = [&](int s, int k0) {
        const uint32_t base = sb + (uint32_t)(s * GSTAGE) * 2;
#pragma unroll
        for (int i = 0; i < 2; i++) {
            int j = tid + (i << 8);
            int row = j >> 2, col = (j & 3) * 8;
            size_t ao = (size_t)(bm + row) * K + k0 + col;
            size_t bo = (size_t)(bn + row) * K + k0 + col;
            uint32_t off = (uint32_t)(row * GPAD + col) * 2;
            cp16(base + off, Ah + ao);
            if (use_lo) cp16(base + GPLANE * 2 + off, Al + ao);
            cp16(base + 2 * GPLANE * 2 + off, Bh + bo);
        }
        asm volatile("cp.async.commit_group;\n");
    };

    // prologue: 2-deep lookahead
    load_stage(0, 0);
    load_stage(1, GK);

    for (int i = 0; i < niter; i++) {
        if (i + 1 < niter) asm volatile("cp.async.wait_group 1;\n");
        else               asm volatile("cp.async.wait_group 0;\n");
        __syncthreads();
        if (i + 2 < niter) load_stage((i + 2) % 3, (i + 2) * GK);

        const int s = i % 3;
        const __half* Asm = gsm + (size_t)s * GSTAGE;
        const __half* Bsm = Asm + 2 * GPLANE;
#pragma unroll
        for (int kk = 0; kk < 2; kk++) {
            const int kb = kk * 16;
            uint32_t aH[4][4], aL[4][4], bH[4][2];
#pragma unroll
            for (int mi = 0; mi < 4; mi++) {
                int rb = warpM * 64 + mi * 16;
                ldsm4(aH[mi][0], aH[mi][1], aH[mi][2], aH[mi][3],
                      Asm + (size_t)(rb + a_r) * GPAD + kb + a_k);
                if (use_lo)
                    ldsm4(aL[mi][0], aL[mi][1], aL[mi][2], aL[mi][3],
                          Asm + GPLANE + (size_t)(rb + a_r) * GPAD + kb + a_k);
            }
#pragma unroll
            for (int np = 0; np < 2; np++) {
                int nb = warpN * 32 + np * 16;
                uint32_t r0, r1, r2, r3;
                ldsm4(r0, r1, r2, r3,
                      Bsm + (size_t)(nb + b_r + b_n8) * GPAD + kb + b_k8);
                bH[np * 2][0] = r0; bH[np * 2][1] = r1;
                bH[np * 2 + 1][0] = r2; bH[np * 2 + 1][1] = r3;
            }
            if (use_lo) {
#pragma unroll
                for (int mi = 0; mi < 4; mi++)
#pragma unroll
                    for (int ni = 0; ni < 4; ni++) {
                        mma16816(c[mi][ni], aH[mi][0], aH[mi][1], aH[mi][2], aH[mi][3],
                                 bH[ni][0], bH[ni][1]);
                        mma16816(c[mi][ni], aL[mi][0], aL[mi][1], aL[mi][2], aL[mi][3],
                                 bH[ni][0], bH[ni][1]);
                    }
            } else {
#pragma unroll
                for (int mi = 0; mi < 4; mi++)
#pragma unroll
                    for (int ni = 0; ni < 4; ni++)
                        mma16816(c[mi][ni], aH[mi][0], aH[mi][1], aH[mi][2], aH[mi][3],
                                 bH[ni][0], bH[ni][1]);
            }
        }
    }

#pragma unroll
    for (int mi = 0; mi < 4; mi++) {
        int r0 = bm + warpM * 64 + mi * 16 + g;
#pragma unroll
        for (int ni = 0; ni < 4; ni++) {
            int cc = bn + warpN * 32 + ni * 8 + 2 * tg;
            *(float2*)(C + (size_t)r0 * N + cc) = make_float2(c[mi][ni][0], c[mi][ni][1]);
            *(float2*)(C + (size_t)(r0 + 8) * N + cc) = make_float2(c[mi][ni][2], c[mi][ni][3]);
        }
    }
}

// ---------------------------------------------------------------------------
// Flash attention: S = (Qh+Ql)Kh^T, O = (Ph+Pl)Vh. Main f32-acc, lo-plane
// corrections f16-acc. 128 threads, 64 q rows, 64-key tiles. smem 69KB.
// ---------------------------------------------------------------------------
#define FQH 0
#define FQL 8704
#define FKH 17408
#define FVH 26112
#define FSMEM_B 70656

__global__ __launch_bounds__(128)
void flash_mma(const __half* __restrict__ Qh, const __half* __restrict__ Ql,
               const __half* __restrict__ Kh, const __half* __restrict__ Vth,
               __half* __restrict__ Oh, __half* __restrict__ Ol) {
    extern __shared__ __half fsm[];
    const uint32_t sb = smem_u32(fsm);

    const int b = blockIdx.z, h = blockIdx.y, qt = blockIdx.x;
    const int qs = qt * 64, hk = h >> 2;
    const int tid = threadIdx.x;
    const int warp = tid >> 5, lane = tid & 31;
    const int g = lane >> 2, tg = lane & 3;

    const int a_r = lane & 15;
    const int a_k = (lane >> 4) * 8;
    const int b_r = lane & 7;
    const int b_n8 = ((lane >> 4) & 1) * 8;
    const int b_k8 = ((lane >> 3) & 1) * 8;

    // ---- load Q tile (hi+lo, once) ----
#pragma unroll
    for (int i = 0; i < 8; i++) {
        int j = tid + (i << 7);
        int row = j >> 4, kc = j & 15;
        uint32_t d = sb + (uint32_t)((row * 136 + kc * 8) * 2);
        size_t src = ((size_t)(b * S_ + qs + row) * NH_ + h) * HD_ + kc * 8;
        cp16(d + FQH * 2, Qh + src);
        cp16(d + FQL * 2, Ql + src);
    }
    asm volatile("cp.async.commit_group;\n");

    float o[16][4];
    uint32_t ocorr[16][2];
#pragma unroll
    for (int nt = 0; nt < 16; nt++) {
#pragma unroll
        for (int j = 0; j < 4; j++) o[nt][j] = 0.f;
        ocorr[nt][0] = 0u; ocorr[nt][1] = 0u;
    }
    float m0 = -1e30f, m1 = -1e30f, l0 = 0.f, l1 = 0.f;

    const int qr0 = qs + warp * 16 + g;
    const int qr1 = qr0 + 8;
    const int ntiles = qt + 1;

    for (int j = 0; j < ntiles; j++) {
        const int ks = j * 64;
#pragma unroll
        for (int i = 0; i < 8; i++) {
            int jj = tid + (i << 7);
            int krow = jj >> 4, kkc = jj & 15;
            uint32_t dk = sb + (uint32_t)((krow * 136 + kkc * 8) * 2);
            size_t ksrc = ((size_t)(b * S_ + ks + krow) * NKV_ + hk) * HD_ + kkc * 8;
            cp16(dk + FKH * 2, Kh + ksrc);
            int vd = jj >> 3, vc = jj & 7;
            uint32_t dv = sb + (uint32_t)((vd * 72 + vc * 8) * 2);
            size_t vsrc = ((size_t)(b * NKV_ + hk) * HD_ + vd) * S_ + ks + vc * 8;
            cp16(dv + FVH * 2, Vth + vsrc);
        }
        asm volatile("cp.async.commit_group;\n");
        asm volatile("cp.async.wait_group 0;\n");
        __syncthreads();

        // ---- S = Q K^T ----
        float S4[8][4];
        uint32_t scorr[8][2];
#pragma unroll
        for (int nt = 0; nt < 8; nt++) {
#pragma unroll
            for (int cc = 0; cc < 4; cc++) S4[nt][cc] = 0.f;
            scorr[nt][0] = 0u; scorr[nt][1] = 0u;
        }

#pragma unroll
        for (int dk = 0; dk < 8; dk++) {
            uint32_t aH[4], aL[4];
            ldsm4(aH[0], aH[1], aH[2], aH[3],
                  fsm + FQH + (size_t)(warp * 16 + a_r) * 136 + dk * 16 + a_k);
            ldsm4(aL[0], aL[1], aL[2], aL[3],
                  fsm + FQL + (size_t)(warp * 16 + a_r) * 136 + dk * 16 + a_k);
#pragma unroll
            for (int np = 0; np < 4; np++) {
                int nb = np * 16;
                uint32_t h0, h1, h2, h3;
                ldsm4(h0, h1, h2, h3,
                      fsm + FKH + (size_t)(nb + b_r + b_n8) * 136 + dk * 16 + b_k8);
                mma16816(S4[2 * np],     aH[0], aH[1], aH[2], aH[3], h0, h1);
                mma16816(S4[2 * np + 1], aH[0], aH[1], aH[2], aH[3], h2, h3);
                mma16816h(scorr[2 * np][0],     scorr[2 * np][1],
                          aL[0], aL[1], aL[2], aL[3], h0, h1);
                mma16816h(scorr[2 * np + 1][0], scorr[2 * np + 1][1],
                          aL[0], aL[1], aL[2], aL[3], h2, h3);
            }
        }
#pragma unroll
        for (int nt = 0; nt < 8; nt++) {
            S4[nt][0] += h2lo(scorr[nt][0]);
            S4[nt][1] += h2hi(scorr[nt][0]);
            S4[nt][2] += h2lo(scorr[nt][1]);
            S4[nt][3] += h2hi(scorr[nt][1]);
        }

        // ---- scale + mask + online softmax ----
        float mx0 = -1e30f, mx1 = -1e30f;
        const bool diag = (j == ntiles - 1);
#pragma unroll
        for (int nt = 0; nt < 8; nt++) {
#pragma unroll
            for (int cc = 0; cc < 4; cc++) {
                float v = S4[nt][cc] * SCALING_;
                if (diag) {
                    int kcol = ks + nt * 8 + 2 * tg + (cc & 1);
                    int qr = (cc < 2) ? qr0 : qr1;
                    if (kcol > qr) v = -1e30f;
                }
                S4[nt][cc] = v;
                if (cc < 2) mx0 = fmaxf(mx0, v); else mx1 = fmaxf(mx1, v);
            }
        }
        mx0 = fmaxf(mx0, __shfl_xor_sync(0xffffffffu, mx0, 1));
        mx0 = fmaxf(mx0, __shfl_xor_sync(0xffffffffu, mx0, 2));
        mx1 = fmaxf(mx1, __shfl_xor_sync(0xffffffffu, mx1, 1));
        mx1 = fmaxf(mx1, __shfl_xor_sync(0xffffffffu, mx1, 2));
        const float mt0 = fmaxf(m0, mx0), mt1 = fmaxf(m1, mx1);
        const float sc0 = __expf(m0 - mt0), sc1 = __expf(m1 - mt1);
        m0 = mt0; m1 = mt1;

        float rs0 = 0.f, rs1 = 0.f;
#pragma unroll
        for (int nt = 0; nt < 8; nt++) {
            float p0 = __expf(S4[nt][0] - mt0);
            float p1 = __expf(S4[nt][1] - mt0);
            float p2 = __expf(S4[nt][2] - mt1);
            float p3 = __expf(S4[nt][3] - mt1);
            S4[nt][0] = p0; S4[nt][1] = p1; S4[nt][2] = p2; S4[nt][3] = p3;
            rs0 += p0 + p1; rs1 += p2 + p3;
        }
        rs0 += __shfl_xor_sync(0xffffffffu, rs0, 1);
        rs0 += __shfl_xor_sync(0xffffffffu, rs0, 2);
        rs1 += __shfl_xor_sync(0xffffffffu, rs1, 1);
        rs1 += __shfl_xor_sync(0xffffffffu, rs1, 2);
        l0 = l0 * sc0 + rs0;
        l1 = l1 * sc1 + rs1;
#pragma unroll
        for (int nt = 0; nt < 16; nt++) {
            o[nt][0] *= sc0; o[nt][1] *= sc0;
            o[nt][2] *= sc1; o[nt][3] *= sc1;
            ocorr[nt][0] = h2scale(ocorr[nt][0], sc0);
            ocorr[nt][1] = h2scale(ocorr[nt][1], sc1);
        }

        // ---- O += P V ----
#pragma unroll
        for (int kt = 0; kt < 4; kt++) {
            uint32_t aPh[4], aPl[4];
#pragma unroll
            for (int half = 0; half < 2; half++) {
                const float* sv = S4[2 * kt + half];
                uint32_t p01 = pk_h2(sv[0], sv[1]);
                uint32_t p23 = pk_h2(sv[2], sv[3]);
                float r0f = sv[0] - h2lo(p01);
                float r1f = sv[1] - h2hi(p01);
                float r2f = sv[2] - h2lo(p23);
                float r3f = sv[3] - h2hi(p23);
                aPh[0 + 2 * half] = p01;
                aPh[1 + 2 * half] = p23;
                aPl[0 + 2 * half] = pk_h2(r0f, r1f);
                aPl[1 + 2 * half] = pk_h2(r2f, r3f);
            }
#pragma unroll
            for (int np = 0; np < 8; np++) {
                int nb = np * 16;
                uint32_t h0, h1, h2, h3;
                ldsm4(h0, h1, h2, h3,
                      fsm + FVH + (size_t)(nb + b_r + b_n8) * 72 + kt * 16 + b_k8);
                mma16816(o[2 * np],     aPh[0], aPh[1], aPh[2], aPh[3], h0, h1);
                mma16816(o[2 * np + 1], aPh[0], aPh[1], aPh[2], aPh[3], h2, h3);
                mma16816h(ocorr[2 * np][0],     ocorr[2 * np][1],
                          aPl[0], aPl[1], aPl[2], aPl[3], h0, h1);
                mma16816h(ocorr[2 * np + 1][0], ocorr[2 * np + 1][1],
                          aPl[0], aPl[1], aPl[2], aPl[3], h2, h3);
            }
        }
        __syncthreads();
    }

    // ---- writeback ----
    const float inv0 = 1.f / l0, inv1 = 1.f / l1;
    const size_t r0base = ((size_t)(b * S_ + qr0) * NH_ + h) * HD_;
    const size_t r1base = ((size_t)(b * S_ + qr1) * NH_ + h) * HD_;
#pragma unroll
    for (int nt = 0; nt < 16; nt++) {
        int cc = nt * 8 + 2 * tg;
        float v00 = (o[nt][0] + h2lo(ocorr[nt][0])) * inv0;
        float v01 = (o[nt][1] + h2hi(ocorr[nt][0])) * inv0;
        float v10 = (o[nt][2] + h2lo(ocorr[nt][1])) * inv1;
        float v11 = (o[nt][3] + h2hi(ocorr[nt][1])) * inv1;
        uint32_t h0p = pk_h2(v00, v01);
        uint32_t h1p = pk_h2(v10, v11);
        float e00 = v00 - h2lo(h0p);
        float e01 = v01 - h2hi(h0p);
        float e10 = v10 - h2lo(h1p);
        float e11 = v11 - h2hi(h1p);
        *(uint32_t*)(Oh + r0base + cc) = h0p;
        *(uint32_t*)(Ol + r0base + cc) = pk_h2(e00, e01);
        *(uint32_t*)(Oh + r1base + cc) = h1p;
        *(uint32_t*)(Ol + r1base + cc) = pk_h2(e10, e11);
    }
}

// ---------------------------------------------------------------------------
// Launch
// ---------------------------------------------------------------------------
extern "C" void kernel_launch(void* const* d_in, const int* in_sizes, int n_in,
                              void* d_out, int out_size) {
    const float* hs   = (const float*)d_in[0];
    const float* cosp = (const float*)d_in[1];
    const float* sinp = (const float*)d_in[2];
    const float* Wq   = (const float*)d_in[4];
    const float* Wk   = (const float*)d_in[5];
    const float* Wv   = (const float*)d_in[6];
    const float* Wo   = (const float*)d_in[7];
    float* out = (float*)d_out;

    float* qkv;
    cudaGetSymbolAddress((void**)&qkv, g_qkv);

    __half *hs_h, *hs_l, *wqkv_h, *wo_h, *ob_h, *ob_l, *qh, *ql, *kh, *vth;
    cudaGetSymbolAddress((void**)&hs_h, g_hs_h); cudaGetSymbolAddress((void**)&hs_l, g_hs_l);
    cudaGetSymbolAddress((void**)&wqkv_h, g_wqkv_h);
    cudaGetSymbolAddress((void**)&wo_h, g_wo_h);
    cudaGetSymbolAddress((void**)&ob_h, g_ob_h); cudaGetSymbolAddress((void**)&ob_l, g_ob_l);
    cudaGetSymbolAddress((void**)&qh, g_qh); cudaGetSymbolAddress((void**)&ql, g_ql);
    cudaGetSymbolAddress((void**)&kh, g_kh);
    cudaGetSymbolAddress((void**)&vth, g_vth);

    cudaFuncSetAttribute(gemm_mma, cudaFuncAttributeMaxDynamicSharedMemorySize, GSMEM_B);
    cudaFuncSetAttribute(flash_mma, cudaFuncAttributeMaxDynamicSharedMemorySize, FSMEM_B);

    const int M = B_ * S_;   // 4096

    // conversions
    cvt_wqkv<<<(WQKV_ELEMS / 4 + 255) / 256, 256>>>(Wq, Wk, Wv, wqkv_h);
    split_kernel<<<(HS_ELEMS / 4 + 255) / 256, 256>>>(hs, hs_h, hs_l, HS_ELEMS);

    // fused QKV projection: correction only for Q columns (< KOFF)
    gemm_mma<<<dim3(NQKV / BN, M / BM), 256, GSMEM_B>>>(
        hs_h, hs_l, wqkv_h, qkv, M, NQKV, HID_, KOFF);

    cvt_hi<<<(WO_ELEMS / 4 + 255) / 256, 256>>>(Wo, wo_h, WO_ELEMS);

    // RoPE + split (Q hi+lo, K hi); V transpose+convert
    {
        int totq = B_ * S_ * NH_ * 64;
        rope_split<<<(totq + 255) / 256, 256>>>(qkv, 0, cosp, sinp, qh, ql, 1, NH_, totq);
        int totk = B_ * S_ * NKV_ * 64;
        rope_split<<<(totk + 255) / 256, 256>>>(qkv, KOFF, cosp, sinp, kh, nullptr, 0, NKV_, totk);
        cvtT_v<<<(KV_ELEMS + 255) / 256, 256>>>(qkv, vth);
    }

    // flash attention
    flash_mma<<<dim3(S_ / 64, NH_, B_), 128, FSMEM_B>>>(qh, ql, kh, vth, ob_h, ob_l);

    // O projection: full correction everywhere
    gemm_mma<<<dim3(HID_ / BN, M / BM), 256, GSMEM_B>>>(
        ob_h, ob_l, wo_h, out, M, HID_, NH_ * HD_, HID_);
}

// round 13
// speedup vs baseline: 1.7700x; 1.0003x over previous
#include <cuda_runtime.h>
#include <cuda_fp16.h>
#include <cstdint>

// Problem constants
#define B_   2
#define S_   2048
#define HID_ 4096
#define NH_  32
#define NKV_ 8
#define HD_  128
#define NREP_ 4
#define SCALING_ 0.08838834764831843f   // 128^-0.5

#define NQKV 6144      // 4096 (Q) + 1024 (K) + 1024 (V)
#define KOFF 4096
#define VOFF 5120

// fp32 scratch: fused QKV GEMM output [B*S][NQKV]
__device__ float g_qkv[(size_t)B_ * S_ * NQKV];

// fp16 planes
#define HS_ELEMS   ((size_t)B_ * S_ * HID_)
#define WQKV_ELEMS ((size_t)NQKV * HID_)
#define WO_ELEMS   ((size_t)HID_ * NH_ * HD_)
#define KV_ELEMS   ((size_t)B_ * S_ * NKV_ * HD_)
__device__ __half g_hs_h[HS_ELEMS], g_hs_l[HS_ELEMS];
__device__ __half g_wqkv_h[WQKV_ELEMS];             // weights: hi only
__device__ __half g_wo_h[WO_ELEMS];                 // weights: hi only
__device__ __half g_ob_h[HS_ELEMS], g_ob_l[HS_ELEMS];
// attention planes (post-rope): Q hi+lo; K,V hi only
__device__ __half g_qh[HS_ELEMS], g_ql[HS_ELEMS];
__device__ __half g_kh[KV_ELEMS];
__device__ __half g_vth[KV_ELEMS];                  // [b][hk][d][s]

// ---------------------------------------------------------------------------
// helpers
// ---------------------------------------------------------------------------
static __device__ __forceinline__ uint32_t smem_u32(const void* p) {
    uint32_t a;
    asm("{ .reg .u64 t; cvta.to.shared.u64 t, %1; cvt.u32.u64 %0, t; }"
        : "=r"(a) : "l"(p));
    return a;
}
static __device__ __forceinline__ void cp16(uint32_t dst, const void* src) {
    asm volatile("cp.async.cg.shared.global [%0], [%1], 16;\n" :: "r"(dst), "l"(src));
}
__device__ __forceinline__ void mma16816(float c[4], uint32_t a0, uint32_t a1,
                                         uint32_t a2, uint32_t a3,
                                         uint32_t b0, uint32_t b1) {
    asm volatile(
        "mma.sync.aligned.m16n8k16.row.col.f32.f16.f16.f32 "
        "{%0,%1,%2,%3}, {%4,%5,%6,%7}, {%8,%9}, {%0,%1,%2,%3};\n"
        : "+f"(c[0]), "+f"(c[1]), "+f"(c[2]), "+f"(c[3])
        : "r"(a0), "r"(a1), "r"(a2), "r"(a3), "r"(b0), "r"(b1));
}
__device__ __forceinline__ void mma16816h(uint32_t& c0, uint32_t& c1,
                                          uint32_t a0, uint32_t a1,
                                          uint32_t a2, uint32_t a3,
                                          uint32_t b0, uint32_t b1) {
    asm volatile(
        "mma.sync.aligned.m16n8k16.row.col.f16.f16.f16.f16 "
        "{%0,%1}, {%2,%3,%4,%5}, {%6,%7}, {%0,%1};\n"
        : "+r"(c0), "+r"(c1)
        : "r"(a0), "r"(a1), "r"(a2), "r"(a3), "r"(b0), "r"(b1));
}
__device__ __forceinline__ void ldsm4(uint32_t& r0, uint32_t& r1, uint32_t& r2,
                                      uint32_t& r3, const void* p) {
    uint32_t a = (uint32_t)__cvta_generic_to_shared(p);
    asm volatile("ldmatrix.sync.aligned.m8n8.x4.shared.b16 {%0,%1,%2,%3}, [%4];\n"
                 : "=r"(r0), "=r"(r1), "=r"(r2), "=r"(r3) : "r"(a));
}
static __device__ __forceinline__ uint32_t pk_h2(float lo, float hi) {
    __half2 t = __floats2half2_rn(lo, hi);
    return *reinterpret_cast<uint32_t*>(&t);
}
static __device__ __forceinline__ float h2lo(uint32_t u) {
    __half2 h = *reinterpret_cast<__half2*>(&u);
    return __half2float(__low2half(h));
}
static __device__ __forceinline__ float h2hi(uint32_t u) {
    __half2 h = *reinterpret_cast<__half2*>(&u);
    return __half2float(__high2half(h));
}
static __device__ __forceinline__ uint32_t h2scale(uint32_t u, float s) {
    __half2 h = *reinterpret_cast<__half2*>(&u);
    __half2 r = __hmul2(h, __float2half2_rn(s));
    return *reinterpret_cast<uint32_t*>(&r);
}

// ---------------------------------------------------------------------------
// conversion kernels
// ---------------------------------------------------------------------------
__global__ void split_kernel(const float* __restrict__ x,
                             __half* __restrict__ hi,
                             __half* __restrict__ lo, size_t n) {
    size_t i = ((size_t)blockIdx.x * blockDim.x + threadIdx.x) * 4;
    if (i >= n) return;
    float4 v = *(const float4*)(x + i);
    float f[4] = {v.x, v.y, v.z, v.w};
#pragma unroll
    for (int j = 0; j < 4; j++) {
        __half h = __float2half_rn(f[j]);
        hi[i + j] = h;
        lo[i + j] = __float2half_rn(f[j] - __half2float(h));
    }
}

__global__ void cvt_hi(const float* __restrict__ x, __half* __restrict__ hi, size_t n) {
    size_t i = ((size_t)blockIdx.x * blockDim.x + threadIdx.x) * 4;
    if (i >= n) return;
    float4 v = *(const float4*)(x + i);
    hi[i + 0] = __float2half_rn(v.x);
    hi[i + 1] = __float2half_rn(v.y);
    hi[i + 2] = __float2half_rn(v.z);
    hi[i + 3] = __float2half_rn(v.w);
}

__global__ void cvt_wqkv(const float* __restrict__ Wq,
                         const float* __restrict__ Wk,
                         const float* __restrict__ Wv,
                         __half* __restrict__ hi) {
    size_t i = ((size_t)blockIdx.x * blockDim.x + threadIdx.x) * 4;
    if (i >= WQKV_ELEMS) return;
    size_t row = i / HID_;
    const float* src;
    size_t off;
    if (row < (size_t)KOFF)      { src = Wq; off = i; }
    else if (row < (size_t)VOFF) { src = Wk; off = i - (size_t)KOFF * HID_; }
    else                         { src = Wv; off = i - (size_t)VOFF * HID_; }
    float4 v = *(const float4*)(src + off);
    hi[i + 0] = __float2half_rn(v.x);
    hi[i + 1] = __float2half_rn(v.y);
    hi[i + 2] = __float2half_rn(v.z);
    hi[i + 3] = __float2half_rn(v.w);
}

__global__ void rope_split(const float* __restrict__ x, int hoff,
                           const float* __restrict__ cosp,
                           const float* __restrict__ sinp,
                           __half* __restrict__ xh,
                           __half* __restrict__ xl, int write_lo,
                           int nheads, int total) {
    int idx = blockIdx.x * blockDim.x + threadIdx.x;
    if (idx >= total) return;
    int d  = idx & 63;
    int h  = (idx >> 6) % nheads;
    int bs = idx / (64 * nheads);
    const float* row = x + (size_t)bs * NQKV + hoff + (size_t)h * HD_;
    const float* c = cosp + (size_t)bs * HD_;
    const float* s = sinp + (size_t)bs * HD_;
    float x1 = row[d], x2 = row[d + 64];
    float y1 = x1 * c[d]      - x2 * s[d];
    float y2 = x2 * c[d + 64] + x1 * s[d + 64];
    size_t base = (size_t)bs * nheads * HD_ + (size_t)h * HD_;
    __half h1 = __float2half_rn(y1);
    __half h2 = __float2half_rn(y2);
    xh[base + d]      = h1;
    xh[base + d + 64] = h2;
    if (write_lo) {
        xl[base + d]      = __float2half_rn(y1 - __half2float(h1));
        xl[base + d + 64] = __float2half_rn(y2 - __half2float(h2));
    }
}

__global__ void cvtT_v(const float* __restrict__ v, __half* __restrict__ vh) {
    size_t idx = (size_t)blockIdx.x * blockDim.x + threadIdx.x;
    if (idx >= KV_ELEMS) return;
    int s  = idx & (S_ - 1);
    size_t r = idx >> 11;
    int d  = r & (HD_ - 1);  r >>= 7;
    int hk = r & (NKV_ - 1);
    int b  = (int)(r >> 3);
    float x = v[(size_t)(b * S_ + s) * NQKV + VOFF + hk * HD_ + d];
    vh[idx] = __float2half_rn(x);
}

// ---------------------------------------------------------------------------
// 2-plane fp16 NT GEMM: C = (Ah+Al) * Bh^T; Al correction skipped for
// output columns >= nlo. BK=32, 3-stage cp.async, one barrier per iter.
// 256 threads (2x4 warps), warp tile 64x32. smem 92160B -> 2 CTA/SM.
// ---------------------------------------------------------------------------
#define BM 128
#define BN 128
#define GK 32
#define GPAD 40
#define GPLANE 5120
#define GSTAGE 15360                  // 3 planes (Ah, Al, Bh)
#define GSMEM_B (3 * GSTAGE * 2)      // 92160 bytes
#define SWG 16

__global__ __launch_bounds__(256)
void gemm_mma(const __half* __restrict__ Ah, const __half* __restrict__ Al,
              const __half* __restrict__ Bh,
              float* __restrict__ C, int M, int N, int K, int nlo) {
    extern __shared__ __half gsm[];
    const uint32_t sb = smem_u32(gsm);

    const int tid = threadIdx.x;
    const int warp = tid >> 5, lane = tid & 31;
    const int g = lane >> 2, tg = lane & 3;
    const int warpM = warp >> 2, warpN = warp & 3;

    int bx, by;
    {
        int bid = blockIdx.y * gridDim.x + blockIdx.x;
        int per = SWG * gridDim.x;
        int grp = bid / per;
        int rem = bid - grp * per;
        by = grp * SWG + (rem & (SWG - 1));
        bx = rem >> 4;
    }
    const int bm = by * BM, bn = bx * BN;
    const bool use_lo = (bn < nlo);   // CTA-uniform

    const int a_r = lane & 15;
    const int a_k = (lane >> 4) * 8;
    const int b_r = lane & 7;
    const int b_n8 = ((lane >> 4) & 1) * 8;
    const int b_k8 = ((lane >> 3) & 1) * 8;

    float c[4][4][4];
#pragma unroll
    for (int mi = 0; mi < 4; mi++)
#pragma unroll
        for (int ni = 0; ni < 4; ni++)
#pragma unroll
            for (int j = 0; j < 4; j++) c[mi][ni][j] = 0.f;

    const int niter = K / GK;

    auto load_stage = [&](int s, int k0) {
        const uint32_t base = sb + (uint32_t)(s * GSTAGE) * 2;
#pragma unroll
        for (int i = 0; i < 2; i++) {
            int j = tid + (i << 8);
            int row = j >> 2, col = (j & 3) * 8;
            size_t ao = (size_t)(bm + row) * K + k0 + col;
            size_t bo = (size_t)(bn + row) * K + k0 + col;
            uint32_t off = (uint32_t)(row * GPAD + col) * 2;
            cp16(base + off, Ah + ao);
            if (use_lo) cp16(base + GPLANE * 2 + off, Al + ao);
            cp16(base + 2 * GPLANE * 2 + off, Bh + bo);
        }
        asm volatile("cp.async.commit_group;\n");
    };

    load_stage(0, 0);
    load_stage(1, GK);

    for (int i = 0; i < niter; i++) {
        if (i + 1 < niter) asm volatile("cp.async.wait_group 1;\n");
        else               asm volatile("cp.async.wait_group 0;\n");
        __syncthreads();
        if (i + 2 < niter) load_stage((i + 2) % 3, (i + 2) * GK);

        const int s = i % 3;
        const __half* Asm = gsm + (size_t)s * GSTAGE;
        const __half* Bsm = Asm + 2 * GPLANE;
#pragma unroll
        for (int kk = 0; kk < 2; kk++) {
            const int kb = kk * 16;
            uint32_t aH[4][4], aL[4][4], bH[4][2];
#pragma unroll
            for (int mi = 0; mi < 4; mi++) {
                int rb = warpM * 64 + mi * 16;
                ldsm4(aH[mi][0], aH[mi][1], aH[mi][2], aH[mi][3],
                      Asm + (size_t)(rb + a_r) * GPAD + kb + a_k);
                if (use_lo)
                    ldsm4(aL[mi][0], aL[mi][1], aL[mi][2], aL[mi][3],
                          Asm + GPLANE + (size_t)(rb + a_r) * GPAD + kb + a_k);
            }
#pragma unroll
            for (int np = 0; np < 2; np++) {
                int nb = warpN * 32 + np * 16;
                uint32_t r0, r1, r2, r3;
                ldsm4(r0, r1, r2, r3,
                      Bsm + (size_t)(nb + b_r + b_n8) * GPAD + kb + b_k8);
                bH[np * 2][0] = r0; bH[np * 2][1] = r1;
                bH[np * 2 + 1][0] = r2; bH[np * 2 + 1][1] = r3;
            }
            if (use_lo) {
#pragma unroll
                for (int mi = 0; mi < 4; mi++)
#pragma unroll
                    for (int ni = 0; ni < 4; ni++) {
                        mma16816(c[mi][ni], aH[mi][0], aH[mi][1], aH[mi][2], aH[mi][3],
                                 bH[ni][0], bH[ni][1]);
                        mma16816(c[mi][ni], aL[mi][0], aL[mi][1], aL[mi][2], aL[mi][3],
                                 bH[ni][0], bH[ni][1]);
                    }
            } else {
#pragma unroll
                for (int mi = 0; mi < 4; mi++)
#pragma unroll
                    for (int ni = 0; ni < 4; ni++)
                        mma16816(c[mi][ni], aH[mi][0], aH[mi][1], aH[mi][2], aH[mi][3],
                                 bH[ni][0], bH[ni][1]);
            }
        }
    }

#pragma unroll
    for (int mi = 0; mi < 4; mi++) {
        int r0 = bm + warpM * 64 + mi * 16 + g;
#pragma unroll
        for (int ni = 0; ni < 4; ni++) {
            int cc = bn + warpN * 32 + ni * 8 + 2 * tg;
            *(float2*)(C + (size_t)r0 * N + cc) = make_float2(c[mi][ni][0], c[mi][ni][1]);
            *(float2*)(C + (size_t)(r0 + 8) * N + cc) = make_float2(c[mi][ni][2], c[mi][ni][3]);
        }
    }
}

// ---------------------------------------------------------------------------
// Flash attention: S = (Qh+Ql)Kh^T, O = (Ph+Pl)Vh. Main f32-acc, lo-plane
// corrections f16-acc. 128 threads, 64 q rows, 64-key tiles.
// DOUBLE-BUFFERED KV with one-tile lookahead. smem 104KB -> 2 CTA/SM.
// ---------------------------------------------------------------------------
#define FQH 0
#define FQL 8704
#define FKV0 17408
#define FKVSZ 17920       // per buffer: K 8704 elems + V 9216 elems
#define FKo 0
#define FVo 8704
#define FSMEM_B 106496    // (17408 + 2*17920) * 2 bytes

__global__ __launch_bounds__(128)
void flash_mma(const __half* __restrict__ Qh, const __half* __restrict__ Ql,
               const __half* __restrict__ Kh, const __half* __restrict__ Vth,
               __half* __restrict__ Oh, __half* __restrict__ Ol) {
    extern __shared__ __half fsm[];
    const uint32_t sb = smem_u32(fsm);

    const int b = blockIdx.z, h = blockIdx.y, qt = blockIdx.x;
    const int qs = qt * 64, hk = h >> 2;
    const int tid = threadIdx.x;
    const int warp = tid >> 5, lane = tid & 31;
    const int g = lane >> 2, tg = lane & 3;

    const int a_r = lane & 15;
    const int a_k = (lane >> 4) * 8;
    const int b_r = lane & 7;
    const int b_n8 = ((lane >> 4) & 1) * 8;
    const int b_k8 = ((lane >> 3) & 1) * 8;

    // ---- load Q tile (hi+lo, once) ----
#pragma unroll
    for (int i = 0; i < 8; i++) {
        int j = tid + (i << 7);
        int row = j >> 4, kc = j & 15;
        uint32_t d = sb + (uint32_t)((row * 136 + kc * 8) * 2);
        size_t src = ((size_t)(b * S_ + qs + row) * NH_ + h) * HD_ + kc * 8;
        cp16(d + FQH * 2, Qh + src);
        cp16(d + FQL * 2, Ql + src);
    }
    asm volatile("cp.async.commit_group;\n");

    auto load_kv = [&](int buf, int ks) {
        const uint32_t kb = sb + (uint32_t)((FKV0 + buf * FKVSZ) * 2);
#pragma unroll
        for (int i = 0; i < 8; i++) {
            int jj = tid + (i << 7);
            int krow = jj >> 4, kkc = jj & 15;
            uint32_t dk = kb + (uint32_t)((FKo + krow * 136 + kkc * 8) * 2);
            size_t ksrc = ((size_t)(b * S_ + ks + krow) * NKV_ + hk) * HD_ + kkc * 8;
            cp16(dk, Kh + ksrc);
            int vd = jj >> 3, vc = jj & 7;
            uint32_t dv = kb + (uint32_t)((FVo + vd * 72 + vc * 8) * 2);
            size_t vsrc = ((size_t)(b * NKV_ + hk) * HD_ + vd) * S_ + ks + vc * 8;
            cp16(dv, Vth + vsrc);
        }
        asm volatile("cp.async.commit_group;\n");
    };

    load_kv(0, 0);

    float o[16][4];
    uint32_t ocorr[16][2];
#pragma unroll
    for (int nt = 0; nt < 16; nt++) {
#pragma unroll
        for (int j = 0; j < 4; j++) o[nt][j] = 0.f;
        ocorr[nt][0] = 0u; ocorr[nt][1] = 0u;
    }
    float m0 = -1e30f, m1 = -1e30f, l0 = 0.f, l1 = 0.f;

    const int qr0 = qs + warp * 16 + g;
    const int qr1 = qr0 + 8;
    const int ntiles = qt + 1;

    for (int j = 0; j < ntiles; j++) {
        const int ks = j * 64;
        // wait for kv(j) (and Q on the first iter); only kv(j) is outstanding here
        asm volatile("cp.async.wait_group 0;\n");
        __syncthreads();
        // prefetch kv(j+1) into the other buffer; overlaps compute of tile j.
        // Safe: the buffer being filled was consumed in iter j-1, and every
        // warp has passed that compute to reach the barrier above.
        if (j + 1 < ntiles) load_kv((j + 1) & 1, (j + 1) * 64);

        const __half* kvb = fsm + FKV0 + (j & 1) * FKVSZ;

        // ---- S = Q K^T ----
        float S4[8][4];
        uint32_t scorr[8][2];
#pragma unroll
        for (int nt = 0; nt < 8; nt++) {
#pragma unroll
            for (int cc = 0; cc < 4; cc++) S4[nt][cc] = 0.f;
            scorr[nt][0] = 0u; scorr[nt][1] = 0u;
        }

#pragma unroll
        for (int dk = 0; dk < 8; dk++) {
            uint32_t aH[4], aL[4];
            ldsm4(aH[0], aH[1], aH[2], aH[3],
                  fsm + FQH + (size_t)(warp * 16 + a_r) * 136 + dk * 16 + a_k);
            ldsm4(aL[0], aL[1], aL[2], aL[3],
                  fsm + FQL + (size_t)(warp * 16 + a_r) * 136 + dk * 16 + a_k);
#pragma unroll
            for (int np = 0; np < 4; np++) {
                int nb = np * 16;
                uint32_t h0, h1, h2, h3;
                ldsm4(h0, h1, h2, h3,
                      kvb + FKo + (size_t)(nb + b_r + b_n8) * 136 + dk * 16 + b_k8);
                mma16816(S4[2 * np],     aH[0], aH[1], aH[2], aH[3], h0, h1);
                mma16816(S4[2 * np + 1], aH[0], aH[1], aH[2], aH[3], h2, h3);
                mma16816h(scorr[2 * np][0],     scorr[2 * np][1],
                          aL[0], aL[1], aL[2], aL[3], h0, h1);
                mma16816h(scorr[2 * np + 1][0], scorr[2 * np + 1][1],
                          aL[0], aL[1], aL[2], aL[3], h2, h3);
            }
        }
#pragma unroll
        for (int nt = 0; nt < 8; nt++) {
            S4[nt][0] += h2lo(scorr[nt][0]);
            S4[nt][1] += h2hi(scorr[nt][0]);
            S4[nt][2] += h2lo(scorr[nt][1]);
            S4[nt][3] += h2hi(scorr[nt][1]);
        }

        // ---- scale + mask + online softmax ----
        float mx0 = -1e30f, mx1 = -1e30f;
        const bool diag = (j == ntiles - 1);
#pragma unroll
        for (int nt = 0; nt < 8; nt++) {
#pragma unroll
            for (int cc = 0; cc < 4; cc++) {
                float v = S4[nt][cc] * SCALING_;
                if (diag) {
                    int kcol = ks + nt * 8 + 2 * tg + (cc & 1);
                    int qr = (cc < 2) ? qr0 : qr1;
                    if (kcol > qr) v = -1e30f;
                }
                S4[nt][cc] = v;
                if (cc < 2) mx0 = fmaxf(mx0, v); else mx1 = fmaxf(mx1, v);
            }
        }
        mx0 = fmaxf(mx0, __shfl_xor_sync(0xffffffffu, mx0, 1));
        mx0 = fmaxf(mx0, __shfl_xor_sync(0xffffffffu, mx0, 2));
        mx1 = fmaxf(mx1, __shfl_xor_sync(0xffffffffu, mx1, 1));
        mx1 = fmaxf(mx1, __shfl_xor_sync(0xffffffffu, mx1, 2));
        const float mt0 = fmaxf(m0, mx0), mt1 = fmaxf(m1, mx1);
        const float sc0 = __expf(m0 - mt0), sc1 = __expf(m1 - mt1);
        m0 = mt0; m1 = mt1;

        float rs0 = 0.f, rs1 = 0.f;
#pragma unroll
        for (int nt = 0; nt < 8; nt++) {
            float p0 = __expf(S4[nt][0] - mt0);
            float p1 = __expf(S4[nt][1] - mt0);
            float p2 = __expf(S4[nt][2] - mt1);
            float p3 = __expf(S4[nt][3] - mt1);
            S4[nt][0] = p0; S4[nt][1] = p1; S4[nt][2] = p2; S4[nt][3] = p3;
            rs0 += p0 + p1; rs1 += p2 + p3;
        }
        rs0 += __shfl_xor_sync(0xffffffffu, rs0, 1);
        rs0 += __shfl_xor_sync(0xffffffffu, rs0, 2);
        rs1 += __shfl_xor_sync(0xffffffffu, rs1, 1);
        rs1 += __shfl_xor_sync(0xffffffffu, rs1, 2);
        l0 = l0 * sc0 + rs0;
        l1 = l1 * sc1 + rs1;
#pragma unroll
        for (int nt = 0; nt < 16; nt++) {
            o[nt][0] *= sc0; o[nt][1] *= sc0;
            o[nt][2] *= sc1; o[nt][3] *= sc1;
            ocorr[nt][0] = h2scale(ocorr[nt][0], sc0);
            ocorr[nt][1] = h2scale(ocorr[nt][1], sc1);
        }

        // ---- O += P V ----
#pragma unroll
        for (int kt = 0; kt < 4; kt++) {
            uint32_t aPh[4], aPl[4];
#pragma unroll
            for (int half = 0; half < 2; half++) {
                const float* sv = S4[2 * kt + half];
                uint32_t p01 = pk_h2(sv[0], sv[1]);
                uint32_t p23 = pk_h2(sv[2], sv[3]);
                float r0f = sv[0] - h2lo(p01);
                float r1f = sv[1] - h2hi(p01);
                float r2f = sv[2] - h2lo(p23);
                float r3f = sv[3] - h2hi(p23);
                aPh[0 + 2 * half] = p01;
                aPh[1 + 2 * half] = p23;
                aPl[0 + 2 * half] = pk_h2(r0f, r1f);
                aPl[1 + 2 * half] = pk_h2(r2f, r3f);
            }
#pragma unroll
            for (int np = 0; np < 8; np++) {
                int nb = np * 16;
                uint32_t h0, h1, h2, h3;
                ldsm4(h0, h1, h2, h3,
                      kvb + FVo + (size_t)(nb + b_r + b_n8) * 72 + kt * 16 + b_k8);
                mma16816(o[2 * np],     aPh[0], aPh[1], aPh[2], aPh[3], h0, h1);
                mma16816(o[2 * np + 1], aPh[0], aPh[1], aPh[2], aPh[3], h2, h3);
                mma16816h(ocorr[2 * np][0],     ocorr[2 * np][1],
                          aPl[0], aPl[1], aPl[2], aPl[3], h0, h1);
                mma16816h(ocorr[2 * np + 1][0], ocorr[2 * np + 1][1],
                          aPl[0], aPl[1], aPl[2], aPl[3], h2, h3);
            }
        }
    }

    // ---- writeback ----
    const float inv0 = 1.f / l0, inv1 = 1.f / l1;
    const size_t r0base = ((size_t)(b * S_ + qr0) * NH_ + h) * HD_;
    const size_t r1base = ((size_t)(b * S_ + qr1) * NH_ + h) * HD_;
#pragma unroll
    for (int nt = 0; nt < 16; nt++) {
        int cc = nt * 8 + 2 * tg;
        float v00 = (o[nt][0] + h2lo(ocorr[nt][0])) * inv0;
        float v01 = (o[nt][1] + h2hi(ocorr[nt][0])) * inv0;
        float v10 = (o[nt][2] + h2lo(ocorr[nt][1])) * inv1;
        float v11 = (o[nt][3] + h2hi(ocorr[nt][1])) * inv1;
        uint32_t h0p = pk_h2(v00, v01);
        uint32_t h1p = pk_h2(v10, v11);
        float e00 = v00 - h2lo(h0p);
        float e01 = v01 - h2hi(h0p);
        float e10 = v10 - h2lo(h1p);
        float e11 = v11 - h2hi(h1p);
        *(uint32_t*)(Oh + r0base + cc) = h0p;
        *(uint32_t*)(Ol + r0base + cc) = pk_h2(e00, e01);
        *(uint32_t*)(Oh + r1base + cc) = h1p;
        *(uint32_t*)(Ol + r1base + cc) = pk_h2(e10, e11);
    }
}

// ---------------------------------------------------------------------------
// Launch
// ---------------------------------------------------------------------------
extern "C" void kernel_launch(void* const* d_in, const int* in_sizes, int n_in,
                              void* d_out, int out_size) {
    const float* hs   = (const float*)d_in[0];
    const float* cosp = (const float*)d_in[1];
    const float* sinp = (const float*)d_in[2];
    const float* Wq   = (const float*)d_in[4];
    const float* Wk   = (const float*)d_in[5];
    const float* Wv   = (const float*)d_in[6];
    const float* Wo   = (const float*)d_in[7];
    float* out = (float*)d_out;

    float* qkv;
    cudaGetSymbolAddress((void**)&qkv, g_qkv);

    __half *hs_h, *hs_l, *wqkv_h, *wo_h, *ob_h, *ob_l, *qh, *ql, *kh, *vth;
    cudaGetSymbolAddress((void**)&hs_h, g_hs_h); cudaGetSymbolAddress((void**)&hs_l, g_hs_l);
    cudaGetSymbolAddress((void**)&wqkv_h, g_wqkv_h);
    cudaGetSymbolAddress((void**)&wo_h, g_wo_h);
    cudaGetSymbolAddress((void**)&ob_h, g_ob_h); cudaGetSymbolAddress((void**)&ob_l, g_ob_l);
    cudaGetSymbolAddress((void**)&qh, g_qh); cudaGetSymbolAddress((void**)&ql, g_ql);
    cudaGetSymbolAddress((void**)&kh, g_kh);
    cudaGetSymbolAddress((void**)&vth, g_vth);

    cudaFuncSetAttribute(gemm_mma, cudaFuncAttributeMaxDynamicSharedMemorySize, GSMEM_B);
    cudaFuncSetAttribute(flash_mma, cudaFuncAttributeMaxDynamicSharedMemorySize, FSMEM_B);

    const int M = B_ * S_;   // 4096

    // conversions
    cvt_wqkv<<<(WQKV_ELEMS / 4 + 255) / 256, 256>>>(Wq, Wk, Wv, wqkv_h);
    split_kernel<<<(HS_ELEMS / 4 + 255) / 256, 256>>>(hs, hs_h, hs_l, HS_ELEMS);

    // fused QKV projection: correction only for Q columns (< KOFF)
    gemm_mma<<<dim3(NQKV / BN, M / BM), 256, GSMEM_B>>>(
        hs_h, hs_l, wqkv_h, qkv, M, NQKV, HID_, KOFF);

    cvt_hi<<<(WO_ELEMS / 4 + 255) / 256, 256>>>(Wo, wo_h, WO_ELEMS);

    // RoPE + split (Q hi+lo, K hi); V transpose+convert
    {
        int totq = B_ * S_ * NH_ * 64;
        rope_split<<<(totq + 255) / 256, 256>>>(qkv, 0, cosp, sinp, qh, ql, 1, NH_, totq);
        int totk = B_ * S_ * NKV_ * 64;
        rope_split<<<(totk + 255) / 256, 256>>>(qkv, KOFF, cosp, sinp, kh, nullptr, 0, NKV_, totk);
        cvtT_v<<<(KV_ELEMS + 255) / 256, 256>>>(qkv, vth);
    }

    // flash attention (double-buffered KV)
    flash_mma<<<dim3(S_ / 64, NH_, B_), 128, FSMEM_B>>>(qh, ql, kh, vth, ob_h, ob_l);

    // O projection: full correction everywhere
    gemm_mma<<<dim3(HID_ / BN, M / BM), 256, GSMEM_B>>>(
        ob_h, ob_l, wo_h, out, M, HID_, NH_ * HD_, HID_);
}

// round 14
// speedup vs baseline: 1.9935x; 1.1262x over previous
#include <cuda_runtime.h>
#include <cuda_fp16.h>
#include <cstdint>

// Problem constants
#define B_   2
#define S_   2048
#define HID_ 4096
#define NH_  32
#define NKV_ 8
#define HD_  128
#define NREP_ 4
#define SCALING_ 0.08838834764831843f   // 128^-0.5

#define NQKV 6144      // 4096 (Q) + 1024 (K) + 1024 (V)
#define KOFF 4096
#define VOFF 5120

// fp32 scratch: fused QKV GEMM output [B*S][NQKV]
__device__ float g_qkv[(size_t)B_ * S_ * NQKV];

// fp16 planes
#define HS_ELEMS   ((size_t)B_ * S_ * HID_)
#define WQKV_ELEMS ((size_t)NQKV * HID_)
#define WO_ELEMS   ((size_t)HID_ * NH_ * HD_)
#define KV_ELEMS   ((size_t)B_ * S_ * NKV_ * HD_)
__device__ __half g_hs_h[HS_ELEMS];                 // hidden states: hi only now
__device__ __half g_wqkv_h[WQKV_ELEMS];             // weights: hi only
__device__ __half g_wo_h[WO_ELEMS];                 // weights: hi only
__device__ __half g_ob_h[HS_ELEMS], g_ob_l[HS_ELEMS];
// attention planes (post-rope): Q hi+lo; K,V hi only
__device__ __half g_qh[HS_ELEMS], g_ql[HS_ELEMS];
__device__ __half g_kh[KV_ELEMS];
__device__ __half g_vth[KV_ELEMS];                  // [b][hk][d][s]

// ---------------------------------------------------------------------------
// helpers
// ---------------------------------------------------------------------------
static __device__ __forceinline__ uint32_t smem_u32(const void* p) {
    uint32_t a;
    asm("{ .reg .u64 t; cvta.to.shared.u64 t, %1; cvt.u32.u64 %0, t; }"
        : "=r"(a) : "l"(p));
    return a;
}
static __device__ __forceinline__ void cp16(uint32_t dst, const void* src) {
    asm volatile("cp.async.cg.shared.global [%0], [%1], 16;\n" :: "r"(dst), "l"(src));
}
__device__ __forceinline__ void mma16816(float c[4], uint32_t a0, uint32_t a1,
                                         uint32_t a2, uint32_t a3,
                                         uint32_t b0, uint32_t b1) {
    asm volatile(
        "mma.sync.aligned.m16n8k16.row.col.f32.f16.f16.f32 "
        "{%0,%1,%2,%3}, {%4,%5,%6,%7}, {%8,%9}, {%0,%1,%2,%3};\n"
        : "+f"(c[0]), "+f"(c[1]), "+f"(c[2]), "+f"(c[3])
        : "r"(a0), "r"(a1), "r"(a2), "r"(a3), "r"(b0), "r"(b1));
}
__device__ __forceinline__ void mma16816h(uint32_t& c0, uint32_t& c1,
                                          uint32_t a0, uint32_t a1,
                                          uint32_t a2, uint32_t a3,
                                          uint32_t b0, uint32_t b1) {
    asm volatile(
        "mma.sync.aligned.m16n8k16.row.col.f16.f16.f16.f16 "
        "{%0,%1}, {%2,%3,%4,%5}, {%6,%7}, {%0,%1};\n"
        : "+r"(c0), "+r"(c1)
        : "r"(a0), "r"(a1), "r"(a2), "r"(a3), "r"(b0), "r"(b1));
}
__device__ __forceinline__ void ldsm4(uint32_t& r0, uint32_t& r1, uint32_t& r2,
                                      uint32_t& r3, const void* p) {
    uint32_t a = (uint32_t)__cvta_generic_to_shared(p);
    asm volatile("ldmatrix.sync.aligned.m8n8.x4.shared.b16 {%0,%1,%2,%3}, [%4];\n"
                 : "=r"(r0), "=r"(r1), "=r"(r2), "=r"(r3) : "r"(a));
}
static __device__ __forceinline__ uint32_t pk_h2(float lo, float hi) {
    __half2 t = __floats2half2_rn(lo, hi);
    return *reinterpret_cast<uint32_t*>(&t);
}
static __device__ __forceinline__ float h2lo(uint32_t u) {
    __half2 h = *reinterpret_cast<__half2*>(&u);
    return __half2float(__low2half(h));
}
static __device__ __forceinline__ float h2hi(uint32_t u) {
    __half2 h = *reinterpret_cast<__half2*>(&u);
    return __half2float(__high2half(h));
}
static __device__ __forceinline__ uint32_t h2scale(uint32_t u, float s) {
    __half2 h = *reinterpret_cast<__half2*>(&u);
    __half2 r = __hmul2(h, __float2half2_rn(s));
    return *reinterpret_cast<uint32_t*>(&r);
}

// ---------------------------------------------------------------------------
// conversion kernels
// ---------------------------------------------------------------------------
__global__ void split_kernel(const float* __restrict__ x,
                             __half* __restrict__ hi,
                             __half* __restrict__ lo, size_t n) {
    size_t i = ((size_t)blockIdx.x * blockDim.x + threadIdx.x) * 4;
    if (i >= n) return;
    float4 v = *(const float4*)(x + i);
    float f[4] = {v.x, v.y, v.z, v.w};
#pragma unroll
    for (int j = 0; j < 4; j++) {
        __half h = __float2half_rn(f[j]);
        hi[i + j] = h;
        lo[i + j] = __float2half_rn(f[j] - __half2float(h));
    }
}

__global__ void cvt_hi(const float* __restrict__ x, __half* __restrict__ hi, size_t n) {
    size_t i = ((size_t)blockIdx.x * blockDim.x + threadIdx.x) * 4;
    if (i >= n) return;
    float4 v = *(const float4*)(x + i);
    hi[i + 0] = __float2half_rn(v.x);
    hi[i + 1] = __float2half_rn(v.y);
    hi[i + 2] = __float2half_rn(v.z);
    hi[i + 3] = __float2half_rn(v.w);
}

__global__ void cvt_wqkv(const float* __restrict__ Wq,
                         const float* __restrict__ Wk,
                         const float* __restrict__ Wv,
                         __half* __restrict__ hi) {
    size_t i = ((size_t)blockIdx.x * blockDim.x + threadIdx.x) * 4;
    if (i >= WQKV_ELEMS) return;
    size_t row = i / HID_;
    const float* src;
    size_t off;
    if (row < (size_t)KOFF)      { src = Wq; off = i; }
    else if (row < (size_t)VOFF) { src = Wk; off = i - (size_t)KOFF * HID_; }
    else                         { src = Wv; off = i - (size_t)VOFF * HID_; }
    float4 v = *(const float4*)(src + off);
    hi[i + 0] = __float2half_rn(v.x);
    hi[i + 1] = __float2half_rn(v.y);
    hi[i + 2] = __float2half_rn(v.z);
    hi[i + 3] = __float2half_rn(v.w);
}

__global__ void rope_split(const float* __restrict__ x, int hoff,
                           const float* __restrict__ cosp,
                           const float* __restrict__ sinp,
                           __half* __restrict__ xh,
                           __half* __restrict__ xl, int write_lo,
                           int nheads, int total) {
    int idx = blockIdx.x * blockDim.x + threadIdx.x;
    if (idx >= total) return;
    int d  = idx & 63;
    int h  = (idx >> 6) % nheads;
    int bs = idx / (64 * nheads);
    const float* row = x + (size_t)bs * NQKV + hoff + (size_t)h * HD_;
    const float* c = cosp + (size_t)bs * HD_;
    const float* s = sinp + (size_t)bs * HD_;
    float x1 = row[d], x2 = row[d + 64];
    float y1 = x1 * c[d]      - x2 * s[d];
    float y2 = x2 * c[d + 64] + x1 * s[d + 64];
    size_t base = (size_t)bs * nheads * HD_ + (size_t)h * HD_;
    __half h1 = __float2half_rn(y1);
    __half h2 = __float2half_rn(y2);
    xh[base + d]      = h1;
    xh[base + d + 64] = h2;
    if (write_lo) {
        xl[base + d]      = __float2half_rn(y1 - __half2float(h1));
        xl[base + d + 64] = __float2half_rn(y2 - __half2float(h2));
    }
}

__global__ void cvtT_v(const float* __restrict__ v, __half* __restrict__ vh) {
    size_t idx = (size_t)blockIdx.x * blockDim.x + threadIdx.x;
    if (idx >= KV_ELEMS) return;
    int s  = idx & (S_ - 1);
    size_t r = idx >> 11;
    int d  = r & (HD_ - 1);  r >>= 7;
    int hk = r & (NKV_ - 1);
    int b  = (int)(r >> 3);
    float x = v[(size_t)(b * S_ + s) * NQKV + VOFF + hk * HD_ + d];
    vh[idx] = __float2half_rn(x);
}

// ---------------------------------------------------------------------------
// 2-plane fp16 NT GEMM: C = (Ah+Al) * Bh^T; Al correction applied only for
// output columns < nlo (nlo=0 -> pure fp16-hi GEMM).
// BK=32, 3-stage cp.async, one barrier per iter.
// 256 threads (2x4 warps), warp tile 64x32. smem 92160B -> 2 CTA/SM.
// ---------------------------------------------------------------------------
#define BM 128
#define BN 128
#define GK 32
#define GPAD 40
#define GPLANE 5120
#define GSTAGE 15360                  // 3 planes (Ah, Al, Bh)
#define GSMEM_B (3 * GSTAGE * 2)      // 92160 bytes
#define SWG 16

__global__ __launch_bounds__(256)
void gemm_mma(const __half* __restrict__ Ah, const __half* __restrict__ Al,
              const __half* __restrict__ Bh,
              float* __restrict__ C, int M, int N, int K, int nlo) {
    extern __shared__ __half gsm[];
    const uint32_t sb = smem_u32(gsm);

    const int tid = threadIdx.x;
    const int warp = tid >> 5, lane = tid & 31;
    const int g = lane >> 2, tg = lane & 3;
    const int warpM = warp >> 2, warpN = warp & 3;

    int bx, by;
    {
        int bid = blockIdx.y * gridDim.x + blockIdx.x;
        int per = SWG * gridDim.x;
        int grp = bid / per;
        int rem = bid - grp * per;
        by = grp * SWG + (rem & (SWG - 1));
        bx = rem >> 4;
    }
    const int bm = by * BM, bn = bx * BN;
    const bool use_lo = (bn < nlo);   // CTA-uniform

    const int a_r = lane & 15;
    const int a_k = (lane >> 4) * 8;
    const int b_r = lane & 7;
    const int b_n8 = ((lane >> 4) & 1) * 8;
    const int b_k8 = ((lane >> 3) & 1) * 8;

    float c[4][4][4];
#pragma unroll
    for (int mi = 0; mi < 4; mi++)
#pragma unroll
        for (int ni = 0; ni < 4; ni++)
#pragma unroll
            for (int j = 0; j < 4; j++) c[mi][ni][j] = 0.f;

    const int niter = K / GK;

    auto load_stage = [&](int s, int k0) {
        const uint32_t base = sb + (uint32_t)(s * GSTAGE) * 2;
#pragma unroll
        for (int i = 0; i < 2; i++) {
            int j = tid + (i << 8);
            int row = j >> 2, col = (j & 3) * 8;
            size_t ao = (size_t)(bm + row) * K + k0 + col;
            size_t bo = (size_t)(bn + row) * K + k0 + col;
            uint32_t off = (uint32_t)(row * GPAD + col) * 2;
            cp16(base + off, Ah + ao);
            if (use_lo) cp16(base + GPLANE * 2 + off, Al + ao);
            cp16(base + 2 * GPLANE * 2 + off, Bh + bo);
        }
        asm volatile("cp.async.commit_group;\n");
    };

    load_stage(0, 0);
    load_stage(1, GK);

    for (int i = 0; i < niter; i++) {
        if (i + 1 < niter) asm volatile("cp.async.wait_group 1;\n");
        else               asm volatile("cp.async.wait_group 0;\n");
        __syncthreads();
        if (i + 2 < niter) load_stage((i + 2) % 3, (i + 2) * GK);

        const int s = i % 3;
        const __half* Asm = gsm + (size_t)s * GSTAGE;
        const __half* Bsm = Asm + 2 * GPLANE;
#pragma unroll
        for (int kk = 0; kk < 2; kk++) {
            const int kb = kk * 16;
            uint32_t aH[4][4], aL[4][4], bH[4][2];
#pragma unroll
            for (int mi = 0; mi < 4; mi++) {
                int rb = warpM * 64 + mi * 16;
                ldsm4(aH[mi][0], aH[mi][1], aH[mi][2], aH[mi][3],
                      Asm + (size_t)(rb + a_r) * GPAD + kb + a_k);
                if (use_lo)
                    ldsm4(aL[mi][0], aL[mi][1], aL[mi][2], aL[mi][3],
                          Asm + GPLANE + (size_t)(rb + a_r) * GPAD + kb + a_k);
            }
#pragma unroll
            for (int np = 0; np < 2; np++) {
                int nb = warpN * 32 + np * 16;
                uint32_t r0, r1, r2, r3;
                ldsm4(r0, r1, r2, r3,
                      Bsm + (size_t)(nb + b_r + b_n8) * GPAD + kb + b_k8);
                bH[np * 2][0] = r0; bH[np * 2][1] = r1;
                bH[np * 2 + 1][0] = r2; bH[np * 2 + 1][1] = r3;
            }
            if (use_lo) {
#pragma unroll
                for (int mi = 0; mi < 4; mi++)
#pragma unroll
                    for (int ni = 0; ni < 4; ni++) {
                        mma16816(c[mi][ni], aH[mi][0], aH[mi][1], aH[mi][2], aH[mi][3],
                                 bH[ni][0], bH[ni][1]);
                        mma16816(c[mi][ni], aL[mi][0], aL[mi][1], aL[mi][2], aL[mi][3],
                                 bH[ni][0], bH[ni][1]);
                    }
            } else {
#pragma unroll
                for (int mi = 0; mi < 4; mi++)
#pragma unroll
                    for (int ni = 0; ni < 4; ni++)
                        mma16816(c[mi][ni], aH[mi][0], aH[mi][1], aH[mi][2], aH[mi][3],
                                 bH[ni][0], bH[ni][1]);
            }
        }
    }

#pragma unroll
    for (int mi = 0; mi < 4; mi++) {
        int r0 = bm + warpM * 64 + mi * 16 + g;
#pragma unroll
        for (int ni = 0; ni < 4; ni++) {
            int cc = bn + warpN * 32 + ni * 8 + 2 * tg;
            *(float2*)(C + (size_t)r0 * N + cc) = make_float2(c[mi][ni][0], c[mi][ni][1]);
            *(float2*)(C + (size_t)(r0 + 8) * N + cc) = make_float2(c[mi][ni][2], c[mi][ni][3]);
        }
    }
}

// ---------------------------------------------------------------------------
// Flash attention: S = (Qh+Ql)Kh^T, O = (Ph+Pl)Vh. Main f32-acc, lo-plane
// corrections f16-acc. 128 threads, 64 q rows, 64-key tiles.
// Double-buffered KV. smem 104KB -> 2 CTA/SM.
// ---------------------------------------------------------------------------
#define FQH 0
#define FQL 8704
#define FKV0 17408
#define FKVSZ 17920       // per buffer: K 8704 elems + V 9216 elems
#define FKo 0
#define FVo 8704
#define FSMEM_B 106496

__global__ __launch_bounds__(128)
void flash_mma(const __half* __restrict__ Qh, const __half* __restrict__ Ql,
               const __half* __restrict__ Kh, const __half* __restrict__ Vth,
               __half* __restrict__ Oh, __half* __restrict__ Ol) {
    extern __shared__ __half fsm[];
    const uint32_t sb = smem_u32(fsm);

    const int b = blockIdx.z, h = blockIdx.y, qt = blockIdx.x;
    const int qs = qt * 64, hk = h >> 2;
    const int tid = threadIdx.x;
    const int warp = tid >> 5, lane = tid & 31;
    const int g = lane >> 2, tg = lane & 3;

    const int a_r = lane & 15;
    const int a_k = (lane >> 4) * 8;
    const int b_r = lane & 7;
    const int b_n8 = ((lane >> 4) & 1) * 8;
    const int b_k8 = ((lane >> 3) & 1) * 8;

    // ---- load Q tile (hi+lo, once) ----
#pragma unroll
    for (int i = 0; i < 8; i++) {
        int j = tid + (i << 7);
        int row = j >> 4, kc = j & 15;
        uint32_t d = sb + (uint32_t)((row * 136 + kc * 8) * 2);
        size_t src = ((size_t)(b * S_ + qs + row) * NH_ + h) * HD_ + kc * 8;
        cp16(d + FQH * 2, Qh + src);
        cp16(d + FQL * 2, Ql + src);
    }
    asm volatile("cp.async.commit_group;\n");

    auto load_kv = [&](int buf, int ks) {
        const uint32_t kb = sb + (uint32_t)((FKV0 + buf * FKVSZ) * 2);
#pragma unroll
        for (int i = 0; i < 8; i++) {
            int jj = tid + (i << 7);
            int krow = jj >> 4, kkc = jj & 15;
            uint32_t dk = kb + (uint32_t)((FKo + krow * 136 + kkc * 8) * 2);
            size_t ksrc = ((size_t)(b * S_ + ks + krow) * NKV_ + hk) * HD_ + kkc * 8;
            cp16(dk, Kh + ksrc);
            int vd = jj >> 3, vc = jj & 7;
            uint32_t dv = kb + (uint32_t)((FVo + vd * 72 + vc * 8) * 2);
            size_t vsrc = ((size_t)(b * NKV_ + hk) * HD_ + vd) * S_ + ks + vc * 8;
            cp16(dv, Vth + vsrc);
        }
        asm volatile("cp.async.commit_group;\n");
    };

    load_kv(0, 0);

    float o[16][4];
    uint32_t ocorr[16][2];
#pragma unroll
    for (int nt = 0; nt < 16; nt++) {
#pragma unroll
        for (int j = 0; j < 4; j++) o[nt][j] = 0.f;
        ocorr[nt][0] = 0u; ocorr[nt][1] = 0u;
    }
    float m0 = -1e30f, m1 = -1e30f, l0 = 0.f, l1 = 0.f;

    const int qr0 = qs + warp * 16 + g;
    const int qr1 = qr0 + 8;
    const int ntiles = qt + 1;

    for (int j = 0; j < ntiles; j++) {
        const int ks = j * 64;
        asm volatile("cp.async.wait_group 0;\n");
        __syncthreads();
        if (j + 1 < ntiles) load_kv((j + 1) & 1, (j + 1) * 64);

        const __half* kvb = fsm + FKV0 + (j & 1) * FKVSZ;

        // ---- S = Q K^T ----
        float S4[8][4];
        uint32_t scorr[8][2];
#pragma unroll
        for (int nt = 0; nt < 8; nt++) {
#pragma unroll
            for (int cc = 0; cc < 4; cc++) S4[nt][cc] = 0.f;
            scorr[nt][0] = 0u; scorr[nt][1] = 0u;
        }

#pragma unroll
        for (int dk = 0; dk < 8; dk++) {
            uint32_t aH[4], aL[4];
            ldsm4(aH[0], aH[1], aH[2], aH[3],
                  fsm + FQH + (size_t)(warp * 16 + a_r) * 136 + dk * 16 + a_k);
            ldsm4(aL[0], aL[1], aL[2], aL[3],
                  fsm + FQL + (size_t)(warp * 16 + a_r) * 136 + dk * 16 + a_k);
#pragma unroll
            for (int np = 0; np < 4; np++) {
                int nb = np * 16;
                uint32_t h0, h1, h2, h3;
                ldsm4(h0, h1, h2, h3,
                      kvb + FKo + (size_t)(nb + b_r + b_n8) * 136 + dk * 16 + b_k8);
                mma16816(S4[2 * np],     aH[0], aH[1], aH[2], aH[3], h0, h1);
                mma16816(S4[2 * np + 1], aH[0], aH[1], aH[2], aH[3], h2, h3);
                mma16816h(scorr[2 * np][0],     scorr[2 * np][1],
                          aL[0], aL[1], aL[2], aL[3], h0, h1);
                mma16816h(scorr[2 * np + 1][0], scorr[2 * np + 1][1],
                          aL[0], aL[1], aL[2], aL[3], h2, h3);
            }
        }
#pragma unroll
        for (int nt = 0; nt < 8; nt++) {
            S4[nt][0] += h2lo(scorr[nt][0]);
            S4[nt][1] += h2hi(scorr[nt][0]);
            S4[nt][2] += h2lo(scorr[nt][1]);
            S4[nt][3] += h2hi(scorr[nt][1]);
        }

        // ---- scale + mask + online softmax ----
        float mx0 = -1e30f, mx1 = -1e30f;
        const bool diag = (j == ntiles - 1);
#pragma unroll
        for (int nt = 0; nt < 8; nt++) {
#pragma unroll
            for (int cc = 0; cc < 4; cc++) {
                float v = S4[nt][cc] * SCALING_;
                if (diag) {
                    int kcol = ks + nt * 8 + 2 * tg + (cc & 1);
                    int qr = (cc < 2) ? qr0 : qr1;
                    if (kcol > qr) v = -1e30f;
                }
                S4[nt][cc] = v;
                if (cc < 2) mx0 = fmaxf(mx0, v); else mx1 = fmaxf(mx1, v);
            }
        }
        mx0 = fmaxf(mx0, __shfl_xor_sync(0xffffffffu, mx0, 1));
        mx0 = fmaxf(mx0, __shfl_xor_sync(0xffffffffu, mx0, 2));
        mx1 = fmaxf(mx1, __shfl_xor_sync(0xffffffffu, mx1, 1));
        mx1 = fmaxf(mx1, __shfl_xor_sync(0xffffffffu, mx1, 2));
        const float mt0 = fmaxf(m0, mx0), mt1 = fmaxf(m1, mx1);
        const float sc0 = __expf(m0 - mt0), sc1 = __expf(m1 - mt1);
        m0 = mt0; m1 = mt1;

        float rs0 = 0.f, rs1 = 0.f;
#pragma unroll
        for (int nt = 0; nt < 8; nt++) {
            float p0 = __expf(S4[nt][0] - mt0);
            float p1 = __expf(S4[nt][1] - mt0);
            float p2 = __expf(S4[nt][2] - mt1);
            float p3 = __expf(S4[nt][3] - mt1);
            S4[nt][0] = p0; S4[nt][1] = p1; S4[nt][2] = p2; S4[nt][3] = p3;
            rs0 += p0 + p1; rs1 += p2 + p3;
        }
        rs0 += __shfl_xor_sync(0xffffffffu, rs0, 1);
        rs0 += __shfl_xor_sync(0xffffffffu, rs0, 2);
        rs1 += __shfl_xor_sync(0xffffffffu, rs1, 1);
        rs1 += __shfl_xor_sync(0xffffffffu, rs1, 2);
        l0 = l0 * sc0 + rs0;
        l1 = l1 * sc1 + rs1;
#pragma unroll
        for (int nt = 0; nt < 16; nt++) {
            o[nt][0] *= sc0; o[nt][1] *= sc0;
            o[nt][2] *= sc1; o[nt][3] *= sc1;
            ocorr[nt][0] = h2scale(ocorr[nt][0], sc0);
            ocorr[nt][1] = h2scale(ocorr[nt][1], sc1);
        }

        // ---- O += P V ----
#pragma unroll
        for (int kt = 0; kt < 4; kt++) {
            uint32_t aPh[4], aPl[4];
#pragma unroll
            for (int half = 0; half < 2; half++) {
                const float* sv = S4[2 * kt + half];
                uint32_t p01 = pk_h2(sv[0], sv[1]);
                uint32_t p23 = pk_h2(sv[2], sv[3]);
                float r0f = sv[0] - h2lo(p01);
                float r1f = sv[1] - h2hi(p01);
                float r2f = sv[2] - h2lo(p23);
                float r3f = sv[3] - h2hi(p23);
                aPh[0 + 2 * half] = p01;
                aPh[1 + 2 * half] = p23;
                aPl[0 + 2 * half] = pk_h2(r0f, r1f);
                aPl[1 + 2 * half] = pk_h2(r2f, r3f);
            }
#pragma unroll
            for (int np = 0; np < 8; np++) {
                int nb = np * 16;
                uint32_t h0, h1, h2, h3;
                ldsm4(h0, h1, h2, h3,
                      kvb + FVo + (size_t)(nb + b_r + b_n8) * 72 + kt * 16 + b_k8);
                mma16816(o[2 * np],     aPh[0], aPh[1], aPh[2], aPh[3], h0, h1);
                mma16816(o[2 * np + 1], aPh[0], aPh[1], aPh[2], aPh[3], h2, h3);
                mma16816h(ocorr[2 * np][0],     ocorr[2 * np][1],
                          aPl[0], aPl[1], aPl[2], aPl[3], h0, h1);
                mma16816h(ocorr[2 * np + 1][0], ocorr[2 * np + 1][1],
                          aPl[0], aPl[1], aPl[2], aPl[3], h2, h3);
            }
        }
    }

    // ---- writeback ----
    const float inv0 = 1.f / l0, inv1 = 1.f / l1;
    const size_t r0base = ((size_t)(b * S_ + qr0) * NH_ + h) * HD_;
    const size_t r1base = ((size_t)(b * S_ + qr1) * NH_ + h) * HD_;
#pragma unroll
    for (int nt = 0; nt < 16; nt++) {
        int cc = nt * 8 + 2 * tg;
        float v00 = (o[nt][0] + h2lo(ocorr[nt][0])) * inv0;
        float v01 = (o[nt][1] + h2hi(ocorr[nt][0])) * inv0;
        float v10 = (o[nt][2] + h2lo(ocorr[nt][1])) * inv1;
        float v11 = (o[nt][3] + h2hi(ocorr[nt][1])) * inv1;
        uint32_t h0p = pk_h2(v00, v01);
        uint32_t h1p = pk_h2(v10, v11);
        float e00 = v00 - h2lo(h0p);
        float e01 = v01 - h2hi(h0p);
        float e10 = v10 - h2lo(h1p);
        float e11 = v11 - h2hi(h1p);
        *(uint32_t*)(Oh + r0base + cc) = h0p;
        *(uint32_t*)(Ol + r0base + cc) = pk_h2(e00, e01);
        *(uint32_t*)(Oh + r1base + cc) = h1p;
        *(uint32_t*)(Ol + r1base + cc) = pk_h2(e10, e11);
    }
}

// ---------------------------------------------------------------------------
// Launch
// ---------------------------------------------------------------------------
extern "C" void kernel_launch(void* const* d_in, const int* in_sizes, int n_in,
                              void* d_out, int out_size) {
    const float* hs   = (const float*)d_in[0];
    const float* cosp = (const float*)d_in[1];
    const float* sinp = (const float*)d_in[2];
    const float* Wq   = (const float*)d_in[4];
    const float* Wk   = (const float*)d_in[5];
    const float* Wv   = (const float*)d_in[6];
    const float* Wo   = (const float*)d_in[7];
    float* out = (float*)d_out;

    float* qkv;
    cudaGetSymbolAddress((void**)&qkv, g_qkv);

    __half *hs_h, *wqkv_h, *wo_h, *ob_h, *ob_l, *qh, *ql, *kh, *vth;
    cudaGetSymbolAddress((void**)&hs_h, g_hs_h);
    cudaGetSymbolAddress((void**)&wqkv_h, g_wqkv_h);
    cudaGetSymbolAddress((void**)&wo_h, g_wo_h);
    cudaGetSymbolAddress((void**)&ob_h, g_ob_h); cudaGetSymbolAddress((void**)&ob_l, g_ob_l);
    cudaGetSymbolAddress((void**)&qh, g_qh); cudaGetSymbolAddress((void**)&ql, g_ql);
    cudaGetSymbolAddress((void**)&kh, g_kh);
    cudaGetSymbolAddress((void**)&vth, g_vth);

    cudaFuncSetAttribute(gemm_mma, cudaFuncAttributeMaxDynamicSharedMemorySize, GSMEM_B);
    cudaFuncSetAttribute(flash_mma, cudaFuncAttributeMaxDynamicSharedMemorySize, FSMEM_B);

    const int M = B_ * S_;   // 4096

    // conversions (hidden states now hi-only)
    cvt_wqkv<<<(WQKV_ELEMS / 4 + 255) / 256, 256>>>(Wq, Wk, Wv, wqkv_h);
    cvt_hi<<<(HS_ELEMS / 4 + 255) / 256, 256>>>(hs, hs_h, HS_ELEMS);

    // fused QKV projection: pure fp16-hi (nlo = 0)
    gemm_mma<<<dim3(NQKV / BN, M / BM), 256, GSMEM_B>>>(
        hs_h, hs_h, wqkv_h, qkv, M, NQKV, HID_, 0);

    cvt_hi<<<(WO_ELEMS / 4 + 255) / 256, 256>>>(Wo, wo_h, WO_ELEMS);

    // RoPE + split (Q hi+lo, K hi); V transpose+convert
    {
        int totq = B_ * S_ * NH_ * 64;
        rope_split<<<(totq + 255) / 256, 256>>>(qkv, 0, cosp, sinp, qh, ql, 1, NH_, totq);
        int totk = B_ * S_ * NKV_ * 64;
        rope_split<<<(totk + 255) / 256, 256>>>(qkv, KOFF, cosp, sinp, kh, nullptr, 0, NKV_, totk);
        cvtT_v<<<(KV_ELEMS + 255) / 256, 256>>>(qkv, vth);
    }

    // flash attention (double-buffered KV)
    flash_mma<<<dim3(S_ / 64, NH_, B_), 128, FSMEM_B>>>(qh, ql, kh, vth, ob_h, ob_l);

    // O projection: full correction (ob hi+lo)
    gemm_mma<<<dim3(HID_ / BN, M / BM), 256, GSMEM_B>>>(
        ob_h, ob_l, wo_h, out, M, HID_, NH_ * HD_, HID_);
}

// round 15
// speedup vs baseline: 2.0453x; 1.0260x over previous
#include <cuda_runtime.h>
#include <cuda_fp16.h>
#include <cstdint>

// Problem constants
#define B_   2
#define S_   2048
#define HID_ 4096
#define NH_  32
#define NKV_ 8
#define HD_  128
#define NREP_ 4
#define SCALING_ 0.08838834764831843f   // 128^-0.5

#define NQKV 6144      // 4096 (Q) + 1024 (K) + 1024 (V)
#define KOFF 4096
#define VOFF 5120

// fp16 planes
#define HS_ELEMS   ((size_t)B_ * S_ * HID_)
#define WQKV_ELEMS ((size_t)NQKV * HID_)
#define WO_ELEMS   ((size_t)HID_ * NH_ * HD_)
#define KV_ELEMS   ((size_t)B_ * S_ * NKV_ * HD_)
__device__ __half g_hs_h[HS_ELEMS];                 // hidden states: hi only
__device__ __half g_wqkv_h[WQKV_ELEMS];             // weights: hi only
__device__ __half g_wo_h[WO_ELEMS];                 // weights: hi only
__device__ __half g_ob_h[HS_ELEMS], g_ob_l[HS_ELEMS];
// attention planes (post-rope): Q hi+lo; K,V hi only
__device__ __half g_qh[HS_ELEMS], g_ql[HS_ELEMS];
__device__ __half g_kh[KV_ELEMS];
__device__ __half g_vth[KV_ELEMS];                  // [b][hk][d][s]

// ---------------------------------------------------------------------------
// helpers
// ---------------------------------------------------------------------------
static __device__ __forceinline__ uint32_t smem_u32(const void* p) {
    uint32_t a;
    asm("{ .reg .u64 t; cvta.to.shared.u64 t, %1; cvt.u32.u64 %0, t; }"
        : "=r"(a) : "l"(p));
    return a;
}
static __device__ __forceinline__ void cp16(uint32_t dst, const void* src) {
    asm volatile("cp.async.cg.shared.global [%0], [%1], 16;\n" :: "r"(dst), "l"(src));
}
__device__ __forceinline__ void mma16816(float c[4], uint32_t a0, uint32_t a1,
                                         uint32_t a2, uint32_t a3,
                                         uint32_t b0, uint32_t b1) {
    asm volatile(
        "mma.sync.aligned.m16n8k16.row.col.f32.f16.f16.f32 "
        "{%0,%1,%2,%3}, {%4,%5,%6,%7}, {%8,%9}, {%0,%1,%2,%3};\n"
        : "+f"(c[0]), "+f"(c[1]), "+f"(c[2]), "+f"(c[3])
        : "r"(a0), "r"(a1), "r"(a2), "r"(a3), "r"(b0), "r"(b1));
}
__device__ __forceinline__ void mma16816h(uint32_t& c0, uint32_t& c1,
                                          uint32_t a0, uint32_t a1,
                                          uint32_t a2, uint32_t a3,
                                          uint32_t b0, uint32_t b1) {
    asm volatile(
        "mma.sync.aligned.m16n8k16.row.col.f16.f16.f16.f16 "
        "{%0,%1}, {%2,%3,%4,%5}, {%6,%7}, {%0,%1};\n"
        : "+r"(c0), "+r"(c1)
        : "r"(a0), "r"(a1), "r"(a2), "r"(a3), "r"(b0), "r"(b1));
}
__device__ __forceinline__ void ldsm4(uint32_t& r0, uint32_t& r1, uint32_t& r2,
                                      uint32_t& r3, const void* p) {
    uint32_t a = (uint32_t)__cvta_generic_to_shared(p);
    asm volatile("ldmatrix.sync.aligned.m8n8.x4.shared.b16 {%0,%1,%2,%3}, [%4];\n"
                 : "=r"(r0), "=r"(r1), "=r"(r2), "=r"(r3) : "r"(a));
}
static __device__ __forceinline__ uint32_t pk_h2(float lo, float hi) {
    __half2 t = __floats2half2_rn(lo, hi);
    return *reinterpret_cast<uint32_t*>(&t);
}
static __device__ __forceinline__ float h2lo(uint32_t u) {
    __half2 h = *reinterpret_cast<__half2*>(&u);
    return __half2float(__low2half(h));
}
static __device__ __forceinline__ float h2hi(uint32_t u) {
    __half2 h = *reinterpret_cast<__half2*>(&u);
    return __half2float(__high2half(h));
}
static __device__ __forceinline__ uint32_t h2scale(uint32_t u, float s) {
    __half2 h = *reinterpret_cast<__half2*>(&u);
    __half2 r = __hmul2(h, __float2half2_rn(s));
    return *reinterpret_cast<uint32_t*>(&r);
}

// ---------------------------------------------------------------------------
// conversion kernels
// ---------------------------------------------------------------------------
__global__ void cvt_hi(const float* __restrict__ x, __half* __restrict__ hi, size_t n) {
    size_t i = ((size_t)blockIdx.x * blockDim.x + threadIdx.x) * 4;
    if (i >= n) return;
    float4 v = *(const float4*)(x + i);
    hi[i + 0] = __float2half_rn(v.x);
    hi[i + 1] = __float2half_rn(v.y);
    hi[i + 2] = __float2half_rn(v.z);
    hi[i + 3] = __float2half_rn(v.w);
}

__global__ void cvt_wqkv(const float* __restrict__ Wq,
                         const float* __restrict__ Wk,
                         const float* __restrict__ Wv,
                         __half* __restrict__ hi) {
    size_t i = ((size_t)blockIdx.x * blockDim.x + threadIdx.x) * 4;
    if (i >= WQKV_ELEMS) return;
    size_t row = i / HID_;
    const float* src;
    size_t off;
    if (row < (size_t)KOFF)      { src = Wq; off = i; }
    else if (row < (size_t)VOFF) { src = Wk; off = i - (size_t)KOFF * HID_; }
    else                         { src = Wv; off = i - (size_t)VOFF * HID_; }
    float4 v = *(const float4*)(src + off);
    hi[i + 0] = __float2half_rn(v.x);
    hi[i + 1] = __float2half_rn(v.y);
    hi[i + 2] = __float2half_rn(v.z);
    hi[i + 3] = __float2half_rn(v.w);
}

// ---------------------------------------------------------------------------
// QKV GEMM with FUSED rope/split/transpose epilogue.
// Pure fp16-hi mainloop (Ah * Bh^T), fp32 accumulate. BN = 128 = HD, so each
// CTA's column tile is exactly one head; RoPE pairs (d, d+64) are CTA-local.
// Epilogue: stage fp32 tile to smem (stride 129, conflict-free), then
//   Q cols: rope -> qh + ql planes; K cols: rope -> kh; V cols: transpose -> vth.
// BK=32, 3-stage cp.async, one barrier per iter. smem 92160B -> 2 CTA/SM.
// ---------------------------------------------------------------------------
#define BM 128
#define BN 128
#define GK 32
#define GPAD 40
#define GPLANE 5120
#define GSTAGE 15360
#define GSMEM_B (3 * GSTAGE * 2)      // 92160 bytes (also covers 128x129 fp32 tile)
#define SWG 16

__global__ __launch_bounds__(256)
void gemm_qkv(const __half* __restrict__ Ah, const __half* __restrict__ Bh,
              const float* __restrict__ cosp, const float* __restrict__ sinp,
              __half* __restrict__ Qhp, __half* __restrict__ Qlp,
              __half* __restrict__ Khp, __half* __restrict__ Vtp) {
    extern __shared__ __half gsm[];
    const uint32_t sb = smem_u32(gsm);
    const int K = HID_;

    const int tid = threadIdx.x;
    const int warp = tid >> 5, lane = tid & 31;
    const int g = lane >> 2, tg = lane & 3;
    const int warpM = warp >> 2, warpN = warp & 3;

    int bx, by;
    {
        int bid = blockIdx.y * gridDim.x + blockIdx.x;
        int per = SWG * gridDim.x;
        int grp = bid / per;
        int rem = bid - grp * per;
        by = grp * SWG + (rem & (SWG - 1));
        bx = rem >> 4;
    }
    const int bm = by * BM, bn = bx * BN;

    const int a_r = lane & 15;
    const int a_k = (lane >> 4) * 8;
    const int b_r = lane & 7;
    const int b_n8 = ((lane >> 4) & 1) * 8;
    const int b_k8 = ((lane >> 3) & 1) * 8;

    float c[4][4][4];
#pragma unroll
    for (int mi = 0; mi < 4; mi++)
#pragma unroll
        for (int ni = 0; ni < 4; ni++)
#pragma unroll
            for (int j = 0; j < 4; j++) c[mi][ni][j] = 0.f;

    const int niter = K / GK;

    auto load_stage = [&](int s, int k0) {
        const uint32_t base = sb + (uint32_t)(s * GSTAGE) * 2;
#pragma unroll
        for (int i = 0; i < 2; i++) {
            int j = tid + (i << 8);
            int row = j >> 2, col = (j & 3) * 8;
            size_t ao = (size_t)(bm + row) * K + k0 + col;
            size_t bo = (size_t)(bn + row) * K + k0 + col;
            uint32_t off = (uint32_t)(row * GPAD + col) * 2;
            cp16(base + off, Ah + ao);
            cp16(base + 2 * GPLANE * 2 + off, Bh + bo);
        }
        asm volatile("cp.async.commit_group;\n");
    };

    load_stage(0, 0);
    load_stage(1, GK);

    for (int i = 0; i < niter; i++) {
        if (i + 1 < niter) asm volatile("cp.async.wait_group 1;\n");
        else               asm volatile("cp.async.wait_group 0;\n");
        __syncthreads();
        if (i + 2 < niter) load_stage((i + 2) % 3, (i + 2) * GK);

        const int s = i % 3;
        const __half* Asm = gsm + (size_t)s * GSTAGE;
        const __half* Bsm = Asm + 2 * GPLANE;
#pragma unroll
        for (int kk = 0; kk < 2; kk++) {
            const int kb = kk * 16;
            uint32_t aH[4][4], bH[4][2];
#pragma unroll
            for (int mi = 0; mi < 4; mi++) {
                int rb = warpM * 64 + mi * 16;
                ldsm4(aH[mi][0], aH[mi][1], aH[mi][2], aH[mi][3],
                      Asm + (size_t)(rb + a_r) * GPAD + kb + a_k);
            }
#pragma unroll
            for (int np = 0; np < 2; np++) {
                int nb = warpN * 32 + np * 16;
                uint32_t r0, r1, r2, r3;
                ldsm4(r0, r1, r2, r3,
                      Bsm + (size_t)(nb + b_r + b_n8) * GPAD + kb + b_k8);
                bH[np * 2][0] = r0; bH[np * 2][1] = r1;
                bH[np * 2 + 1][0] = r2; bH[np * 2 + 1][1] = r3;
            }
#pragma unroll
            for (int mi = 0; mi < 4; mi++)
#pragma unroll
                for (int ni = 0; ni < 4; ni++)
                    mma16816(c[mi][ni], aH[mi][0], aH[mi][1], aH[mi][2], aH[mi][3],
                             bH[ni][0], bH[ni][1]);
        }
    }

    // ---- fused epilogue ----
    __syncthreads();                       // main-loop smem reads complete
    float* tile = (float*)gsm;             // 128 x 128, stride 129 (66048 B)
#pragma unroll
    for (int mi = 0; mi < 4; mi++) {
        int r0 = warpM * 64 + mi * 16 + g;
#pragma unroll
        for (int ni = 0; ni < 4; ni++) {
            int cc = warpN * 32 + ni * 8 + 2 * tg;
            tile[r0 * 129 + cc]           = c[mi][ni][0];
            tile[r0 * 129 + cc + 1]       = c[mi][ni][1];
            tile[(r0 + 8) * 129 + cc]     = c[mi][ni][2];
            tile[(r0 + 8) * 129 + cc + 1] = c[mi][ni][3];
        }
    }
    __syncthreads();

    if (bn < KOFF) {
        // Q: rope + hi/lo split
        const int h = bn >> 7;
#pragma unroll 4
        for (int it = 0; it < 32; it++) {
            int idx = tid + (it << 8);
            int row = idx >> 6, d = idx & 63;
            int tok = bm + row;
            float x1 = tile[row * 129 + d];
            float x2 = tile[row * 129 + d + 64];
            float cd  = cosp[(size_t)tok * HD_ + d];
            float sd  = sinp[(size_t)tok * HD_ + d];
            float cd2 = cosp[(size_t)tok * HD_ + d + 64];
            float sd2 = sinp[(size_t)tok * HD_ + d + 64];
            float y1 = x1 * cd  - x2 * sd;
            float y2 = x2 * cd2 + x1 * sd2;
            size_t base = ((size_t)tok * NH_ + h) * HD_;
            __half h1 = __float2half_rn(y1);
            __half h2 = __float2half_rn(y2);
            Qhp[base + d]      = h1;
            Qhp[base + d + 64] = h2;
            Qlp[base + d]      = __float2half_rn(y1 - __half2float(h1));
            Qlp[base + d + 64] = __float2half_rn(y2 - __half2float(h2));
        }
    } else if (bn < VOFF) {
        // K: rope, hi only
        const int hk = (bn - KOFF) >> 7;
#pragma unroll 4
        for (int it = 0; it < 32; it++) {
            int idx = tid + (it << 8);
            int row = idx >> 6, d = idx & 63;
            int tok = bm + row;
            float x1 = tile[row * 129 + d];
            float x2 = tile[row * 129 + d + 64];
            float cd  = cosp[(size_t)tok * HD_ + d];
            float sd  = sinp[(size_t)tok * HD_ + d];
            float cd2 = cosp[(size_t)tok * HD_ + d + 64];
            float sd2 = sinp[(size_t)tok * HD_ + d + 64];
            float y1 = x1 * cd  - x2 * sd;
            float y2 = x2 * cd2 + x1 * sd2;
            size_t base = ((size_t)tok * NKV_ + hk) * HD_;
            Khp[base + d]      = __float2half_rn(y1);
            Khp[base + d + 64] = __float2half_rn(y2);
        }
    } else {
        // V: transpose -> [b][hk][d][s], hi only. Coalesced along s.
        const int hk = (bn - VOFF) >> 7;
        const int s_loc = tid & 127, halfsel = tid >> 7;
        const int bb = bm >> 11;                 // bm / S_
        const int s = (bm & (S_ - 1)) + s_loc;
#pragma unroll 8
        for (int dd = 0; dd < 64; dd++) {
            int d = halfsel * 64 + dd;
            float x = tile[s_loc * 129 + d];
            Vtp[(((size_t)(bb * NKV_ + hk)) * HD_ + d) * S_ + s] = __float2half_rn(x);
        }
    }
}

// ---------------------------------------------------------------------------
// Generic 2-plane fp16 NT GEMM (used for O projection): C = (Ah+Al) * Bh^T.
// BK=32, 3-stage cp.async, one barrier per iter. smem 92160B -> 2 CTA/SM.
// ---------------------------------------------------------------------------
__global__ __launch_bounds__(256)
void gemm_mma(const __half* __restrict__ Ah, const __half* __restrict__ Al,
              const __half* __restrict__ Bh,
              float* __restrict__ C, int M, int N, int K) {
    extern __shared__ __half gsm[];
    const uint32_t sb = smem_u32(gsm);

    const int tid = threadIdx.x;
    const int warp = tid >> 5, lane = tid & 31;
    const int g = lane >> 2, tg = lane & 3;
    const int warpM = warp >> 2, warpN = warp & 3;

    int bx, by;
    {
        int bid = blockIdx.y * gridDim.x + blockIdx.x;
        int per = SWG * gridDim.x;
        int grp = bid / per;
        int rem = bid - grp * per;
        by = grp * SWG + (rem & (SWG - 1));
        bx = rem >> 4;
    }
    const int bm = by * BM, bn = bx * BN;

    const int a_r = lane & 15;
    const int a_k = (lane >> 4) * 8;
    const int b_r = lane & 7;
    const int b_n8 = ((lane >> 4) & 1) * 8;
    const int b_k8 = ((lane >> 3) & 1) * 8;

    float c[4][4][4];
#pragma unroll
    for (int mi = 0; mi < 4; mi++)
#pragma unroll
        for (int ni = 0; ni < 4; ni++)
#pragma unroll
            for (int j = 0; j < 4; j++) c[mi][ni][j] = 0.f;

    const int niter = K / GK;

    auto load_stage = [&](int s, int k0) {
        const uint32_t base = sb + (uint32_t)(s * GSTAGE) * 2;
#pragma unroll
        for (int i = 0; i < 2; i++) {
            int j = tid + (i << 8);
            int row = j >> 2, col = (j & 3) * 8;
            size_t ao = (size_t)(bm + row) * K + k0 + col;
            size_t bo = (size_t)(bn + row) * K + k0 + col;
            uint32_t off = (uint32_t)(row * GPAD + col) * 2;
            cp16(base + off, Ah + ao);
            cp16(base + GPLANE * 2 + off, Al + ao);
            cp16(base + 2 * GPLANE * 2 + off, Bh + bo);
        }
        asm volatile("cp.async.commit_group;\n");
    };

    load_stage(0, 0);
    load_stage(1, GK);

    for (int i = 0; i < niter; i++) {
        if (i + 1 < niter) asm volatile("cp.async.wait_group 1;\n");
        else               asm volatile("cp.async.wait_group 0;\n");
        __syncthreads();
        if (i + 2 < niter) load_stage((i + 2) % 3, (i + 2) * GK);

        const int s = i % 3;
        const __half* Asm = gsm + (size_t)s * GSTAGE;
        const __half* Bsm = Asm + 2 * GPLANE;
#pragma unroll
        for (int kk = 0; kk < 2; kk++) {
            const int kb = kk * 16;
            uint32_t aH[4][4], aL[4][4], bH[4][2];
#pragma unroll
            for (int mi = 0; mi < 4; mi++) {
                int rb = warpM * 64 + mi * 16;
                ldsm4(aH[mi][0], aH[mi][1], aH[mi][2], aH[mi][3],
                      Asm + (size_t)(rb + a_r) * GPAD + kb + a_k);
                ldsm4(aL[mi][0], aL[mi][1], aL[mi][2], aL[mi][3],
                      Asm + GPLANE + (size_t)(rb + a_r) * GPAD + kb + a_k);
            }
#pragma unroll
            for (int np = 0; np < 2; np++) {
                int nb = warpN * 32 + np * 16;
                uint32_t r0, r1, r2, r3;
                ldsm4(r0, r1, r2, r3,
                      Bsm + (size_t)(nb + b_r + b_n8) * GPAD + kb + b_k8);
                bH[np * 2][0] = r0; bH[np * 2][1] = r1;
                bH[np * 2 + 1][0] = r2; bH[np * 2 + 1][1] = r3;
            }
#pragma unroll
            for (int mi = 0; mi < 4; mi++)
#pragma unroll
                for (int ni = 0; ni < 4; ni++) {
                    mma16816(c[mi][ni], aH[mi][0], aH[mi][1], aH[mi][2], aH[mi][3],
                             bH[ni][0], bH[ni][1]);
                    mma16816(c[mi][ni], aL[mi][0], aL[mi][1], aL[mi][2], aL[mi][3],
                             bH[ni][0], bH[ni][1]);
                }
        }
    }

#pragma unroll
    for (int mi = 0; mi < 4; mi++) {
        int r0 = bm + warpM * 64 + mi * 16 + g;
#pragma unroll
        for (int ni = 0; ni < 4; ni++) {
            int cc = bn + warpN * 32 + ni * 8 + 2 * tg;
            *(float2*)(C + (size_t)r0 * N + cc) = make_float2(c[mi][ni][0], c[mi][ni][1]);
            *(float2*)(C + (size_t)(r0 + 8) * N + cc) = make_float2(c[mi][ni][2], c[mi][ni][3]);
        }
    }
}

// ---------------------------------------------------------------------------
// Flash attention: S = (Qh+Ql)Kh^T, O = (Ph+Pl)Vh. Main f32-acc, lo-plane
// corrections f16-acc. 128 threads, 64 q rows, 64-key tiles.
// Double-buffered KV. smem 104KB -> 2 CTA/SM.
// ---------------------------------------------------------------------------
#define FQH 0
#define FQL 8704
#define FKV0 17408
#define FKVSZ 17920
#define FKo 0
#define FVo 8704
#define FSMEM_B 106496

__global__ __launch_bounds__(128)
void flash_mma(const __half* __restrict__ Qh, const __half* __restrict__ Ql,
               const __half* __restrict__ Kh, const __half* __restrict__ Vth,
               __half* __restrict__ Oh, __half* __restrict__ Ol) {
    extern __shared__ __half fsm[];
    const uint32_t sb = smem_u32(fsm);

    const int b = blockIdx.z, h = blockIdx.y, qt = blockIdx.x;
    const int qs = qt * 64, hk = h >> 2;
    const int tid = threadIdx.x;
    const int warp = tid >> 5, lane = tid & 31;
    const int g = lane >> 2, tg = lane & 3;

    const int a_r = lane & 15;
    const int a_k = (lane >> 4) * 8;
    const int b_r = lane & 7;
    const int b_n8 = ((lane >> 4) & 1) * 8;
    const int b_k8 = ((lane >> 3) & 1) * 8;

    // ---- load Q tile (hi+lo, once) ----
#pragma unroll
    for (int i = 0; i < 8; i++) {
        int j = tid + (i << 7);
        int row = j >> 4, kc = j & 15;
        uint32_t d = sb + (uint32_t)((row * 136 + kc * 8) * 2);
        size_t src = ((size_t)(b * S_ + qs + row) * NH_ + h) * HD_ + kc * 8;
        cp16(d + FQH * 2, Qh + src);
        cp16(d + FQL * 2, Ql + src);
    }
    asm volatile("cp.async.commit_group;\n");

    auto load_kv = [&](int buf, int ks) {
        const uint32_t kb = sb + (uint32_t)((FKV0 + buf * FKVSZ) * 2);
#pragma unroll
        for (int i = 0; i < 8; i++) {
            int jj = tid + (i << 7);
            int krow = jj >> 4, kkc = jj & 15;
            uint32_t dk = kb + (uint32_t)((FKo + krow * 136 + kkc * 8) * 2);
            size_t ksrc = ((size_t)(b * S_ + ks + krow) * NKV_ + hk) * HD_ + kkc * 8;
            cp16(dk, Kh + ksrc);
            int vd = jj >> 3, vc = jj & 7;
            uint32_t dv = kb + (uint32_t)((FVo + vd * 72 + vc * 8) * 2);
            size_t vsrc = ((size_t)(b * NKV_ + hk) * HD_ + vd) * S_ + ks + vc * 8;
            cp16(dv, Vth + vsrc);
        }
        asm volatile("cp.async.commit_group;\n");
    };

    load_kv(0, 0);

    float o[16][4];
    uint32_t ocorr[16][2];
#pragma unroll
    for (int nt = 0; nt < 16; nt++) {
#pragma unroll
        for (int j = 0; j < 4; j++) o[nt][j] = 0.f;
        ocorr[nt][0] = 0u; ocorr[nt][1] = 0u;
    }
    float m0 = -1e30f, m1 = -1e30f, l0 = 0.f, l1 = 0.f;

    const int qr0 = qs + warp * 16 + g;
    const int qr1 = qr0 + 8;
    const int ntiles = qt + 1;

    for (int j = 0; j < ntiles; j++) {
        const int ks = j * 64;
        asm volatile("cp.async.wait_group 0;\n");
        __syncthreads();
        if (j + 1 < ntiles) load_kv((j + 1) & 1, (j + 1) * 64);

        const __half* kvb = fsm + FKV0 + (j & 1) * FKVSZ;

        // ---- S = Q K^T ----
        float S4[8][4];
        uint32_t scorr[8][2];
#pragma unroll
        for (int nt = 0; nt < 8; nt++) {
#pragma unroll
            for (int cc = 0; cc < 4; cc++) S4[nt][cc] = 0.f;
            scorr[nt][0] = 0u; scorr[nt][1] = 0u;
        }

#pragma unroll
        for (int dk = 0; dk < 8; dk++) {
            uint32_t aH[4], aL[4];
            ldsm4(aH[0], aH[1], aH[2], aH[3],
                  fsm + FQH + (size_t)(warp * 16 + a_r) * 136 + dk * 16 + a_k);
            ldsm4(aL[0], aL[1], aL[2], aL[3],
                  fsm + FQL + (size_t)(warp * 16 + a_r) * 136 + dk * 16 + a_k);
#pragma unroll
            for (int np = 0; np < 4; np++) {
                int nb = np * 16;
                uint32_t h0, h1, h2, h3;
                ldsm4(h0, h1, h2, h3,
                      kvb + FKo + (size_t)(nb + b_r + b_n8) * 136 + dk * 16 + b_k8);
                mma16816(S4[2 * np],     aH[0], aH[1], aH[2], aH[3], h0, h1);
                mma16816(S4[2 * np + 1], aH[0], aH[1], aH[2], aH[3], h2, h3);
                mma16816h(scorr[2 * np][0],     scorr[2 * np][1],
                          aL[0], aL[1], aL[2], aL[3], h0, h1);
                mma16816h(scorr[2 * np + 1][0], scorr[2 * np + 1][1],
                          aL[0], aL[1], aL[2], aL[3], h2, h3);
            }
        }
#pragma unroll
        for (int nt = 0; nt < 8; nt++) {
            S4[nt][0] += h2lo(scorr[nt][0]);
            S4[nt][1] += h2hi(scorr[nt][0]);
            S4[nt][2] += h2lo(scorr[nt][1]);
            S4[nt][3] += h2hi(scorr[nt][1]);
        }

        // ---- scale + mask + online softmax ----
        float mx0 = -1e30f, mx1 = -1e30f;
        const bool diag = (j == ntiles - 1);
#pragma unroll
        for (int nt = 0; nt < 8; nt++) {
#pragma unroll
            for (int cc = 0; cc < 4; cc++) {
                float v = S4[nt][cc] * SCALING_;
                if (diag) {
                    int kcol = ks + nt * 8 + 2 * tg + (cc & 1);
                    int qr = (cc < 2) ? qr0 : qr1;
                    if (kcol > qr) v = -1e30f;
                }
                S4[nt][cc] = v;
                if (cc < 2) mx0 = fmaxf(mx0, v); else mx1 = fmaxf(mx1, v);
            }
        }
        mx0 = fmaxf(mx0, __shfl_xor_sync(0xffffffffu, mx0, 1));
        mx0 = fmaxf(mx0, __shfl_xor_sync(0xffffffffu, mx0, 2));
        mx1 = fmaxf(mx1, __shfl_xor_sync(0xffffffffu, mx1, 1));
        mx1 = fmaxf(mx1, __shfl_xor_sync(0xffffffffu, mx1, 2));
        const float mt0 = fmaxf(m0, mx0), mt1 = fmaxf(m1, mx1);
        const float sc0 = __expf(m0 - mt0), sc1 = __expf(m1 - mt1);
        m0 = mt0; m1 = mt1;

        float rs0 = 0.f, rs1 = 0.f;
#pragma unroll
        for (int nt = 0; nt < 8; nt++) {
            float p0 = __expf(S4[nt][0] - mt0);
            float p1 = __expf(S4[nt][1] - mt0);
            float p2 = __expf(S4[nt][2] - mt1);
            float p3 = __expf(S4[nt][3] - mt1);
            S4[nt][0] = p0; S4[nt][1] = p1; S4[nt][2] = p2; S4[nt][3] = p3;
            rs0 += p0 + p1; rs1 += p2 + p3;
        }
        rs0 += __shfl_xor_sync(0xffffffffu, rs0, 1);
        rs0 += __shfl_xor_sync(0xffffffffu, rs0, 2);
        rs1 += __shfl_xor_sync(0xffffffffu, rs1, 1);
        rs1 += __shfl_xor_sync(0xffffffffu, rs1, 2);
        l0 = l0 * sc0 + rs0;
        l1 = l1 * sc1 + rs1;
#pragma unroll
        for (int nt = 0; nt < 16; nt++) {
            o[nt][0] *= sc0; o[nt][1] *= sc0;
            o[nt][2] *= sc1; o[nt][3] *= sc1;
            ocorr[nt][0] = h2scale(ocorr[nt][0], sc0);
            ocorr[nt][1] = h2scale(ocorr[nt][1], sc1);
        }

        // ---- O += P V ----
#pragma unroll
        for (int kt = 0; kt < 4; kt++) {
            uint32_t aPh[4], aPl[4];
#pragma unroll
            for (int half = 0; half < 2; half++) {
                const float* sv = S4[2 * kt + half];
                uint32_t p01 = pk_h2(sv[0], sv[1]);
                uint32_t p23 = pk_h2(sv[2], sv[3]);
                float r0f = sv[0] - h2lo(p01);
                float r1f = sv[1] - h2hi(p01);
                float r2f = sv[2] - h2lo(p23);
                float r3f = sv[3] - h2hi(p23);
                aPh[0 + 2 * half] = p01;
                aPh[1 + 2 * half] = p23;
                aPl[0 + 2 * half] = pk_h2(r0f, r1f);
                aPl[1 + 2 * half] = pk_h2(r2f, r3f);
            }
#pragma unroll
            for (int np = 0; np < 8; np++) {
                int nb = np * 16;
                uint32_t h0, h1, h2, h3;
                ldsm4(h0, h1, h2, h3,
                      kvb + FVo + (size_t)(nb + b_r + b_n8) * 72 + kt * 16 + b_k8);
                mma16816(o[2 * np],     aPh[0], aPh[1], aPh[2], aPh[3], h0, h1);
                mma16816(o[2 * np + 1], aPh[0], aPh[1], aPh[2], aPh[3], h2, h3);
                mma16816h(ocorr[2 * np][0],     ocorr[2 * np][1],
                          aPl[0], aPl[1], aPl[2], aPl[3], h0, h1);
                mma16816h(ocorr[2 * np + 1][0], ocorr[2 * np + 1][1],
                          aPl[0], aPl[1], aPl[2], aPl[3], h2, h3);
            }
        }
    }

    // ---- writeback ----
    const float inv0 = 1.f / l0, inv1 = 1.f / l1;
    const size_t r0base = ((size_t)(b * S_ + qr0) * NH_ + h) * HD_;
    const size_t r1base = ((size_t)(b * S_ + qr1) * NH_ + h) * HD_;
#pragma unroll
    for (int nt = 0; nt < 16; nt++) {
        int cc = nt * 8 + 2 * tg;
        float v00 = (o[nt][0] + h2lo(ocorr[nt][0])) * inv0;
        float v01 = (o[nt][1] + h2hi(ocorr[nt][0])) * inv0;
        float v10 = (o[nt][2] + h2lo(ocorr[nt][1])) * inv1;
        float v11 = (o[nt][3] + h2hi(ocorr[nt][1])) * inv1;
        uint32_t h0p = pk_h2(v00, v01);
        uint32_t h1p = pk_h2(v10, v11);
        float e00 = v00 - h2lo(h0p);
        float e01 = v01 - h2hi(h0p);
        float e10 = v10 - h2lo(h1p);
        float e11 = v11 - h2hi(h1p);
        *(uint32_t*)(Oh + r0base + cc) = h0p;
        *(uint32_t*)(Ol + r0base + cc) = pk_h2(e00, e01);
        *(uint32_t*)(Oh + r1base + cc) = h1p;
        *(uint32_t*)(Ol + r1base + cc) = pk_h2(e10, e11);
    }
}

// ---------------------------------------------------------------------------
// Launch
// ---------------------------------------------------------------------------
extern "C" void kernel_launch(void* const* d_in, const int* in_sizes, int n_in,
                              void* d_out, int out_size) {
    const float* hs   = (const float*)d_in[0];
    const float* cosp = (const float*)d_in[1];
    const float* sinp = (const float*)d_in[2];
    const float* Wq   = (const float*)d_in[4];
    const float* Wk   = (const float*)d_in[5];
    const float* Wv   = (const float*)d_in[6];
    const float* Wo   = (const float*)d_in[7];
    float* out = (float*)d_out;

    __half *hs_h, *wqkv_h, *wo_h, *ob_h, *ob_l, *qh, *ql, *kh, *vth;
    cudaGetSymbolAddress((void**)&hs_h, g_hs_h);
    cudaGetSymbolAddress((void**)&wqkv_h, g_wqkv_h);
    cudaGetSymbolAddress((void**)&wo_h, g_wo_h);
    cudaGetSymbolAddress((void**)&ob_h, g_ob_h); cudaGetSymbolAddress((void**)&ob_l, g_ob_l);
    cudaGetSymbolAddress((void**)&qh, g_qh); cudaGetSymbolAddress((void**)&ql, g_ql);
    cudaGetSymbolAddress((void**)&kh, g_kh);
    cudaGetSymbolAddress((void**)&vth, g_vth);

    cudaFuncSetAttribute(gemm_qkv, cudaFuncAttributeMaxDynamicSharedMemorySize, GSMEM_B);
    cudaFuncSetAttribute(gemm_mma, cudaFuncAttributeMaxDynamicSharedMemorySize, GSMEM_B);
    cudaFuncSetAttribute(flash_mma, cudaFuncAttributeMaxDynamicSharedMemorySize, FSMEM_B);

    const int M = B_ * S_;   // 4096

    // conversions
    cvt_wqkv<<<(WQKV_ELEMS / 4 + 255) / 256, 256>>>(Wq, Wk, Wv, wqkv_h);
    cvt_hi<<<(HS_ELEMS / 4 + 255) / 256, 256>>>(hs, hs_h, HS_ELEMS);

    // fused QKV projection + rope/split/transpose epilogue
    gemm_qkv<<<dim3(NQKV / BN, M / BM), 256, GSMEM_B>>>(
        hs_h, wqkv_h, cosp, sinp, qh, ql, kh, vth);

    cvt_hi<<<(WO_ELEMS / 4 + 255) / 256, 256>>>(Wo, wo_h, WO_ELEMS);

    // flash attention (double-buffered KV)
    flash_mma<<<dim3(S_ / 64, NH_, B_), 128, FSMEM_B>>>(qh, ql, kh, vth, ob_h, ob_l);

    // O projection: full hi+lo correction
    gemm_mma<<<dim3(HID_ / BN, M / BM), 256, GSMEM_B>>>(
        ob_h, ob_l, wo_h, out, M, HID_, NH_ * HD_);
}

// round 16
// speedup vs baseline: 2.0489x; 1.0018x over previous
#include <cuda_runtime.h>
#include <cuda_fp16.h>
#include <cstdint>

// Problem constants
#define B_   2
#define S_   2048
#define HID_ 4096
#define NH_  32
#define NKV_ 8
#define HD_  128
#define NREP_ 4
#define SCALING_ 0.08838834764831843f   // 128^-0.5

#define NQKV 6144      // 4096 (Q) + 1024 (K) + 1024 (V)
#define KOFF 4096
#define VOFF 5120

// fp16 planes
#define HS_ELEMS   ((size_t)B_ * S_ * HID_)
#define WQKV_ELEMS ((size_t)NQKV * HID_)
#define WO_ELEMS   ((size_t)HID_ * NH_ * HD_)
#define KV_ELEMS   ((size_t)B_ * S_ * NKV_ * HD_)
__device__ __half g_hs_h[HS_ELEMS];                 // hidden states: hi only
__device__ __half g_wqkv_h[WQKV_ELEMS];             // weights: hi only
__device__ __half g_wo_h[WO_ELEMS];                 // weights: hi only
__device__ __half g_ob_h[HS_ELEMS], g_ob_l[HS_ELEMS];
// attention planes (post-rope): Q hi+lo; K,V hi only
__device__ __half g_qh[HS_ELEMS], g_ql[HS_ELEMS];
__device__ __half g_kh[KV_ELEMS];
__device__ __half g_vth[KV_ELEMS];                  // [b][hk][d][s]

// ---------------------------------------------------------------------------
// helpers
// ---------------------------------------------------------------------------
static __device__ __forceinline__ uint32_t smem_u32(const void* p) {
    uint32_t a;
    asm("{ .reg .u64 t; cvta.to.shared.u64 t, %1; cvt.u32.u64 %0, t; }"
        : "=r"(a) : "l"(p));
    return a;
}
static __device__ __forceinline__ void cp16(uint32_t dst, const void* src) {
    asm volatile("cp.async.cg.shared.global [%0], [%1], 16;\n" :: "r"(dst), "l"(src));
}
__device__ __forceinline__ void mma16816(float c[4], uint32_t a0, uint32_t a1,
                                         uint32_t a2, uint32_t a3,
                                         uint32_t b0, uint32_t b1) {
    asm volatile(
        "mma.sync.aligned.m16n8k16.row.col.f32.f16.f16.f32 "
        "{%0,%1,%2,%3}, {%4,%5,%6,%7}, {%8,%9}, {%0,%1,%2,%3};\n"
        : "+f"(c[0]), "+f"(c[1]), "+f"(c[2]), "+f"(c[3])
        : "r"(a0), "r"(a1), "r"(a2), "r"(a3), "r"(b0), "r"(b1));
}
__device__ __forceinline__ void mma16816h(uint32_t& c0, uint32_t& c1,
                                          uint32_t a0, uint32_t a1,
                                          uint32_t a2, uint32_t a3,
                                          uint32_t b0, uint32_t b1) {
    asm volatile(
        "mma.sync.aligned.m16n8k16.row.col.f16.f16.f16.f16 "
        "{%0,%1}, {%2,%3,%4,%5}, {%6,%7}, {%0,%1};\n"
        : "+r"(c0), "+r"(c1)
        : "r"(a0), "r"(a1), "r"(a2), "r"(a3), "r"(b0), "r"(b1));
}
__device__ __forceinline__ void ldsm4(uint32_t& r0, uint32_t& r1, uint32_t& r2,
                                      uint32_t& r3, const void* p) {
    uint32_t a = (uint32_t)__cvta_generic_to_shared(p);
    asm volatile("ldmatrix.sync.aligned.m8n8.x4.shared.b16 {%0,%1,%2,%3}, [%4];\n"
                 : "=r"(r0), "=r"(r1), "=r"(r2), "=r"(r3) : "r"(a));
}
static __device__ __forceinline__ uint32_t pk_h2(float lo, float hi) {
    __half2 t = __floats2half2_rn(lo, hi);
    return *reinterpret_cast<uint32_t*>(&t);
}
static __device__ __forceinline__ float h2lo(uint32_t u) {
    __half2 h = *reinterpret_cast<__half2*>(&u);
    return __half2float(__low2half(h));
}
static __device__ __forceinline__ float h2hi(uint32_t u) {
    __half2 h = *reinterpret_cast<__half2*>(&u);
    return __half2float(__high2half(h));
}
static __device__ __forceinline__ uint32_t h2scale(uint32_t u, float s) {
    __half2 h = *reinterpret_cast<__half2*>(&u);
    __half2 r = __hmul2(h, __float2half2_rn(s));
    return *reinterpret_cast<uint32_t*>(&r);
}

// ---------------------------------------------------------------------------
// ONE fused conversion kernel: Wq|Wk|Wv -> wqkv_h, hs -> hs_h, Wo -> wo_h.
// Segmented by vectorized (x4) global index. Single launch.
// ---------------------------------------------------------------------------
#define CVT_N4 ((WQKV_ELEMS + HS_ELEMS + WO_ELEMS) / 4)   // 14,680,064

__global__ void cvt_all(const float* __restrict__ Wq, const float* __restrict__ Wk,
                        const float* __restrict__ Wv, const float* __restrict__ hs,
                        const float* __restrict__ Wo,
                        __half* __restrict__ wqkv_h, __half* __restrict__ hs_h,
                        __half* __restrict__ wo_h) {
    size_t t4 = (size_t)blockIdx.x * blockDim.x + threadIdx.x;
    if (t4 >= CVT_N4) return;
    size_t i = t4 * 4;

    const float* src;
    __half* dst;
    size_t off;
    if (i < WQKV_ELEMS) {
        size_t row = i / HID_;
        dst = wqkv_h; 
        if (row < (size_t)KOFF)      { src = Wq; off = i; }
        else if (row < (size_t)VOFF) { src = Wk; off = i - (size_t)KOFF * HID_; }
        else                         { src = Wv; off = i - (size_t)VOFF * HID_; }
        dst += i - off;   // dst base offset equals segment start within wqkv_h
        // note: dst + off == wqkv_h + i
        float4 v = *(const float4*)(src + off);
        __half* d = wqkv_h + i;
        d[0] = __float2half_rn(v.x); d[1] = __float2half_rn(v.y);
        d[2] = __float2half_rn(v.z); d[3] = __float2half_rn(v.w);
    } else if (i < WQKV_ELEMS + HS_ELEMS) {
        size_t j = i - WQKV_ELEMS;
        float4 v = *(const float4*)(hs + j);
        __half* d = hs_h + j;
        d[0] = __float2half_rn(v.x); d[1] = __float2half_rn(v.y);
        d[2] = __float2half_rn(v.z); d[3] = __float2half_rn(v.w);
    } else {
        size_t j = i - WQKV_ELEMS - HS_ELEMS;
        float4 v = *(const float4*)(Wo + j);
        __half* d = wo_h + j;
        d[0] = __float2half_rn(v.x); d[1] = __float2half_rn(v.y);
        d[2] = __float2half_rn(v.z); d[3] = __float2half_rn(v.w);
    }
}

// ---------------------------------------------------------------------------
// QKV GEMM with FUSED rope/split/transpose epilogue (unchanged from R15).
// ---------------------------------------------------------------------------
#define BM 128
#define BN 128
#define GK 32
#define GPAD 40
#define GPLANE 5120
#define GSTAGE 15360
#define GSMEM_B (3 * GSTAGE * 2)      // 92160 bytes
#define SWG 16

__global__ __launch_bounds__(256)
void gemm_qkv(const __half* __restrict__ Ah, const __half* __restrict__ Bh,
              const float* __restrict__ cosp, const float* __restrict__ sinp,
              __half* __restrict__ Qhp, __half* __restrict__ Qlp,
              __half* __restrict__ Khp, __half* __restrict__ Vtp) {
    extern __shared__ __half gsm[];
    const uint32_t sb = smem_u32(gsm);
    const int K = HID_;

    const int tid = threadIdx.x;
    const int warp = tid >> 5, lane = tid & 31;
    const int g = lane >> 2, tg = lane & 3;
    const int warpM = warp >> 2, warpN = warp & 3;

    int bx, by;
    {
        int bid = blockIdx.y * gridDim.x + blockIdx.x;
        int per = SWG * gridDim.x;
        int grp = bid / per;
        int rem = bid - grp * per;
        by = grp * SWG + (rem & (SWG - 1));
        bx = rem >> 4;
    }
    const int bm = by * BM, bn = bx * BN;

    const int a_r = lane & 15;
    const int a_k = (lane >> 4) * 8;
    const int b_r = lane & 7;
    const int b_n8 = ((lane >> 4) & 1) * 8;
    const int b_k8 = ((lane >> 3) & 1) * 8;

    float c[4][4][4];
#pragma unroll
    for (int mi = 0; mi < 4; mi++)
#pragma unroll
        for (int ni = 0; ni < 4; ni++)
#pragma unroll
            for (int j = 0; j < 4; j++) c[mi][ni][j] = 0.f;

    const int niter = K / GK;

    auto load_stage = [&](int s, int k0) {
        const uint32_t base = sb + (uint32_t)(s * GSTAGE) * 2;
#pragma unroll
        for (int i = 0; i < 2; i++) {
            int j = tid + (i << 8);
            int row = j >> 2, col = (j & 3) * 8;
            size_t ao = (size_t)(bm + row) * K + k0 + col;
            size_t bo = (size_t)(bn + row) * K + k0 + col;
            uint32_t off = (uint32_t)(row * GPAD + col) * 2;
            cp16(base + off, Ah + ao);
            cp16(base + 2 * GPLANE * 2 + off, Bh + bo);
        }
        asm volatile("cp.async.commit_group;\n");
    };

    load_stage(0, 0);
    load_stage(1, GK);

    for (int i = 0; i < niter; i++) {
        if (i + 1 < niter) asm volatile("cp.async.wait_group 1;\n");
        else               asm volatile("cp.async.wait_group 0;\n");
        __syncthreads();
        if (i + 2 < niter) load_stage((i + 2) % 3, (i + 2) * GK);

        const int s = i % 3;
        const __half* Asm = gsm + (size_t)s * GSTAGE;
        const __half* Bsm = Asm + 2 * GPLANE;
#pragma unroll
        for (int kk = 0; kk < 2; kk++) {
            const int kb = kk * 16;
            uint32_t aH[4][4], bH[4][2];
#pragma unroll
            for (int mi = 0; mi < 4; mi++) {
                int rb = warpM * 64 + mi * 16;
                ldsm4(aH[mi][0], aH[mi][1], aH[mi][2], aH[mi][3],
                      Asm + (size_t)(rb + a_r) * GPAD + kb + a_k);
            }
#pragma unroll
            for (int np = 0; np < 2; np++) {
                int nb = warpN * 32 + np * 16;
                uint32_t r0, r1, r2, r3;
                ldsm4(r0, r1, r2, r3,
                      Bsm + (size_t)(nb + b_r + b_n8) * GPAD + kb + b_k8);
                bH[np * 2][0] = r0; bH[np * 2][1] = r1;
                bH[np * 2 + 1][0] = r2; bH[np * 2 + 1][1] = r3;
            }
#pragma unroll
            for (int mi = 0; mi < 4; mi++)
#pragma unroll
                for (int ni = 0; ni < 4; ni++)
                    mma16816(c[mi][ni], aH[mi][0], aH[mi][1], aH[mi][2], aH[mi][3],
                             bH[ni][0], bH[ni][1]);
        }
    }

    // ---- fused epilogue ----
    __syncthreads();
    float* tile = (float*)gsm;             // 128 x 128, stride 129
#pragma unroll
    for (int mi = 0; mi < 4; mi++) {
        int r0 = warpM * 64 + mi * 16 + g;
#pragma unroll
        for (int ni = 0; ni < 4; ni++) {
            int cc = warpN * 32 + ni * 8 + 2 * tg;
            tile[r0 * 129 + cc]           = c[mi][ni][0];
            tile[r0 * 129 + cc + 1]       = c[mi][ni][1];
            tile[(r0 + 8) * 129 + cc]     = c[mi][ni][2];
            tile[(r0 + 8) * 129 + cc + 1] = c[mi][ni][3];
        }
    }
    __syncthreads();

    if (bn < KOFF) {
        const int h = bn >> 7;
#pragma unroll 4
        for (int it = 0; it < 32; it++) {
            int idx = tid + (it << 8);
            int row = idx >> 6, d = idx & 63;
            int tok = bm + row;
            float x1 = tile[row * 129 + d];
            float x2 = tile[row * 129 + d + 64];
            float cd  = cosp[(size_t)tok * HD_ + d];
            float sd  = sinp[(size_t)tok * HD_ + d];
            float cd2 = cosp[(size_t)tok * HD_ + d + 64];
            float sd2 = sinp[(size_t)tok * HD_ + d + 64];
            float y1 = x1 * cd  - x2 * sd;
            float y2 = x2 * cd2 + x1 * sd2;
            size_t base = ((size_t)tok * NH_ + h) * HD_;
            __half h1 = __float2half_rn(y1);
            __half h2 = __float2half_rn(y2);
            Qhp[base + d]      = h1;
            Qhp[base + d + 64] = h2;
            Qlp[base + d]      = __float2half_rn(y1 - __half2float(h1));
            Qlp[base + d + 64] = __float2half_rn(y2 - __half2float(h2));
        }
    } else if (bn < VOFF) {
        const int hk = (bn - KOFF) >> 7;
#pragma unroll 4
        for (int it = 0; it < 32; it++) {
            int idx = tid + (it << 8);
            int row = idx >> 6, d = idx & 63;
            int tok = bm + row;
            float x1 = tile[row * 129 + d];
            float x2 = tile[row * 129 + d + 64];
            float cd  = cosp[(size_t)tok * HD_ + d];
            float sd  = sinp[(size_t)tok * HD_ + d];
            float cd2 = cosp[(size_t)tok * HD_ + d + 64];
            float sd2 = sinp[(size_t)tok * HD_ + d + 64];
            float y1 = x1 * cd  - x2 * sd;
            float y2 = x2 * cd2 + x1 * sd2;
            size_t base = ((size_t)tok * NKV_ + hk) * HD_;
            Khp[base + d]      = __float2half_rn(y1);
            Khp[base + d + 64] = __float2half_rn(y2);
        }
    } else {
        const int hk = (bn - VOFF) >> 7;
        const int s_loc = tid & 127, halfsel = tid >> 7;
        const int bb = bm >> 11;
        const int s = (bm & (S_ - 1)) + s_loc;
#pragma unroll 8
        for (int dd = 0; dd < 64; dd++) {
            int d = halfsel * 64 + dd;
            float x = tile[s_loc * 129 + d];
            Vtp[(((size_t)(bb * NKV_ + hk)) * HD_ + d) * S_ + s] = __float2half_rn(x);
        }
    }
}

// ---------------------------------------------------------------------------
// Generic 2-plane fp16 NT GEMM (O projection) — unchanged.
// ---------------------------------------------------------------------------
__global__ __launch_bounds__(256)
void gemm_mma(const __half* __restrict__ Ah, const __half* __restrict__ Al,
              const __half* __restrict__ Bh,
              float* __restrict__ C, int M, int N, int K) {
    extern __shared__ __half gsm[];
    const uint32_t sb = smem_u32(gsm);

    const int tid = threadIdx.x;
    const int warp = tid >> 5, lane = tid & 31;
    const int g = lane >> 2, tg = lane & 3;
    const int warpM = warp >> 2, warpN = warp & 3;

    int bx, by;
    {
        int bid = blockIdx.y * gridDim.x + blockIdx.x;
        int per = SWG * gridDim.x;
        int grp = bid / per;
        int rem = bid - grp * per;
        by = grp * SWG + (rem & (SWG - 1));
        bx = rem >> 4;
    }
    const int bm = by * BM, bn = bx * BN;

    const int a_r = lane & 15;
    const int a_k = (lane >> 4) * 8;
    const int b_r = lane & 7;
    const int b_n8 = ((lane >> 4) & 1) * 8;
    const int b_k8 = ((lane >> 3) & 1) * 8;

    float c[4][4][4];
#pragma unroll
    for (int mi = 0; mi < 4; mi++)
#pragma unroll
        for (int ni = 0; ni < 4; ni++)
#pragma unroll
            for (int j = 0; j < 4; j++) c[mi][ni][j] = 0.f;

    const int niter = K / GK;

    auto load_stage = [&](int s, int k0) {
        const uint32_t base = sb + (uint32_t)(s * GSTAGE) * 2;
#pragma unroll
        for (int i = 0; i < 2; i++) {
            int j = tid + (i << 8);
            int row = j >> 2, col = (j & 3) * 8;
            size_t ao = (size_t)(bm + row) * K + k0 + col;
            size_t bo = (size_t)(bn + row) * K + k0 + col;
            uint32_t off = (uint32_t)(row * GPAD + col) * 2;
            cp16(base + off, Ah + ao);
            cp16(base + GPLANE * 2 + off, Al + ao);
            cp16(base + 2 * GPLANE * 2 + off, Bh + bo);
        }
        asm volatile("cp.async.commit_group;\n");
    };

    load_stage(0, 0);
    load_stage(1, GK);

    for (int i = 0; i < niter; i++) {
        if (i + 1 < niter) asm volatile("cp.async.wait_group 1;\n");
        else               asm volatile("cp.async.wait_group 0;\n");
        __syncthreads();
        if (i + 2 < niter) load_stage((i + 2) % 3, (i + 2) * GK);

        const int s = i % 3;
        const __half* Asm = gsm + (size_t)s * GSTAGE;
        const __half* Bsm = Asm + 2 * GPLANE;
#pragma unroll
        for (int kk = 0; kk < 2; kk++) {
            const int kb = kk * 16;
            uint32_t aH[4][4], aL[4][4], bH[4][2];
#pragma unroll
            for (int mi = 0; mi < 4; mi++) {
                int rb = warpM * 64 + mi * 16;
                ldsm4(aH[mi][0], aH[mi][1], aH[mi][2], aH[mi][3],
                      Asm + (size_t)(rb + a_r) * GPAD + kb + a_k);
                ldsm4(aL[mi][0], aL[mi][1], aL[mi][2], aL[mi][3],
                      Asm + GPLANE + (size_t)(rb + a_r) * GPAD + kb + a_k);
            }
#pragma unroll
            for (int np = 0; np < 2; np++) {
                int nb = warpN * 32 + np * 16;
                uint32_t r0, r1, r2, r3;
                ldsm4(r0, r1, r2, r3,
                      Bsm + (size_t)(nb + b_r + b_n8) * GPAD + kb + b_k8);
                bH[np * 2][0] = r0; bH[np * 2][1] = r1;
                bH[np * 2 + 1][0] = r2; bH[np * 2 + 1][1] = r3;
            }
#pragma unroll
            for (int mi = 0; mi < 4; mi++)
#pragma unroll
                for (int ni = 0; ni < 4; ni++) {
                    mma16816(c[mi][ni], aH[mi][0], aH[mi][1], aH[mi][2], aH[mi][3],
                             bH[ni][0], bH[ni][1]);
                    mma16816(c[mi][ni], aL[mi][0], aL[mi][1], aL[mi][2], aL[mi][3],
                             bH[ni][0], bH[ni][1]);
                }
        }
    }

#pragma unroll
    for (int mi = 0; mi < 4; mi++) {
        int r0 = bm + warpM * 64 + mi * 16 + g;
#pragma unroll
        for (int ni = 0; ni < 4; ni++) {
            int cc = bn + warpN * 32 + ni * 8 + 2 * tg;
            *(float2*)(C + (size_t)r0 * N + cc) = make_float2(c[mi][ni][0], c[mi][ni][1]);
            *(float2*)(C + (size_t)(r0 + 8) * N + cc) = make_float2(c[mi][ni][2], c[mi][ni][3]);
        }
    }
}

// ---------------------------------------------------------------------------
// Flash attention — unchanged from R15 (double-buffered KV, 104KB, 2 CTA/SM).
// ---------------------------------------------------------------------------
#define FQH 0
#define FQL 8704
#define FKV0 17408
#define FKVSZ 17920
#define FKo 0
#define FVo 8704
#define FSMEM_B 106496

__global__ __launch_bounds__(128)
void flash_mma(const __half* __restrict__ Qh, const __half* __restrict__ Ql,
               const __half* __restrict__ Kh, const __half* __restrict__ Vth,
               __half* __restrict__ Oh, __half* __restrict__ Ol) {
    extern __shared__ __half fsm[];
    const uint32_t sb = smem_u32(fsm);

    const int b = blockIdx.z, h = blockIdx.y, qt = blockIdx.x;
    const int qs = qt * 64, hk = h >> 2;
    const int tid = threadIdx.x;
    const int warp = tid >> 5, lane = tid & 31;
    const int g = lane >> 2, tg = lane & 3;

    const int a_r = lane & 15;
    const int a_k = (lane >> 4) * 8;
    const int b_r = lane & 7;
    const int b_n8 = ((lane >> 4) & 1) * 8;
    const int b_k8 = ((lane >> 3) & 1) * 8;

#pragma unroll
    for (int i = 0; i < 8; i++) {
        int j = tid + (i << 7);
        int row = j >> 4, kc = j & 15;
        uint32_t d = sb + (uint32_t)((row * 136 + kc * 8) * 2);
        size_t src = ((size_t)(b * S_ + qs + row) * NH_ + h) * HD_ + kc * 8;
        cp16(d + FQH * 2, Qh + src);
        cp16(d + FQL * 2, Ql + src);
    }
    asm volatile("cp.async.commit_group;\n");

    auto load_kv = [&](int buf, int ks) {
        const uint32_t kb = sb + (uint32_t)((FKV0 + buf * FKVSZ) * 2);
#pragma unroll
        for (int i = 0; i < 8; i++) {
            int jj = tid + (i << 7);
            int krow = jj >> 4, kkc = jj & 15;
            uint32_t dk = kb + (uint32_t)((FKo + krow * 136 + kkc * 8) * 2);
            size_t ksrc = ((size_t)(b * S_ + ks + krow) * NKV_ + hk) * HD_ + kkc * 8;
            cp16(dk, Kh + ksrc);
            int vd = jj >> 3, vc = jj & 7;
            uint32_t dv = kb + (uint32_t)((FVo + vd * 72 + vc * 8) * 2);
            size_t vsrc = ((size_t)(b * NKV_ + hk) * HD_ + vd) * S_ + ks + vc * 8;
            cp16(dv, Vth + vsrc);
        }
        asm volatile("cp.async.commit_group;\n");
    };

    load_kv(0, 0);

    float o[16][4];
    uint32_t ocorr[16][2];
#pragma unroll
    for (int nt = 0; nt < 16; nt++) {
#pragma unroll
        for (int j = 0; j < 4; j++) o[nt][j] = 0.f;
        ocorr[nt][0] = 0u; ocorr[nt][1] = 0u;
    }
    float m0 = -1e30f, m1 = -1e30f, l0 = 0.f, l1 = 0.f;

    const int qr0 = qs + warp * 16 + g;
    const int qr1 = qr0 + 8;
    const int ntiles = qt + 1;

    for (int j = 0; j < ntiles; j++) {
        const int ks = j * 64;
        asm volatile("cp.async.wait_group 0;\n");
        __syncthreads();
        if (j + 1 < ntiles) load_kv((j + 1) & 1, (j + 1) * 64);

        const __half* kvb = fsm + FKV0 + (j & 1) * FKVSZ;

        float S4[8][4];
        uint32_t scorr[8][2];
#pragma unroll
        for (int nt = 0; nt < 8; nt++) {
#pragma unroll
            for (int cc = 0; cc < 4; cc++) S4[nt][cc] = 0.f;
            scorr[nt][0] = 0u; scorr[nt][1] = 0u;
        }

#pragma unroll
        for (int dk = 0; dk < 8; dk++) {
            uint32_t aH[4], aL[4];
            ldsm4(aH[0], aH[1], aH[2], aH[3],
                  fsm + FQH + (size_t)(warp * 16 + a_r) * 136 + dk * 16 + a_k);
            ldsm4(aL[0], aL[1], aL[2], aL[3],
                  fsm + FQL + (size_t)(warp * 16 + a_r) * 136 + dk * 16 + a_k);
#pragma unroll
            for (int np = 0; np < 4; np++) {
                int nb = np * 16;
                uint32_t h0, h1, h2, h3;
                ldsm4(h0, h1, h2, h3,
                      kvb + FKo + (size_t)(nb + b_r + b_n8) * 136 + dk * 16 + b_k8);
                mma16816(S4[2 * np],     aH[0], aH[1], aH[2], aH[3], h0, h1);
                mma16816(S4[2 * np + 1], aH[0], aH[1], aH[2], aH[3], h2, h3);
                mma16816h(scorr[2 * np][0],     scorr[2 * np][1],
                          aL[0], aL[1], aL[2], aL[3], h0, h1);
                mma16816h(scorr[2 * np + 1][0], scorr[2 * np + 1][1],
                          aL[0], aL[1], aL[2], aL[3], h2, h3);
            }
        }
#pragma unroll
        for (int nt = 0; nt < 8; nt++) {
            S4[nt][0] += h2lo(scorr[nt][0]);
            S4[nt][1] += h2hi(scorr[nt][0]);
            S4[nt][2] += h2lo(scorr[nt][1]);
            S4[nt][3] += h2hi(scorr[nt][1]);
        }

        float mx0 = -1e30f, mx1 = -1e30f;
        const bool diag = (j == ntiles - 1);
#pragma unroll
        for (int nt = 0; nt < 8; nt++) {
#pragma unroll
            for (int cc = 0; cc < 4; cc++) {
                float v = S4[nt][cc] * SCALING_;
                if (diag) {
                    int kcol = ks + nt * 8 + 2 * tg + (cc & 1);
                    int qr = (cc < 2) ? qr0 : qr1;
                    if (kcol > qr) v = -1e30f;
                }
                S4[nt][cc] = v;
                if (cc < 2) mx0 = fmaxf(mx0, v); else mx1 = fmaxf(mx1, v);
            }
        }
        mx0 = fmaxf(mx0, __shfl_xor_sync(0xffffffffu, mx0, 1));
        mx0 = fmaxf(mx0, __shfl_xor_sync(0xffffffffu, mx0, 2));
        mx1 = fmaxf(mx1, __shfl_xor_sync(0xffffffffu, mx1, 1));
        mx1 = fmaxf(mx1, __shfl_xor_sync(0xffffffffu, mx1, 2));
        const float mt0 = fmaxf(m0, mx0), mt1 = fmaxf(m1, mx1);
        const float sc0 = __expf(m0 - mt0), sc1 = __expf(m1 - mt1);
        m0 = mt0; m1 = mt1;

        float rs0 = 0.f, rs1 = 0.f;
#pragma unroll
        for (int nt = 0; nt < 8; nt++) {
            float p0 = __expf(S4[nt][0] - mt0);
            float p1 = __expf(S4[nt][1] - mt0);
            float p2 = __expf(S4[nt][2] - mt1);
            float p3 = __expf(S4[nt][3] - mt1);
            S4[nt][0] = p0; S4[nt][1] = p1; S4[nt][2] = p2; S4[nt][3] = p3;
            rs0 += p0 + p1; rs1 += p2 + p3;
        }
        rs0 += __shfl_xor_sync(0xffffffffu, rs0, 1);
        rs0 += __shfl_xor_sync(0xffffffffu, rs0, 2);
        rs1 += __shfl_xor_sync(0xffffffffu, rs1, 1);
        rs1 += __shfl_xor_sync(0xffffffffu, rs1, 2);
        l0 = l0 * sc0 + rs0;
        l1 = l1 * sc1 + rs1;
#pragma unroll
        for (int nt = 0; nt < 16; nt++) {
            o[nt][0] *= sc0; o[nt][1] *= sc0;
            o[nt][2] *= sc1; o[nt][3] *= sc1;
            ocorr[nt][0] = h2scale(ocorr[nt][0], sc0);
            ocorr[nt][1] = h2scale(ocorr[nt][1], sc1);
        }

#pragma unroll
        for (int kt = 0; kt < 4; kt++) {
            uint32_t aPh[4], aPl[4];
#pragma unroll
            for (int half = 0; half < 2; half++) {
                const float* sv = S4[2 * kt + half];
                uint32_t p01 = pk_h2(sv[0], sv[1]);
                uint32_t p23 = pk_h2(sv[2], sv[3]);
                float r0f = sv[0] - h2lo(p01);
                float r1f = sv[1] - h2hi(p01);
                float r2f = sv[2] - h2lo(p23);
                float r3f = sv[3] - h2hi(p23);
                aPh[0 + 2 * half] = p01;
                aPh[1 + 2 * half] = p23;
                aPl[0 + 2 * half] = pk_h2(r0f, r1f);
                aPl[1 + 2 * half] = pk_h2(r2f, r3f);
            }
#pragma unroll
            for (int np = 0; np < 8; np++) {
                int nb = np * 16;
                uint32_t h0, h1, h2, h3;
                ldsm4(h0, h1, h2, h3,
                      kvb + FVo + (size_t)(nb + b_r + b_n8) * 72 + kt * 16 + b_k8);
                mma16816(o[2 * np],     aPh[0], aPh[1], aPh[2], aPh[3], h0, h1);
                mma16816(o[2 * np + 1], aPh[0], aPh[1], aPh[2], aPh[3], h2, h3);
                mma16816h(ocorr[2 * np][0],     ocorr[2 * np][1],
                          aPl[0], aPl[1], aPl[2], aPl[3], h0, h1);
                mma16816h(ocorr[2 * np + 1][0], ocorr[2 * np + 1][1],
                          aPl[0], aPl[1], aPl[2], aPl[3], h2, h3);
            }
        }
    }

    const float inv0 = 1.f / l0, inv1 = 1.f / l1;
    const size_t r0base = ((size_t)(b * S_ + qr0) * NH_ + h) * HD_;
    const size_t r1base = ((size_t)(b * S_ + qr1) * NH_ + h) * HD_;
#pragma unroll
    for (int nt = 0; nt < 16; nt++) {
        int cc = nt * 8 + 2 * tg;
        float v00 = (o[nt][0] + h2lo(ocorr[nt][0])) * inv0;
        float v01 = (o[nt][1] + h2hi(ocorr[nt][0])) * inv0;
        float v10 = (o[nt][2] + h2lo(ocorr[nt][1])) * inv1;
        float v11 = (o[nt][3] + h2hi(ocorr[nt][1])) * inv1;
        uint32_t h0p = pk_h2(v00, v01);
        uint32_t h1p = pk_h2(v10, v11);
        float e00 = v00 - h2lo(h0p);
        float e01 = v01 - h2hi(h0p);
        float e10 = v10 - h2lo(h1p);
        float e11 = v11 - h2hi(h1p);
        *(uint32_t*)(Oh + r0base + cc) = h0p;
        *(uint32_t*)(Ol + r0base + cc) = pk_h2(e00, e01);
        *(uint32_t*)(Oh + r1base + cc) = h1p;
        *(uint32_t*)(Ol + r1base + cc) = pk_h2(e10, e11);
    }
}

// ---------------------------------------------------------------------------
// Launch: 4 kernels total
// ---------------------------------------------------------------------------
extern "C" void kernel_launch(void* const* d_in, const int* in_sizes, int n_in,
                              void* d_out, int out_size) {
    const float* hs   = (const float*)d_in[0];
    const float* cosp = (const float*)d_in[1];
    const float* sinp = (const float*)d_in[2];
    const float* Wq   = (const float*)d_in[4];
    const float* Wk   = (const float*)d_in[5];
    const float* Wv   = (const float*)d_in[6];
    const float* Wo   = (const float*)d_in[7];
    float* out = (float*)d_out;

    __half *hs_h, *wqkv_h, *wo_h, *ob_h, *ob_l, *qh, *ql, *kh, *vth;
    cudaGetSymbolAddress((void**)&hs_h, g_hs_h);
    cudaGetSymbolAddress((void**)&wqkv_h, g_wqkv_h);
    cudaGetSymbolAddress((void**)&wo_h, g_wo_h);
    cudaGetSymbolAddress((void**)&ob_h, g_ob_h); cudaGetSymbolAddress((void**)&ob_l, g_ob_l);
    cudaGetSymbolAddress((void**)&qh, g_qh); cudaGetSymbolAddress((void**)&ql, g_ql);
    cudaGetSymbolAddress((void**)&kh, g_kh);
    cudaGetSymbolAddress((void**)&vth, g_vth);

    cudaFuncSetAttribute(gemm_qkv, cudaFuncAttributeMaxDynamicSharedMemorySize, GSMEM_B);
    cudaFuncSetAttribute(gemm_mma, cudaFuncAttributeMaxDynamicSharedMemorySize, GSMEM_B);
    cudaFuncSetAttribute(flash_mma, cudaFuncAttributeMaxDynamicSharedMemorySize, FSMEM_B);

    const int M = B_ * S_;   // 4096

    // single fused conversion pass (Wqkv + hs + Wo)
    cvt_all<<<(unsigned)((CVT_N4 + 255) / 256), 256>>>(
        Wq, Wk, Wv, hs, Wo, wqkv_h, hs_h, wo_h);

    // fused QKV projection + rope/split/transpose epilogue
    gemm_qkv<<<dim3(NQKV / BN, M / BM), 256, GSMEM_B>>>(
        hs_h, wqkv_h, cosp, sinp, qh, ql, kh, vth);

    // flash attention
    flash_mma<<<dim3(S_ / 64, NH_, B_), 128, FSMEM_B>>>(qh, ql, kh, vth, ob_h, ob_l);

    // O projection (hi+lo correction)
    gemm_mma<<<dim3(HID_ / BN, M / BM), 256, GSMEM_B>>>(
        ob_h, ob_l, wo_h, out, M, HID_, NH_ * HD_);
}

// round 17
// speedup vs baseline: 2.0532x; 1.0021x over previous
#include <cuda_runtime.h>
#include <cuda_fp16.h>
#include <cstdint>

// Problem constants
#define B_   2
#define S_   2048
#define HID_ 4096
#define NH_  32
#define NKV_ 8
#define HD_  128
#define NREP_ 4
#define SCALING_ 0.08838834764831843f   // 128^-0.5

#define NQKV 6144      // 4096 (Q) + 1024 (K) + 1024 (V)
#define KOFF 4096
#define VOFF 5120

// fp16 planes
#define HS_ELEMS   ((size_t)B_ * S_ * HID_)
#define WQKV_ELEMS ((size_t)NQKV * HID_)
#define WO_ELEMS   ((size_t)HID_ * NH_ * HD_)
#define KV_ELEMS   ((size_t)B_ * S_ * NKV_ * HD_)
__device__ __half g_hs_h[HS_ELEMS];                 // hidden states: hi only
__device__ __half g_wqkv_h[WQKV_ELEMS];             // weights: hi only
__device__ __half g_wo_h[WO_ELEMS];                 // weights: hi only
__device__ __half g_ob_h[HS_ELEMS], g_ob_l[HS_ELEMS];
// attention planes (post-rope): Q hi+lo; K,V hi only
__device__ __half g_qh[HS_ELEMS], g_ql[HS_ELEMS];
__device__ __half g_kh[KV_ELEMS];
__device__ __half g_vth[KV_ELEMS];                  // [b][hk][d][s]

// ---------------------------------------------------------------------------
// helpers
// ---------------------------------------------------------------------------
static __device__ __forceinline__ uint32_t smem_u32(const void* p) {
    uint32_t a;
    asm("{ .reg .u64 t; cvta.to.shared.u64 t, %1; cvt.u32.u64 %0, t; }"
        : "=r"(a) : "l"(p));
    return a;
}
static __device__ __forceinline__ void cp16(uint32_t dst, const void* src) {
    asm volatile("cp.async.cg.shared.global [%0], [%1], 16;\n" :: "r"(dst), "l"(src));
}
__device__ __forceinline__ void mma16816(float c[4], uint32_t a0, uint32_t a1,
                                         uint32_t a2, uint32_t a3,
                                         uint32_t b0, uint32_t b1) {
    asm volatile(
        "mma.sync.aligned.m16n8k16.row.col.f32.f16.f16.f32 "
        "{%0,%1,%2,%3}, {%4,%5,%6,%7}, {%8,%9}, {%0,%1,%2,%3};\n"
        : "+f"(c[0]), "+f"(c[1]), "+f"(c[2]), "+f"(c[3])
        : "r"(a0), "r"(a1), "r"(a2), "r"(a3), "r"(b0), "r"(b1));
}
__device__ __forceinline__ void mma16816h(uint32_t& c0, uint32_t& c1,
                                          uint32_t a0, uint32_t a1,
                                          uint32_t a2, uint32_t a3,
                                          uint32_t b0, uint32_t b1) {
    asm volatile(
        "mma.sync.aligned.m16n8k16.row.col.f16.f16.f16.f16 "
        "{%0,%1}, {%2,%3,%4,%5}, {%6,%7}, {%0,%1};\n"
        : "+r"(c0), "+r"(c1)
        : "r"(a0), "r"(a1), "r"(a2), "r"(a3), "r"(b0), "r"(b1));
}
__device__ __forceinline__ void ldsm4(uint32_t& r0, uint32_t& r1, uint32_t& r2,
                                      uint32_t& r3, const void* p) {
    uint32_t a = (uint32_t)__cvta_generic_to_shared(p);
    asm volatile("ldmatrix.sync.aligned.m8n8.x4.shared.b16 {%0,%1,%2,%3}, [%4];\n"
                 : "=r"(r0), "=r"(r1), "=r"(r2), "=r"(r3) : "r"(a));
}
static __device__ __forceinline__ uint32_t pk_h2(float lo, float hi) {
    __half2 t = __floats2half2_rn(lo, hi);
    return *reinterpret_cast<uint32_t*>(&t);
}
static __device__ __forceinline__ float h2lo(uint32_t u) {
    __half2 h = *reinterpret_cast<__half2*>(&u);
    return __half2float(__low2half(h));
}
static __device__ __forceinline__ float h2hi(uint32_t u) {
    __half2 h = *reinterpret_cast<__half2*>(&u);
    return __half2float(__high2half(h));
}
static __device__ __forceinline__ uint32_t h2scale(uint32_t u, float s) {
    __half2 h = *reinterpret_cast<__half2*>(&u);
    __half2 r = __hmul2(h, __float2half2_rn(s));
    return *reinterpret_cast<uint32_t*>(&r);
}

// ---------------------------------------------------------------------------
// ONE fused conversion kernel (unchanged from R16)
// ---------------------------------------------------------------------------
#define CVT_N4 ((WQKV_ELEMS + HS_ELEMS + WO_ELEMS) / 4)

__global__ void cvt_all(const float* __restrict__ Wq, const float* __restrict__ Wk,
                        const float* __restrict__ Wv, const float* __restrict__ hs,
                        const float* __restrict__ Wo,
                        __half* __restrict__ wqkv_h, __half* __restrict__ hs_h,
                        __half* __restrict__ wo_h) {
    size_t t4 = (size_t)blockIdx.x * blockDim.x + threadIdx.x;
    if (t4 >= CVT_N4) return;
    size_t i = t4 * 4;

    if (i < WQKV_ELEMS) {
        size_t row = i / HID_;
        const float* src;
        size_t off;
        if (row < (size_t)KOFF)      { src = Wq; off = i; }
        else if (row < (size_t)VOFF) { src = Wk; off = i - (size_t)KOFF * HID_; }
        else                         { src = Wv; off = i - (size_t)VOFF * HID_; }
        float4 v = *(const float4*)(src + off);
        __half* d = wqkv_h + i;
        d[0] = __float2half_rn(v.x); d[1] = __float2half_rn(v.y);
        d[2] = __float2half_rn(v.z); d[3] = __float2half_rn(v.w);
    } else if (i < WQKV_ELEMS + HS_ELEMS) {
        size_t j = i - WQKV_ELEMS;
        float4 v = *(const float4*)(hs + j);
        __half* d = hs_h + j;
        d[0] = __float2half_rn(v.x); d[1] = __float2half_rn(v.y);
        d[2] = __float2half_rn(v.z); d[3] = __float2half_rn(v.w);
    } else {
        size_t j = i - WQKV_ELEMS - HS_ELEMS;
        float4 v = *(const float4*)(Wo + j);
        __half* d = wo_h + j;
        d[0] = __float2half_rn(v.x); d[1] = __float2half_rn(v.y);
        d[2] = __float2half_rn(v.z); d[3] = __float2half_rn(v.w);
    }
}

// ---------------------------------------------------------------------------
// QKV GEMM with FUSED rope/split/transpose epilogue (unchanged).
// ---------------------------------------------------------------------------
#define BM 128
#define BN 128
#define GK 32
#define GPAD 40
#define GPLANE 5120
#define GSTAGE 15360
#define GSMEM_B (3 * GSTAGE * 2)      // 92160 bytes
#define SWG 16

__global__ __launch_bounds__(256)
void gemm_qkv(const __half* __restrict__ Ah, const __half* __restrict__ Bh,
              const float* __restrict__ cosp, const float* __restrict__ sinp,
              __half* __restrict__ Qhp, __half* __restrict__ Qlp,
              __half* __restrict__ Khp, __half* __restrict__ Vtp) {
    extern __shared__ __half gsm[];
    const uint32_t sb = smem_u32(gsm);
    const int K = HID_;

    const int tid = threadIdx.x;
    const int warp = tid >> 5, lane = tid & 31;
    const int g = lane >> 2, tg = lane & 3;
    const int warpM = warp >> 2, warpN = warp & 3;

    int bx, by;
    {
        int bid = blockIdx.y * gridDim.x + blockIdx.x;
        int per = SWG * gridDim.x;
        int grp = bid / per;
        int rem = bid - grp * per;
        by = grp * SWG + (rem & (SWG - 1));
        bx = rem >> 4;
    }
    const int bm = by * BM, bn = bx * BN;

    const int a_r = lane & 15;
    const int a_k = (lane >> 4) * 8;
    const int b_r = lane & 7;
    const int b_n8 = ((lane >> 4) & 1) * 8;
    const int b_k8 = ((lane >> 3) & 1) * 8;

    float c[4][4][4];
#pragma unroll
    for (int mi = 0; mi < 4; mi++)
#pragma unroll
        for (int ni = 0; ni < 4; ni++)
#pragma unroll
            for (int j = 0; j < 4; j++) c[mi][ni][j] = 0.f;

    const int niter = K / GK;

    auto load_stage = [&](int s, int k0) {
        const uint32_t base = sb + (uint32_t)(s * GSTAGE) * 2;
#pragma unroll
        for (int i = 0; i < 2; i++) {
            int j = tid + (i << 8);
            int row = j >> 2, col = (j & 3) * 8;
            size_t ao = (size_t)(bm + row) * K + k0 + col;
            size_t bo = (size_t)(bn + row) * K + k0 + col;
            uint32_t off = (uint32_t)(row * GPAD + col) * 2;
            cp16(base + off, Ah + ao);
            cp16(base + 2 * GPLANE * 2 + off, Bh + bo);
        }
        asm volatile("cp.async.commit_group;\n");
    };

    load_stage(0, 0);
    load_stage(1, GK);

    for (int i = 0; i < niter; i++) {
        if (i + 1 < niter) asm volatile("cp.async.wait_group 1;\n");
        else               asm volatile("cp.async.wait_group 0;\n");
        __syncthreads();
        if (i + 2 < niter) load_stage((i + 2) % 3, (i + 2) * GK);

        const int s = i % 3;
        const __half* Asm = gsm + (size_t)s * GSTAGE;
        const __half* Bsm = Asm + 2 * GPLANE;
#pragma unroll
        for (int kk = 0; kk < 2; kk++) {
            const int kb = kk * 16;
            uint32_t aH[4][4], bH[4][2];
#pragma unroll
            for (int mi = 0; mi < 4; mi++) {
                int rb = warpM * 64 + mi * 16;
                ldsm4(aH[mi][0], aH[mi][1], aH[mi][2], aH[mi][3],
                      Asm + (size_t)(rb + a_r) * GPAD + kb + a_k);
            }
#pragma unroll
            for (int np = 0; np < 2; np++) {
                int nb = warpN * 32 + np * 16;
                uint32_t r0, r1, r2, r3;
                ldsm4(r0, r1, r2, r3,
                      Bsm + (size_t)(nb + b_r + b_n8) * GPAD + kb + b_k8);
                bH[np * 2][0] = r0; bH[np * 2][1] = r1;
                bH[np * 2 + 1][0] = r2; bH[np * 2 + 1][1] = r3;
            }
#pragma unroll
            for (int mi = 0; mi < 4; mi++)
#pragma unroll
                for (int ni = 0; ni < 4; ni++)
                    mma16816(c[mi][ni], aH[mi][0], aH[mi][1], aH[mi][2], aH[mi][3],
                             bH[ni][0], bH[ni][1]);
        }
    }

    // ---- fused epilogue ----
    __syncthreads();
    float* tile = (float*)gsm;             // 128 x 128, stride 129
#pragma unroll
    for (int mi = 0; mi < 4; mi++) {
        int r0 = warpM * 64 + mi * 16 + g;
#pragma unroll
        for (int ni = 0; ni < 4; ni++) {
            int cc = warpN * 32 + ni * 8 + 2 * tg;
            tile[r0 * 129 + cc]           = c[mi][ni][0];
            tile[r0 * 129 + cc + 1]       = c[mi][ni][1];
            tile[(r0 + 8) * 129 + cc]     = c[mi][ni][2];
            tile[(r0 + 8) * 129 + cc + 1] = c[mi][ni][3];
        }
    }
    __syncthreads();

    if (bn < KOFF) {
        const int h = bn >> 7;
#pragma unroll 4
        for (int it = 0; it < 32; it++) {
            int idx = tid + (it << 8);
            int row = idx >> 6, d = idx & 63;
            int tok = bm + row;
            float x1 = tile[row * 129 + d];
            float x2 = tile[row * 129 + d + 64];
            float cd  = cosp[(size_t)tok * HD_ + d];
            float sd  = sinp[(size_t)tok * HD_ + d];
            float cd2 = cosp[(size_t)tok * HD_ + d + 64];
            float sd2 = sinp[(size_t)tok * HD_ + d + 64];
            float y1 = x1 * cd  - x2 * sd;
            float y2 = x2 * cd2 + x1 * sd2;
            size_t base = ((size_t)tok * NH_ + h) * HD_;
            __half h1 = __float2half_rn(y1);
            __half h2 = __float2half_rn(y2);
            Qhp[base + d]      = h1;
            Qhp[base + d + 64] = h2;
            Qlp[base + d]      = __float2half_rn(y1 - __half2float(h1));
            Qlp[base + d + 64] = __float2half_rn(y2 - __half2float(h2));
        }
    } else if (bn < VOFF) {
        const int hk = (bn - KOFF) >> 7;
#pragma unroll 4
        for (int it = 0; it < 32; it++) {
            int idx = tid + (it << 8);
            int row = idx >> 6, d = idx & 63;
            int tok = bm + row;
            float x1 = tile[row * 129 + d];
            float x2 = tile[row * 129 + d + 64];
            float cd  = cosp[(size_t)tok * HD_ + d];
            float sd  = sinp[(size_t)tok * HD_ + d];
            float cd2 = cosp[(size_t)tok * HD_ + d + 64];
            float sd2 = sinp[(size_t)tok * HD_ + d + 64];
            float y1 = x1 * cd  - x2 * sd;
            float y2 = x2 * cd2 + x1 * sd2;
            size_t base = ((size_t)tok * NKV_ + hk) * HD_;
            Khp[base + d]      = __float2half_rn(y1);
            Khp[base + d + 64] = __float2half_rn(y2);
        }
    } else {
        const int hk = (bn - VOFF) >> 7;
        const int s_loc = tid & 127, halfsel = tid >> 7;
        const int bb = bm >> 11;
        const int s = (bm & (S_ - 1)) + s_loc;
#pragma unroll 8
        for (int dd = 0; dd < 64; dd++) {
            int d = halfsel * 64 + dd;
            float x = tile[s_loc * 129 + d];
            Vtp[(((size_t)(bb * NKV_ + hk)) * HD_ + d) * S_ + s] = __float2half_rn(x);
        }
    }
}

// ---------------------------------------------------------------------------
// O-projection GEMM: C = (Ah+Al) * Bh^T. MMA schedule reordered: all 16
// hi-MMAs, then all 16 lo-MMAs per kk-step -> accumulator reuse distance
// 1 -> 16 (removes HMMA RAW stalls). Per-accumulator op order unchanged
// (hi then lo) => bit-identical results.
// ---------------------------------------------------------------------------
__global__ __launch_bounds__(256)
void gemm_mma(const __half* __restrict__ Ah, const __half* __restrict__ Al,
              const __half* __restrict__ Bh,
              float* __restrict__ C, int M, int N, int K) {
    extern __shared__ __half gsm[];
    const uint32_t sb = smem_u32(gsm);

    const int tid = threadIdx.x;
    const int warp = tid >> 5, lane = tid & 31;
    const int g = lane >> 2, tg = lane & 3;
    const int warpM = warp >> 2, warpN = warp & 3;

    int bx, by;
    {
        int bid = blockIdx.y * gridDim.x + blockIdx.x;
        int per = SWG * gridDim.x;
        int grp = bid / per;
        int rem = bid - grp * per;
        by = grp * SWG + (rem & (SWG - 1));
        bx = rem >> 4;
    }
    const int bm = by * BM, bn = bx * BN;

    const int a_r = lane & 15;
    const int a_k = (lane >> 4) * 8;
    const int b_r = lane & 7;
    const int b_n8 = ((lane >> 4) & 1) * 8;
    const int b_k8 = ((lane >> 3) & 1) * 8;

    float c[4][4][4];
#pragma unroll
    for (int mi = 0; mi < 4; mi++)
#pragma unroll
        for (int ni = 0; ni < 4; ni++)
#pragma unroll
            for (int j = 0; j < 4; j++) c[mi][ni][j] = 0.f;

    const int niter = K / GK;

    auto load_stage = [&](int s, int k0) {
        const uint32_t base = sb + (uint32_t)(s * GSTAGE) * 2;
#pragma unroll
        for (int i = 0; i < 2; i++) {
            int j = tid + (i << 8);
            int row = j >> 2, col = (j & 3) * 8;
            size_t ao = (size_t)(bm + row) * K + k0 + col;
            size_t bo = (size_t)(bn + row) * K + k0 + col;
            uint32_t off = (uint32_t)(row * GPAD + col) * 2;
            cp16(base + off, Ah + ao);
            cp16(base + GPLANE * 2 + off, Al + ao);
            cp16(base + 2 * GPLANE * 2 + off, Bh + bo);
        }
        asm volatile("cp.async.commit_group;\n");
    };

    load_stage(0, 0);
    load_stage(1, GK);

    for (int i = 0; i < niter; i++) {
        if (i + 1 < niter) asm volatile("cp.async.wait_group 1;\n");
        else               asm volatile("cp.async.wait_group 0;\n");
        __syncthreads();
        if (i + 2 < niter) load_stage((i + 2) % 3, (i + 2) * GK);

        const int s = i % 3;
        const __half* Asm = gsm + (size_t)s * GSTAGE;
        const __half* Bsm = Asm + 2 * GPLANE;
#pragma unroll
        for (int kk = 0; kk < 2; kk++) {
            const int kb = kk * 16;
            uint32_t aH[4][4], aL[4][4], bH[4][2];
#pragma unroll
            for (int mi = 0; mi < 4; mi++) {
                int rb = warpM * 64 + mi * 16;
                ldsm4(aH[mi][0], aH[mi][1], aH[mi][2], aH[mi][3],
                      Asm + (size_t)(rb + a_r) * GPAD + kb + a_k);
                ldsm4(aL[mi][0], aL[mi][1], aL[mi][2], aL[mi][3],
                      Asm + GPLANE + (size_t)(rb + a_r) * GPAD + kb + a_k);
            }
#pragma unroll
            for (int np = 0; np < 2; np++) {
                int nb = warpN * 32 + np * 16;
                uint32_t r0, r1, r2, r3;
                ldsm4(r0, r1, r2, r3,
                      Bsm + (size_t)(nb + b_r + b_n8) * GPAD + kb + b_k8);
                bH[np * 2][0] = r0; bH[np * 2][1] = r1;
                bH[np * 2 + 1][0] = r2; bH[np * 2 + 1][1] = r3;
            }
            // pass 1: all hi-plane MMAs
#pragma unroll
            for (int mi = 0; mi < 4; mi++)
#pragma unroll
                for (int ni = 0; ni < 4; ni++)
                    mma16816(c[mi][ni], aH[mi][0], aH[mi][1], aH[mi][2], aH[mi][3],
                             bH[ni][0], bH[ni][1]);
            // pass 2: all lo-plane MMAs (same per-accumulator order as before)
#pragma unroll
            for (int mi = 0; mi < 4; mi++)
#pragma unroll
                for (int ni = 0; ni < 4; ni++)
                    mma16816(c[mi][ni], aL[mi][0], aL[mi][1], aL[mi][2], aL[mi][3],
                             bH[ni][0], bH[ni][1]);
        }
    }

#pragma unroll
    for (int mi = 0; mi < 4; mi++) {
        int r0 = bm + warpM * 64 + mi * 16 + g;
#pragma unroll
        for (int ni = 0; ni < 4; ni++) {
            int cc = bn + warpN * 32 + ni * 8 + 2 * tg;
            *(float2*)(C + (size_t)r0 * N + cc) = make_float2(c[mi][ni][0], c[mi][ni][1]);
            *(float2*)(C + (size_t)(r0 + 8) * N + cc) = make_float2(c[mi][ni][2], c[mi][ni][3]);
        }
    }
}

// ---------------------------------------------------------------------------
// Flash attention — unchanged (double-buffered KV, 104KB, 2 CTA/SM).
// ---------------------------------------------------------------------------
#define FQH 0
#define FQL 8704
#define FKV0 17408
#define FKVSZ 17920
#define FKo 0
#define FVo 8704
#define FSMEM_B 106496

__global__ __launch_bounds__(128)
void flash_mma(const __half* __restrict__ Qh, const __half* __restrict__ Ql,
               const __half* __restrict__ Kh, const __half* __restrict__ Vth,
               __half* __restrict__ Oh, __half* __restrict__ Ol) {
    extern __shared__ __half fsm[];
    const uint32_t sb = smem_u32(fsm);

    const int b = blockIdx.z, h = blockIdx.y, qt = blockIdx.x;
    const int qs = qt * 64, hk = h >> 2;
    const int tid = threadIdx.x;
    const int warp = tid >> 5, lane = tid & 31;
    const int g = lane >> 2, tg = lane & 3;

    const int a_r = lane & 15;
    const int a_k = (lane >> 4) * 8;
    const int b_r = lane & 7;
    const int b_n8 = ((lane >> 4) & 1) * 8;
    const int b_k8 = ((lane >> 3) & 1) * 8;

#pragma unroll
    for (int i = 0; i < 8; i++) {
        int j = tid + (i << 7);
        int row = j >> 4, kc = j & 15;
        uint32_t d = sb + (uint32_t)((row * 136 + kc * 8) * 2);
        size_t src = ((size_t)(b * S_ + qs + row) * NH_ + h) * HD_ + kc * 8;
        cp16(d + FQH * 2, Qh + src);
        cp16(d + FQL * 2, Ql + src);
    }
    asm volatile("cp.async.commit_group;\n");

    auto load_kv = [&](int buf, int ks) {
        const uint32_t kb = sb + (uint32_t)((FKV0 + buf * FKVSZ) * 2);
#pragma unroll
        for (int i = 0; i < 8; i++) {
            int jj = tid + (i << 7);
            int krow = jj >> 4, kkc = jj & 15;
            uint32_t dk = kb + (uint32_t)((FKo + krow * 136 + kkc * 8) * 2);
            size_t ksrc = ((size_t)(b * S_ + ks + krow) * NKV_ + hk) * HD_ + kkc * 8;
            cp16(dk, Kh + ksrc);
            int vd = jj >> 3, vc = jj & 7;
            uint32_t dv = kb + (uint32_t)((FVo + vd * 72 + vc * 8) * 2);
            size_t vsrc = ((size_t)(b * NKV_ + hk) * HD_ + vd) * S_ + ks + vc * 8;
            cp16(dv, Vth + vsrc);
        }
        asm volatile("cp.async.commit_group;\n");
    };

    load_kv(0, 0);

    float o[16][4];
    uint32_t ocorr[16][2];
#pragma unroll
    for (int nt = 0; nt < 16; nt++) {
#pragma unroll
        for (int j = 0; j < 4; j++) o[nt][j] = 0.f;
        ocorr[nt][0] = 0u; ocorr[nt][1] = 0u;
    }
    float m0 = -1e30f, m1 = -1e30f, l0 = 0.f, l1 = 0.f;

    const int qr0 = qs + warp * 16 + g;
    const int qr1 = qr0 + 8;
    const int ntiles = qt + 1;

    for (int j = 0; j < ntiles; j++) {
        const int ks = j * 64;
        asm volatile("cp.async.wait_group 0;\n");
        __syncthreads();
        if (j + 1 < ntiles) load_kv((j + 1) & 1, (j + 1) * 64);

        const __half* kvb = fsm + FKV0 + (j & 1) * FKVSZ;

        float S4[8][4];
        uint32_t scorr[8][2];
#pragma unroll
        for (int nt = 0; nt < 8; nt++) {
#pragma unroll
            for (int cc = 0; cc < 4; cc++) S4[nt][cc] = 0.f;
            scorr[nt][0] = 0u; scorr[nt][1] = 0u;
        }

#pragma unroll
        for (int dk = 0; dk < 8; dk++) {
            uint32_t aH[4], aL[4];
            ldsm4(aH[0], aH[1], aH[2], aH[3],
                  fsm + FQH + (size_t)(warp * 16 + a_r) * 136 + dk * 16 + a_k);
            ldsm4(aL[0], aL[1], aL[2], aL[3],
                  fsm + FQL + (size_t)(warp * 16 + a_r) * 136 + dk * 16 + a_k);
#pragma unroll
            for (int np = 0; np < 4; np++) {
                int nb = np * 16;
                uint32_t h0, h1, h2, h3;
                ldsm4(h0, h1, h2, h3,
                      kvb + FKo + (size_t)(nb + b_r + b_n8) * 136 + dk * 16 + b_k8);
                mma16816(S4[2 * np],     aH[0], aH[1], aH[2], aH[3], h0, h1);
                mma16816(S4[2 * np + 1], aH[0], aH[1], aH[2], aH[3], h2, h3);
                mma16816h(scorr[2 * np][0],     scorr[2 * np][1],
                          aL[0], aL[1], aL[2], aL[3], h0, h1);
                mma16816h(scorr[2 * np + 1][0], scorr[2 * np + 1][1],
                          aL[0], aL[1], aL[2], aL[3], h2, h3);
            }
        }
#pragma unroll
        for (int nt = 0; nt < 8; nt++) {
            S4[nt][0] += h2lo(scorr[nt][0]);
            S4[nt][1] += h2hi(scorr[nt][0]);
            S4[nt][2] += h2lo(scorr[nt][1]);
            S4[nt][3] += h2hi(scorr[nt][1]);
        }

        float mx0 = -1e30f, mx1 = -1e30f;
        const bool diag = (j == ntiles - 1);
#pragma unroll
        for (int nt = 0; nt < 8; nt++) {
#pragma unroll
            for (int cc = 0; cc < 4; cc++) {
                float v = S4[nt][cc] * SCALING_;
                if (diag) {
                    int kcol = ks + nt * 8 + 2 * tg + (cc & 1);
                    int qr = (cc < 2) ? qr0 : qr1;
                    if (kcol > qr) v = -1e30f;
                }
                S4[nt][cc] = v;
                if (cc < 2) mx0 = fmaxf(mx0, v); else mx1 = fmaxf(mx1, v);
            }
        }
        mx0 = fmaxf(mx0, __shfl_xor_sync(0xffffffffu, mx0, 1));
        mx0 = fmaxf(mx0, __shfl_xor_sync(0xffffffffu, mx0, 2));
        mx1 = fmaxf(mx1, __shfl_xor_sync(0xffffffffu, mx1, 1));
        mx1 = fmaxf(mx1, __shfl_xor_sync(0xffffffffu, mx1, 2));
        const float mt0 = fmaxf(m0, mx0), mt1 = fmaxf(m1, mx1);
        const float sc0 = __expf(m0 - mt0), sc1 = __expf(m1 - mt1);
        m0 = mt0; m1 = mt1;

        float rs0 = 0.f, rs1 = 0.f;
#pragma unroll
        for (int nt = 0; nt < 8; nt++) {
            float p0 = __expf(S4[nt][0] - mt0);
            float p1 = __expf(S4[nt][1] - mt0);
            float p2 = __expf(S4[nt][2] - mt1);
            float p3 = __expf(S4[nt][3] - mt1);
            S4[nt][0] = p0; S4[nt][1] = p1; S4[nt][2] = p2; S4[nt][3] = p3;
            rs0 += p0 + p1; rs1 += p2 + p3;
        }
        rs0 += __shfl_xor_sync(0xffffffffu, rs0, 1);
        rs0 += __shfl_xor_sync(0xffffffffu, rs0, 2);
        rs1 += __shfl_xor_sync(0xffffffffu, rs1, 1);
        rs1 += __shfl_xor_sync(0xffffffffu, rs1, 2);
        l0 = l0 * sc0 + rs0;
        l1 = l1 * sc1 + rs1;
#pragma unroll
        for (int nt = 0; nt < 16; nt++) {
            o[nt][0] *= sc0; o[nt][1] *= sc0;
            o[nt][2] *= sc1; o[nt][3] *= sc1;
            ocorr[nt][0] = h2scale(ocorr[nt][0], sc0);
            ocorr[nt][1] = h2scale(ocorr[nt][1], sc1);
        }

#pragma unroll
        for (int kt = 0; kt < 4; kt++) {
            uint32_t aPh[4], aPl[4];
#pragma unroll
            for (int half = 0; half < 2; half++) {
                const float* sv = S4[2 * kt + half];
                uint32_t p01 = pk_h2(sv[0], sv[1]);
                uint32_t p23 = pk_h2(sv[2], sv[3]);
                float r0f = sv[0] - h2lo(p01);
                float r1f = sv[1] - h2hi(p01);
                float r2f = sv[2] - h2lo(p23);
                float r3f = sv[3] - h2hi(p23);
                aPh[0 + 2 * half] = p01;
                aPh[1 + 2 * half] = p23;
                aPl[0 + 2 * half] = pk_h2(r0f, r1f);
                aPl[1 + 2 * half] = pk_h2(r2f, r3f);
            }
#pragma unroll
            for (int np = 0; np < 8; np++) {
                int nb = np * 16;
                uint32_t h0, h1, h2, h3;
                ldsm4(h0, h1, h2, h3,
                      kvb + FVo + (size_t)(nb + b_r + b_n8) * 72 + kt * 16 + b_k8);
                mma16816(o[2 * np],     aPh[0], aPh[1], aPh[2], aPh[3], h0, h1);
                mma16816(o[2 * np + 1], aPh[0], aPh[1], aPh[2], aPh[3], h2, h3);
                mma16816h(ocorr[2 * np][0],     ocorr[2 * np][1],
                          aPl[0], aPl[1], aPl[2], aPl[3], h0, h1);
                mma16816h(ocorr[2 * np + 1][0], ocorr[2 * np + 1][1],
                          aPl[0], aPl[1], aPl[2], aPl[3], h2, h3);
            }
        }
    }

    const float inv0 = 1.f / l0, inv1 = 1.f / l1;
    const size_t r0base = ((size_t)(b * S_ + qr0) * NH_ + h) * HD_;
    const size_t r1base = ((size_t)(b * S_ + qr1) * NH_ + h) * HD_;
#pragma unroll
    for (int nt = 0; nt < 16; nt++) {
        int cc = nt * 8 + 2 * tg;
        float v00 = (o[nt][0] + h2lo(ocorr[nt][0])) * inv0;
        float v01 = (o[nt][1] + h2hi(ocorr[nt][0])) * inv0;
        float v10 = (o[nt][2] + h2lo(ocorr[nt][1])) * inv1;
        float v11 = (o[nt][3] + h2hi(ocorr[nt][1])) * inv1;
        uint32_t h0p = pk_h2(v00, v01);
        uint32_t h1p = pk_h2(v10, v11);
        float e00 = v00 - h2lo(h0p);
        float e01 = v01 - h2hi(h0p);
        float e10 = v10 - h2lo(h1p);
        float e11 = v11 - h2hi(h1p);
        *(uint32_t*)(Oh + r0base + cc) = h0p;
        *(uint32_t*)(Ol + r0base + cc) = pk_h2(e00, e01);
        *(uint32_t*)(Oh + r1base + cc) = h1p;
        *(uint32_t*)(Ol + r1base + cc) = pk_h2(e10, e11);
    }
}

// ---------------------------------------------------------------------------
// Launch: 4 kernels total
// ---------------------------------------------------------------------------
extern "C" void kernel_launch(void* const* d_in, const int* in_sizes, int n_in,
                              void* d_out, int out_size) {
    const float* hs   = (const float*)d_in[0];
    const float* cosp = (const float*)d_in[1];
    const float* sinp = (const float*)d_in[2];
    const float* Wq   = (const float*)d_in[4];
    const float* Wk   = (const float*)d_in[5];
    const float* Wv   = (const float*)d_in[6];
    const float* Wo   = (const float*)d_in[7];
    float* out = (float*)d_out;

    __half *hs_h, *wqkv_h, *wo_h, *ob_h, *ob_l, *qh, *ql, *kh, *vth;
    cudaGetSymbolAddress((void**)&hs_h, g_hs_h);
    cudaGetSymbolAddress((void**)&wqkv_h, g_wqkv_h);
    cudaGetSymbolAddress((void**)&wo_h, g_wo_h);
    cudaGetSymbolAddress((void**)&ob_h, g_ob_h); cudaGetSymbolAddress((void**)&ob_l, g_ob_l);
    cudaGetSymbolAddress((void**)&qh, g_qh); cudaGetSymbolAddress((void**)&ql, g_ql);
    cudaGetSymbolAddress((void**)&kh, g_kh);
    cudaGetSymbolAddress((void**)&vth, g_vth);

    cudaFuncSetAttribute(gemm_qkv, cudaFuncAttributeMaxDynamicSharedMemorySize, GSMEM_B);
    cudaFuncSetAttribute(gemm_mma, cudaFuncAttributeMaxDynamicSharedMemorySize, GSMEM_B);
    cudaFuncSetAttribute(flash_mma, cudaFuncAttributeMaxDynamicSharedMemorySize, FSMEM_B);

    const int M = B_ * S_;   // 4096

    // single fused conversion pass (Wqkv + hs + Wo)
    cvt_all<<<(unsigned)((CVT_N4 + 255) / 256), 256>>>(
        Wq, Wk, Wv, hs, Wo, wqkv_h, hs_h, wo_h);

    // fused QKV projection + rope/split/transpose epilogue
    gemm_qkv<<<dim3(NQKV / BN, M / BM), 256, GSMEM_B>>>(
        hs_h, wqkv_h, cosp, sinp, qh, ql, kh, vth);

    // flash attention
    flash_mma<<<dim3(S_ / 64, NH_, B_), 128, FSMEM_B>>>(qh, ql, kh, vth, ob_h, ob_l);

    // O projection (hi+lo correction, reordered MMA schedule)
    gemm_mma<<<dim3(HID_ / BN, M / BM), 256, GSMEM_B>>>(
        ob_h, ob_l, wo_h, out, M, HID_, NH_ * HD_);
}